// round 1
// baseline (speedup 1.0000x reference)
#include <cuda_runtime.h>
#include <math.h>

// ---------------- problem constants ----------------
#define SS 2048
#define DD 4096
#define HH 32
#define QLORA 1536
#define KVLORA 512
#define ROPEW 64
#define NOPEW 128
#define QKH 192           // NOPE + ROPE
#define VH 128
#define KEFF 576          // KVLORA + ROPE
#define EPSV 1e-6f
#define SCALE 0.07216878364870322f   // 1/sqrt(192)

// ---------------- scratch (static device memory; no allocations allowed) ----
__device__ float g_qa[(size_t)SS * QLORA];            // 12.6 MB
__device__ float g_q[(size_t)SS * HH * QKH];          // 50 MB
__device__ float g_keff[(size_t)SS * KEFF];           // 4.7 MB  (kv_c | k_rot)
__device__ float g_qeff[(size_t)HH * SS * KEFF];      // 151 MB  (q_latent | q_rope), head-major
__device__ float g_scores[(size_t)HH * SS * SS];      // 537 MB
__device__ float g_ctxl[(size_t)HH * SS * KVLORA];    // 134 MB  head-major
__device__ float g_ctx[(size_t)SS * HH * VH];         // 33.5 MB

// ============================================================================
// Generic fp32 SGEMM, C = A * B^T   (A:[M,K] lda, B:[N,K] ldb, C:[M,N] ldc)
// 128x128 tile, BK=8, 256 threads, 8x8 micro-tile. Batched via blockIdx.z.
// CAUSAL_SKIP: skip whole tiles with bn > bm (scores GEMM upper triangle).
// ============================================================================
template<int CAUSAL_SKIP>
__global__ __launch_bounds__(256)
void gemm_nt(const float* __restrict__ Ag, const float* __restrict__ Bg,
             float* __restrict__ Cg,
             int M, int N, int K, int lda, int ldb, int ldc,
             long long sA, long long sB, long long sC)
{
    const int bm = blockIdx.y, bn = blockIdx.x;
    if (CAUSAL_SKIP && bn > bm) return;
    const float* A = Ag + (long long)blockIdx.z * sA;
    const float* B = Bg + (long long)blockIdx.z * sB;
    float*       C = Cg + (long long)blockIdx.z * sC;

    __shared__ float As[8][128];
    __shared__ float Bs[8][128];

    const int tid  = threadIdx.x;
    const int lrow = tid >> 1;           // 0..127
    const int lcol = (tid & 1) * 4;      // 0 or 4
    const int tx   = tid & 15;
    const int ty   = tid >> 4;

    float acc[8][8];
    #pragma unroll
    for (int i = 0; i < 8; i++)
        #pragma unroll
        for (int j = 0; j < 8; j++) acc[i][j] = 0.f;

    const int arow = bm * 128 + lrow;
    const int brow = bn * 128 + lrow;
    const float* Ap = A + (long long)arow * lda + lcol;
    const float* Bp = B + (long long)brow * ldb + lcol;
    const bool av = arow < M;
    const bool bv = brow < N;

    for (int k0 = 0; k0 < K; k0 += 8) {
        float4 a4 = av ? *(const float4*)(Ap + k0) : make_float4(0.f,0.f,0.f,0.f);
        float4 b4 = bv ? *(const float4*)(Bp + k0) : make_float4(0.f,0.f,0.f,0.f);
        As[lcol+0][lrow] = a4.x; As[lcol+1][lrow] = a4.y;
        As[lcol+2][lrow] = a4.z; As[lcol+3][lrow] = a4.w;
        Bs[lcol+0][lrow] = b4.x; Bs[lcol+1][lrow] = b4.y;
        Bs[lcol+2][lrow] = b4.z; Bs[lcol+3][lrow] = b4.w;
        __syncthreads();
        #pragma unroll
        for (int kk = 0; kk < 8; kk++) {
            float af[8], bf[8];
            *(float4*)&af[0] = *(const float4*)&As[kk][ty*8];
            *(float4*)&af[4] = *(const float4*)&As[kk][ty*8+4];
            *(float4*)&bf[0] = *(const float4*)&Bs[kk][tx*8];
            *(float4*)&bf[4] = *(const float4*)&Bs[kk][tx*8+4];
            #pragma unroll
            for (int i = 0; i < 8; i++)
                #pragma unroll
                for (int j = 0; j < 8; j++) acc[i][j] += af[i] * bf[j];
        }
        __syncthreads();
    }

    const int r0 = bm * 128 + ty * 8;
    const int c0 = bn * 128 + tx * 8;
    #pragma unroll
    for (int i = 0; i < 8; i++) {
        int r = r0 + i;
        if (r >= M) break;
        #pragma unroll
        for (int j = 0; j < 8; j++) {
            int c = c0 + j;
            if (c < N) C[(long long)r * ldc + c] = acc[i][j];
        }
    }
}

// ============================================================================
// Generic fp32 SGEMM, C = A * B      (A:[M,K] lda, B:[K,N] ldb, C:[M,N] ldc)
// CAUSAL_KEND: limit K loop to (bm+1)*128 (P*V with causal-zero-padded P rows)
// ============================================================================
template<int CAUSAL_KEND>
__global__ __launch_bounds__(256)
void gemm_nn(const float* __restrict__ Ag, const float* __restrict__ Bg,
             float* __restrict__ Cg,
             int M, int N, int K, int lda, int ldb, int ldc,
             long long sA, long long sB, long long sC)
{
    const int bm = blockIdx.y, bn = blockIdx.x;
    const float* A = Ag + (long long)blockIdx.z * sA;
    const float* B = Bg + (long long)blockIdx.z * sB;
    float*       C = Cg + (long long)blockIdx.z * sC;

    const int Kend = CAUSAL_KEND ? min(K, (bm + 1) * 128) : K;

    __shared__ float As[8][128];
    __shared__ float Bs[8][128];

    const int tid  = threadIdx.x;
    const int lrow = tid >> 1;
    const int lcol = (tid & 1) * 4;
    const int tx   = tid & 15;
    const int ty   = tid >> 4;
    const int bkr  = tid >> 5;           // 0..7  (B tile row)
    const int bkc  = (tid & 31) * 4;     // 0..124 (B tile col)

    float acc[8][8];
    #pragma unroll
    for (int i = 0; i < 8; i++)
        #pragma unroll
        for (int j = 0; j < 8; j++) acc[i][j] = 0.f;

    const int arow = bm * 128 + lrow;
    const float* Ap = A + (long long)arow * lda + lcol;
    const bool av = arow < M;
    const int gc = bn * 128 + bkc;
    const bool bvc = gc < N;

    for (int k0 = 0; k0 < Kend; k0 += 8) {
        float4 a4 = av ? *(const float4*)(Ap + k0) : make_float4(0.f,0.f,0.f,0.f);
        float4 b4 = bvc ? *(const float4*)(B + (long long)(k0 + bkr) * ldb + gc)
                        : make_float4(0.f,0.f,0.f,0.f);
        As[lcol+0][lrow] = a4.x; As[lcol+1][lrow] = a4.y;
        As[lcol+2][lrow] = a4.z; As[lcol+3][lrow] = a4.w;
        *(float4*)&Bs[bkr][bkc] = b4;
        __syncthreads();
        #pragma unroll
        for (int kk = 0; kk < 8; kk++) {
            float af[8], bf[8];
            *(float4*)&af[0] = *(const float4*)&As[kk][ty*8];
            *(float4*)&af[4] = *(const float4*)&As[kk][ty*8+4];
            *(float4*)&bf[0] = *(const float4*)&Bs[kk][tx*8];
            *(float4*)&bf[4] = *(const float4*)&Bs[kk][tx*8+4];
            #pragma unroll
            for (int i = 0; i < 8; i++)
                #pragma unroll
                for (int j = 0; j < 8; j++) acc[i][j] += af[i] * bf[j];
        }
        __syncthreads();
    }

    const int r0 = bm * 128 + ty * 8;
    const int c0 = bn * 128 + tx * 8;
    #pragma unroll
    for (int i = 0; i < 8; i++) {
        int r = r0 + i;
        if (r >= M) break;
        #pragma unroll
        for (int j = 0; j < 8; j++) {
            int c = c0 + j;
            if (c < N) C[(long long)r * ldc + c] = acc[i][j];
        }
    }
}

// ============================================================================
// RMSNorm rows in place: x = x * rsqrt(mean(x^2)+eps) * g
// ============================================================================
__global__ void rmsnorm_rows(float* __restrict__ X, const float* __restrict__ g, int n)
{
    float* x = X + (long long)blockIdx.x * n;
    __shared__ float red[256];
    const int tid = threadIdx.x;
    float s = 0.f;
    for (int i = tid; i < n; i += 256) { float v = x[i]; s += v * v; }
    red[tid] = s; __syncthreads();
    for (int o = 128; o > 0; o >>= 1) {
        if (tid < o) red[tid] += red[tid + o];
        __syncthreads();
    }
    float inv = rsqrtf(red[0] / (float)n + EPSV);
    for (int i = tid; i < n; i += 256) x[i] = x[i] * inv * g[i];
}

// ============================================================================
// kv post: row of g_keff [576] = (rmsnorm(kv[0:512], g) | rope(kv[512:576]))
// ============================================================================
__global__ void kv_post(float* __restrict__ KV, const float* __restrict__ g,
                        const float* __restrict__ cosb, const float* __restrict__ sinb)
{
    const int srow = blockIdx.x;
    float* x = KV + (long long)srow * KEFF;
    __shared__ float red[256];
    const int tid = threadIdx.x;
    float s = 0.f;
    for (int i = tid; i < KVLORA; i += 256) { float v = x[i]; s += v * v; }
    red[tid] = s; __syncthreads();
    for (int o = 128; o > 0; o >>= 1) {
        if (tid < o) red[tid] += red[tid + o];
        __syncthreads();
    }
    float inv = rsqrtf(red[0] / (float)KVLORA + EPSV);
    for (int i = tid; i < KVLORA; i += 256) x[i] = x[i] * inv * g[i];
    if (tid < 32) {
        float x1 = x[KVLORA + tid];
        float x2 = x[KVLORA + 32 + tid];
        float c1 = cosb[srow * ROPEW + tid];
        float c2 = cosb[srow * ROPEW + 32 + tid];
        float s1 = sinb[srow * ROPEW + tid];
        float s2 = sinb[srow * ROPEW + 32 + tid];
        x[KVLORA + tid]      = x1 * c1 - x2 * s1;
        x[KVLORA + 32 + tid] = x2 * c2 + x1 * s2;
    }
}

// ============================================================================
// q rope: g_qeff[h][s][512+j] = rope(q[s, h*192 + 128 + j])
// one thread per (s,h,j<32) pair
// ============================================================================
__global__ void q_rope(const float* __restrict__ Q, float* __restrict__ Qeff,
                       const float* __restrict__ cosb, const float* __restrict__ sinb)
{
    long long idx = (long long)blockIdx.x * blockDim.x + threadIdx.x;
    const long long total = (long long)SS * HH * 32;
    if (idx >= total) return;
    int j  = (int)(idx & 31);
    long long sh = idx >> 5;
    int h = (int)(sh & (HH - 1));
    int s = (int)(sh >> 5);
    const float* q = Q + ((long long)s * HH + h) * QKH + NOPEW;
    float x1 = q[j], x2 = q[j + 32];
    float c1 = cosb[s * ROPEW + j];
    float c2 = cosb[s * ROPEW + 32 + j];
    float s1 = sinb[s * ROPEW + j];
    float s2 = sinb[s * ROPEW + 32 + j];
    float* o = Qeff + ((long long)h * SS + s) * KEFF + KVLORA;
    o[j]      = x1 * c1 - x2 * s1;
    o[j + 32] = x2 * c2 + x1 * s2;
}

// ============================================================================
// causal softmax in place on scores row (scale applied here).
// Writes zeros for cols (m, pad) where pad = next 128 multiple, so the
// causal-K-limited P*V GEMM reads exact zeros beyond the diagonal.
// ============================================================================
__global__ void softmax_causal(float* __restrict__ Sc)
{
    const int m = blockIdx.x;
    const int h = blockIdx.y;
    float* row = Sc + ((long long)h * SS + m) * SS;
    const int len = m + 1;
    const int pad = ((m >> 7) + 1) << 7;
    const int tid = threadIdx.x;
    __shared__ float red[256];

    float mx = -3.4e38f;
    for (int i = tid; i < len; i += 256) mx = fmaxf(mx, row[i]);
    red[tid] = mx; __syncthreads();
    for (int o = 128; o > 0; o >>= 1) {
        if (tid < o) red[tid] = fmaxf(red[tid], red[tid + o]);
        __syncthreads();
    }
    const float rowmax = red[0];
    __syncthreads();

    float sum = 0.f;
    for (int i = tid; i < len; i += 256) {
        float e = expf(SCALE * (row[i] - rowmax));
        row[i] = e;
        sum += e;
    }
    red[tid] = sum; __syncthreads();
    for (int o = 128; o > 0; o >>= 1) {
        if (tid < o) red[tid] += red[tid + o];
        __syncthreads();
    }
    const float rinv = 1.f / red[0];
    for (int i = tid; i < len; i += 256) row[i] *= rinv;
    for (int i = len + tid; i < pad; i += 256) row[i] = 0.f;
}

// ============================================================================
extern "C" void kernel_launch(void* const* d_in, const int* in_sizes, int n_in,
                              void* d_out, int out_size)
{
    (void)in_sizes; (void)n_in; (void)out_size;
    const float* h      = (const float*)d_in[0];
    const float* cosb   = (const float*)d_in[1];
    const float* sinb   = (const float*)d_in[2];
    const float* w_q_a  = (const float*)d_in[3];
    const float* gq     = (const float*)d_in[4];
    const float* w_q_b  = (const float*)d_in[5];
    const float* w_kv_a = (const float*)d_in[6];
    const float* gkv    = (const float*)d_in[7];
    const float* w_uk   = (const float*)d_in[8];
    const float* w_uv   = (const float*)d_in[9];
    const float* w_o    = (const float*)d_in[10];
    float* out = (float*)d_out;

    float *qa, *q, *keff, *qeff, *sc, *ctxl, *ctx;
    cudaGetSymbolAddress((void**)&qa,   g_qa);
    cudaGetSymbolAddress((void**)&q,    g_q);
    cudaGetSymbolAddress((void**)&keff, g_keff);
    cudaGetSymbolAddress((void**)&qeff, g_qeff);
    cudaGetSymbolAddress((void**)&sc,   g_scores);
    cudaGetSymbolAddress((void**)&ctxl, g_ctxl);
    cudaGetSymbolAddress((void**)&ctx,  g_ctx);

    // 1) q_a = h @ w_q_a^T           [2048,1536]
    gemm_nt<0><<<dim3(QLORA/128, SS/128, 1), 256>>>(
        h, w_q_a, qa, SS, QLORA, DD, DD, DD, QLORA, 0, 0, 0);
    // 2) rmsnorm(q_a)
    rmsnorm_rows<<<SS, 256>>>(qa, gq, QLORA);
    // 3) q = q_a @ w_q_b^T           [2048,6144]
    gemm_nt<0><<<dim3((HH*QKH)/128, SS/128, 1), 256>>>(
        qa, w_q_b, q, SS, HH*QKH, QLORA, QLORA, QLORA, HH*QKH, 0, 0, 0);
    // 4) kv = h @ w_kv_a^T           [2048,576]
    gemm_nt<0><<<dim3((KEFF+127)/128, SS/128, 1), 256>>>(
        h, w_kv_a, keff, SS, KEFF, DD, DD, DD, KEFF, 0, 0, 0);
    // 5) kv post: rmsnorm + rope -> k_eff
    kv_post<<<SS, 256>>>(keff, gkv, cosb, sinb);
    // 6) q_latent per head: q_eff[h][:,0:512] = q_nope_h @ w_uk_t[h]
    gemm_nn<0><<<dim3(KVLORA/128, SS/128, HH), 256>>>(
        q, w_uk, qeff, SS, KVLORA, NOPEW,
        HH*QKH, KVLORA, KEFF,
        (long long)QKH, (long long)NOPEW*KVLORA, (long long)SS*KEFF);
    // 7) q rope -> q_eff[h][:,512:576]
    {
        long long total = (long long)SS * HH * 32;
        q_rope<<<(unsigned)((total + 255) / 256), 256>>>(q, qeff, cosb, sinb);
    }
    // 8) scores[h] = q_eff[h] @ k_eff^T   (skip tiles above diagonal)
    gemm_nt<1><<<dim3(SS/128, SS/128, HH), 256>>>(
        qeff, keff, sc, SS, SS, KEFF, KEFF, KEFF, SS,
        (long long)SS*KEFF, 0, (long long)SS*SS);
    // 9) causal softmax (+ zero pad to 128 boundary)
    softmax_causal<<<dim3(SS, HH), 256>>>(sc);
    // 10) ctx_latent[h] = P[h] @ kv_c   (K limited to (bm+1)*128)
    gemm_nn<1><<<dim3(KVLORA/128, SS/128, HH), 256>>>(
        sc, keff, ctxl, SS, KVLORA, SS,
        SS, KEFF, KVLORA,
        (long long)SS*SS, 0, (long long)SS*KVLORA);
    // 11) ctx[s, h*128+v] = ctx_latent[h] @ w_uv[h]
    gemm_nn<0><<<dim3(1, SS/128, HH), 256>>>(
        ctxl, w_uv, ctx, SS, VH, KVLORA,
        KVLORA, VH, HH*VH,
        (long long)SS*KVLORA, (long long)KVLORA*VH, (long long)VH);
    // 12) out = ctx @ w_o^T
    gemm_nt<0><<<dim3(DD/128, SS/128, 1), 256>>>(
        ctx, w_o, out, SS, DD, HH*VH, HH*VH, HH*VH, DD, 0, 0, 0);
}

// round 3
// speedup vs baseline: 1.2932x; 1.2932x over previous
#include <cuda_runtime.h>
#include <cuda_bf16.h>
#include <stdint.h>
#include <math.h>

// ---------------- problem constants ----------------
#define SS 2048
#define DD 4096
#define HH 32
#define QLORA 1536
#define KVLORA 512
#define ROPEW 64
#define NOPEW 128
#define QKH 192           // NOPE + ROPE
#define VH 128
#define KEFF 576          // KVLORA + ROPE
#define EPSV 1e-6f
#define SCALE 0.07216878364870322f   // 1/sqrt(192)

#define LDT 40            // smem row stride in bf16 elements (80B; conflict-free)

// ---------------- scratch (static device memory) ----
__device__ float g_qa[(size_t)SS * QLORA];
__device__ float g_q[(size_t)SS * HH * QKH];
__device__ float g_keff[(size_t)SS * KEFF];
__device__ float g_qeff[(size_t)HH * SS * KEFF];
__device__ float g_scores[(size_t)HH * SS * SS];
__device__ float g_ctxl[(size_t)HH * SS * KVLORA];
__device__ float g_ctx[(size_t)SS * HH * VH];

// ---------------- helpers ----------------
// fp32 -> (bf16 hi, bf16 lo) packed pairs
__device__ __forceinline__ void cvt_hilo4(float4 v, uint2& hi, uint2& lo) {
    __nv_bfloat16 h0 = __float2bfloat16(v.x), h1 = __float2bfloat16(v.y);
    __nv_bfloat16 h2 = __float2bfloat16(v.z), h3 = __float2bfloat16(v.w);
    __nv_bfloat16 l0 = __float2bfloat16(v.x - __bfloat162float(h0));
    __nv_bfloat16 l1 = __float2bfloat16(v.y - __bfloat162float(h1));
    __nv_bfloat16 l2 = __float2bfloat16(v.z - __bfloat162float(h2));
    __nv_bfloat16 l3 = __float2bfloat16(v.w - __bfloat162float(h3));
    hi.x = ((uint32_t)__bfloat16_as_ushort(h1) << 16) | __bfloat16_as_ushort(h0);
    hi.y = ((uint32_t)__bfloat16_as_ushort(h3) << 16) | __bfloat16_as_ushort(h2);
    lo.x = ((uint32_t)__bfloat16_as_ushort(l1) << 16) | __bfloat16_as_ushort(l0);
    lo.y = ((uint32_t)__bfloat16_as_ushort(l3) << 16) | __bfloat16_as_ushort(l2);
}

__device__ __forceinline__ void mma_bf16(float* c, const uint32_t* a, const uint32_t* b) {
    asm volatile(
        "mma.sync.aligned.m16n8k16.row.col.f32.bf16.bf16.f32 "
        "{%0,%1,%2,%3}, {%4,%5,%6,%7}, {%8,%9}, {%0,%1,%2,%3};"
        : "+f"(c[0]), "+f"(c[1]), "+f"(c[2]), "+f"(c[3])
        : "r"(a[0]), "r"(a[1]), "r"(a[2]), "r"(a[3]), "r"(b[0]), "r"(b[1]));
}

// ============================================================================
// warp-MMA bf16 hi/lo GEMM core pieces (shared by NT and NN via fill lambdas)
// smem: A[128][32] and B[128][32] K-major, hi & lo, LDT-padded rows.
// ============================================================================
struct SmemTiles {
    __nv_bfloat16 Ah[128 * LDT];
    __nv_bfloat16 Al[128 * LDT];
    __nv_bfloat16 Bh[128 * LDT];
    __nv_bfloat16 Bl[128 * LDT];
};

// compute one BK=32 chunk from smem tiles
__device__ __forceinline__ void compute_chunk(SmemTiles* t, float acc[4][4][4],
                                              int wm, int wn, int lane) {
    const int qr = lane >> 2;
    const int qc = lane & 3;
    #pragma unroll
    for (int ks = 0; ks < 2; ks++) {
        const int kb = ks * 16 + qc * 2;
        uint32_t Ahf[4][4], Alf[4][4], Bhf[4][2], Blf[4][2];
        #pragma unroll
        for (int mi = 0; mi < 4; mi++) {
            int r0 = wm * 64 + mi * 16 + qr;
            Ahf[mi][0] = *(const uint32_t*)&t->Ah[r0 * LDT + kb];
            Ahf[mi][1] = *(const uint32_t*)&t->Ah[(r0 + 8) * LDT + kb];
            Ahf[mi][2] = *(const uint32_t*)&t->Ah[r0 * LDT + kb + 8];
            Ahf[mi][3] = *(const uint32_t*)&t->Ah[(r0 + 8) * LDT + kb + 8];
            Alf[mi][0] = *(const uint32_t*)&t->Al[r0 * LDT + kb];
            Alf[mi][1] = *(const uint32_t*)&t->Al[(r0 + 8) * LDT + kb];
            Alf[mi][2] = *(const uint32_t*)&t->Al[r0 * LDT + kb + 8];
            Alf[mi][3] = *(const uint32_t*)&t->Al[(r0 + 8) * LDT + kb + 8];
        }
        #pragma unroll
        for (int ni = 0; ni < 4; ni++) {
            int nr = wn * 32 + ni * 8 + qr;
            Bhf[ni][0] = *(const uint32_t*)&t->Bh[nr * LDT + kb];
            Bhf[ni][1] = *(const uint32_t*)&t->Bh[nr * LDT + kb + 8];
            Blf[ni][0] = *(const uint32_t*)&t->Bl[nr * LDT + kb];
            Blf[ni][1] = *(const uint32_t*)&t->Bl[nr * LDT + kb + 8];
        }
        #pragma unroll
        for (int mi = 0; mi < 4; mi++)
            #pragma unroll
            for (int ni = 0; ni < 4; ni++) {
                mma_bf16(acc[mi][ni], Ahf[mi], Bhf[ni]);
                mma_bf16(acc[mi][ni], Ahf[mi], Blf[ni]);
                mma_bf16(acc[mi][ni], Alf[mi], Bhf[ni]);
            }
    }
}

__device__ __forceinline__ void epilogue(float acc[4][4][4], float* C,
                                         int bm, int bn, int N, int ldc,
                                         int wm, int wn, int lane) {
    const int qr = lane >> 2;
    const int qc = lane & 3;
    #pragma unroll
    for (int mi = 0; mi < 4; mi++) {
        #pragma unroll
        for (int ni = 0; ni < 4; ni++) {
            int r = bm * 128 + wm * 64 + mi * 16 + qr;
            int cc = bn * 128 + wn * 32 + ni * 8 + qc * 2;
            if (cc < N) {
                float2 v0 = make_float2(acc[mi][ni][0], acc[mi][ni][1]);
                float2 v1 = make_float2(acc[mi][ni][2], acc[mi][ni][3]);
                *(float2*)(C + (long long)r * ldc + cc) = v0;
                *(float2*)(C + (long long)(r + 8) * ldc + cc) = v1;
            }
        }
    }
}

// ============================================================================
// NT:  C = A * B^T    (A:[M,K] lda, B:[N,K] ldb, C:[M,N] ldc).  K%32==0.
// CAUSAL_SKIP: skip tiles with bn > bm.
// ============================================================================
template<int CAUSAL_SKIP>
__global__ __launch_bounds__(256)
void wgemm_nt(const float* __restrict__ Ag, const float* __restrict__ Bg,
              float* __restrict__ Cg, int M, int N, int K,
              int lda, int ldb, int ldc, long long sA, long long sB, long long sC)
{
    const int bm = blockIdx.y, bn = blockIdx.x;
    if (CAUSAL_SKIP && bn > bm) return;
    __shared__ SmemTiles t;

    const float* A = Ag + (long long)blockIdx.z * sA;
    const float* B = Bg + (long long)blockIdx.z * sB;
    float*       C = Cg + (long long)blockIdx.z * sC;

    const int tid  = threadIdx.x;
    const int lane = tid & 31;
    const int wid  = tid >> 5;
    const int wm   = wid & 1;
    const int wn   = wid >> 1;

    const int fk = (tid & 7) * 4;   // k offset within chunk (0..28)
    const int fr = tid >> 3;        // base row (0..31), 4 passes

    float acc[4][4][4];
    #pragma unroll
    for (int a = 0; a < 4; a++)
        #pragma unroll
        for (int b = 0; b < 4; b++)
            #pragma unroll
            for (int cidx = 0; cidx < 4; cidx++) acc[a][b][cidx] = 0.f;

    uint2 pah[4], pal[4], pbh[4], pbl[4];

    auto fill_regs = [&](int k0) {
        #pragma unroll
        for (int p = 0; p < 4; p++) {
            int row = p * 32 + fr;
            float4 a = *(const float4*)(A + (long long)(bm * 128 + row) * lda + k0 + fk);
            cvt_hilo4(a, pah[p], pal[p]);
            int brow = bn * 128 + row;
            float4 b = (brow < N) ? *(const float4*)(B + (long long)brow * ldb + k0 + fk)
                                  : make_float4(0.f, 0.f, 0.f, 0.f);
            cvt_hilo4(b, pbh[p], pbl[p]);
        }
    };
    auto store_smem = [&]() {
        #pragma unroll
        for (int p = 0; p < 4; p++) {
            int row = p * 32 + fr;
            *(uint2*)&t.Ah[row * LDT + fk] = pah[p];
            *(uint2*)&t.Al[row * LDT + fk] = pal[p];
            *(uint2*)&t.Bh[row * LDT + fk] = pbh[p];
            *(uint2*)&t.Bl[row * LDT + fk] = pbl[p];
        }
    };

    const int nchunks = K / 32;
    fill_regs(0);
    store_smem();
    __syncthreads();

    for (int c = 0; c < nchunks; c++) {
        if (c + 1 < nchunks) fill_regs((c + 1) * 32);
        compute_chunk(&t, acc, wm, wn, lane);
        __syncthreads();
        if (c + 1 < nchunks) { store_smem(); __syncthreads(); }
    }

    epilogue(acc, C, bm, bn, N, ldc, wm, wn, lane);
}

// ============================================================================
// NN:  C = A * B      (A:[M,K] lda, B:[K,N] ldb, C:[M,N] ldc).  K%32==0,
// N covered by full tiles at every call site.
// CAUSAL_KEND: limit K to (bm+1)*128 (P*V with zero-padded P rows).
// ============================================================================
template<int CAUSAL_KEND>
__global__ __launch_bounds__(256)
void wgemm_nn(const float* __restrict__ Ag, const float* __restrict__ Bg,
              float* __restrict__ Cg, int M, int N, int K,
              int lda, int ldb, int ldc, long long sA, long long sB, long long sC)
{
    const int bm = blockIdx.y, bn = blockIdx.x;
    __shared__ SmemTiles t;

    const float* A = Ag + (long long)blockIdx.z * sA;
    const float* B = Bg + (long long)blockIdx.z * sB;
    float*       C = Cg + (long long)blockIdx.z * sC;

    const int Kend = CAUSAL_KEND ? min(K, (bm + 1) * 128) : K;

    const int tid  = threadIdx.x;
    const int lane = tid & 31;
    const int wid  = tid >> 5;
    const int wm   = wid & 1;
    const int wn   = wid >> 1;

    const int fk  = (tid & 7) * 4;
    const int fr  = tid >> 3;
    const int bn4 = (tid & 31) * 4;  // B: N col group
    const int bkr = tid >> 5;        // B: k row sub (8 per pass)

    float acc[4][4][4];
    #pragma unroll
    for (int a = 0; a < 4; a++)
        #pragma unroll
        for (int b = 0; b < 4; b++)
            #pragma unroll
            for (int cidx = 0; cidx < 4; cidx++) acc[a][b][cidx] = 0.f;

    uint2 pah[4], pal[4], pbh[4], pbl[4];

    auto fill_regs = [&](int k0) {
        #pragma unroll
        for (int p = 0; p < 4; p++) {
            int row = p * 32 + fr;
            float4 a = *(const float4*)(A + (long long)(bm * 128 + row) * lda + k0 + fk);
            cvt_hilo4(a, pah[p], pal[p]);
            int k = p * 8 + bkr;
            float4 b = *(const float4*)(B + (long long)(k0 + k) * ldb + bn * 128 + bn4);
            cvt_hilo4(b, pbh[p], pbl[p]);
        }
    };
    auto store_smem = [&]() {
        #pragma unroll
        for (int p = 0; p < 4; p++) {
            int row = p * 32 + fr;
            *(uint2*)&t.Ah[row * LDT + fk] = pah[p];
            *(uint2*)&t.Al[row * LDT + fk] = pal[p];
            int k = p * 8 + bkr;
            // transposed scatter: smem[n][k] <- B[k][n]
            t.Bh[(bn4 + 0) * LDT + k] = __ushort_as_bfloat16((uint16_t)(pbh[p].x));
            t.Bh[(bn4 + 1) * LDT + k] = __ushort_as_bfloat16((uint16_t)(pbh[p].x >> 16));
            t.Bh[(bn4 + 2) * LDT + k] = __ushort_as_bfloat16((uint16_t)(pbh[p].y));
            t.Bh[(bn4 + 3) * LDT + k] = __ushort_as_bfloat16((uint16_t)(pbh[p].y >> 16));
            t.Bl[(bn4 + 0) * LDT + k] = __ushort_as_bfloat16((uint16_t)(pbl[p].x));
            t.Bl[(bn4 + 1) * LDT + k] = __ushort_as_bfloat16((uint16_t)(pbl[p].x >> 16));
            t.Bl[(bn4 + 2) * LDT + k] = __ushort_as_bfloat16((uint16_t)(pbl[p].y));
            t.Bl[(bn4 + 3) * LDT + k] = __ushort_as_bfloat16((uint16_t)(pbl[p].y >> 16));
        }
    };

    const int nchunks = Kend / 32;
    fill_regs(0);
    store_smem();
    __syncthreads();

    for (int c = 0; c < nchunks; c++) {
        if (c + 1 < nchunks) fill_regs((c + 1) * 32);
        compute_chunk(&t, acc, wm, wn, lane);
        __syncthreads();
        if (c + 1 < nchunks) { store_smem(); __syncthreads(); }
    }

    epilogue(acc, C, bm, bn, N, ldc, wm, wn, lane);
}

// ============================================================================
// elementwise / normalization kernels (unchanged, proven correct)
// ============================================================================
__global__ void rmsnorm_rows(float* __restrict__ X, const float* __restrict__ g, int n)
{
    float* x = X + (long long)blockIdx.x * n;
    __shared__ float red[256];
    const int tid = threadIdx.x;
    float s = 0.f;
    for (int i = tid; i < n; i += 256) { float v = x[i]; s += v * v; }
    red[tid] = s; __syncthreads();
    for (int o = 128; o > 0; o >>= 1) {
        if (tid < o) red[tid] += red[tid + o];
        __syncthreads();
    }
    float inv = rsqrtf(red[0] / (float)n + EPSV);
    for (int i = tid; i < n; i += 256) x[i] = x[i] * inv * g[i];
}

__global__ void kv_post(float* __restrict__ KV, const float* __restrict__ g,
                        const float* __restrict__ cosb, const float* __restrict__ sinb)
{
    const int srow = blockIdx.x;
    float* x = KV + (long long)srow * KEFF;
    __shared__ float red[256];
    const int tid = threadIdx.x;
    float s = 0.f;
    for (int i = tid; i < KVLORA; i += 256) { float v = x[i]; s += v * v; }
    red[tid] = s; __syncthreads();
    for (int o = 128; o > 0; o >>= 1) {
        if (tid < o) red[tid] += red[tid + o];
        __syncthreads();
    }
    float inv = rsqrtf(red[0] / (float)KVLORA + EPSV);
    for (int i = tid; i < KVLORA; i += 256) x[i] = x[i] * inv * g[i];
    if (tid < 32) {
        float x1 = x[KVLORA + tid];
        float x2 = x[KVLORA + 32 + tid];
        float c1 = cosb[srow * ROPEW + tid];
        float c2 = cosb[srow * ROPEW + 32 + tid];
        float s1 = sinb[srow * ROPEW + tid];
        float s2 = sinb[srow * ROPEW + 32 + tid];
        x[KVLORA + tid]      = x1 * c1 - x2 * s1;
        x[KVLORA + 32 + tid] = x2 * c2 + x1 * s2;
    }
}

__global__ void q_rope(const float* __restrict__ Q, float* __restrict__ Qeff,
                       const float* __restrict__ cosb, const float* __restrict__ sinb)
{
    long long idx = (long long)blockIdx.x * blockDim.x + threadIdx.x;
    const long long total = (long long)SS * HH * 32;
    if (idx >= total) return;
    int j  = (int)(idx & 31);
    long long sh = idx >> 5;
    int h = (int)(sh & (HH - 1));
    int s = (int)(sh >> 5);
    const float* q = Q + ((long long)s * HH + h) * QKH + NOPEW;
    float x1 = q[j], x2 = q[j + 32];
    float c1 = cosb[s * ROPEW + j];
    float c2 = cosb[s * ROPEW + 32 + j];
    float s1 = sinb[s * ROPEW + j];
    float s2 = sinb[s * ROPEW + 32 + j];
    float* o = Qeff + ((long long)h * SS + s) * KEFF + KVLORA;
    o[j]      = x1 * c1 - x2 * s1;
    o[j + 32] = x2 * c2 + x1 * s2;
}

__global__ void softmax_causal(float* __restrict__ Sc)
{
    const int m = blockIdx.x;
    const int h = blockIdx.y;
    float* row = Sc + ((long long)h * SS + m) * SS;
    const int len = m + 1;
    const int pad = ((m >> 7) + 1) << 7;
    const int tid = threadIdx.x;
    __shared__ float red[256];

    float mx = -3.4e38f;
    for (int i = tid; i < len; i += 256) mx = fmaxf(mx, row[i]);
    red[tid] = mx; __syncthreads();
    for (int o = 128; o > 0; o >>= 1) {
        if (tid < o) red[tid] = fmaxf(red[tid], red[tid + o]);
        __syncthreads();
    }
    const float rowmax = red[0];
    __syncthreads();

    float sum = 0.f;
    for (int i = tid; i < len; i += 256) {
        float e = expf(SCALE * (row[i] - rowmax));
        row[i] = e;
        sum += e;
    }
    red[tid] = sum; __syncthreads();
    for (int o = 128; o > 0; o >>= 1) {
        if (tid < o) red[tid] += red[tid + o];
        __syncthreads();
    }
    const float rinv = 1.f / red[0];
    for (int i = tid; i < len; i += 256) row[i] *= rinv;
    for (int i = len + tid; i < pad; i += 256) row[i] = 0.f;
}

// ============================================================================
extern "C" void kernel_launch(void* const* d_in, const int* in_sizes, int n_in,
                              void* d_out, int out_size)
{
    (void)in_sizes; (void)n_in; (void)out_size;
    const float* h      = (const float*)d_in[0];
    const float* cosb   = (const float*)d_in[1];
    const float* sinb   = (const float*)d_in[2];
    const float* w_q_a  = (const float*)d_in[3];
    const float* gq     = (const float*)d_in[4];
    const float* w_q_b  = (const float*)d_in[5];
    const float* w_kv_a = (const float*)d_in[6];
    const float* gkv    = (const float*)d_in[7];
    const float* w_uk   = (const float*)d_in[8];
    const float* w_uv   = (const float*)d_in[9];
    const float* w_o    = (const float*)d_in[10];
    float* out = (float*)d_out;

    float *qa, *q, *keff, *qeff, *sc, *ctxl, *ctx;
    cudaGetSymbolAddress((void**)&qa,   g_qa);
    cudaGetSymbolAddress((void**)&q,    g_q);
    cudaGetSymbolAddress((void**)&keff, g_keff);
    cudaGetSymbolAddress((void**)&qeff, g_qeff);
    cudaGetSymbolAddress((void**)&sc,   g_scores);
    cudaGetSymbolAddress((void**)&ctxl, g_ctxl);
    cudaGetSymbolAddress((void**)&ctx,  g_ctx);

    // 1) q_a = h @ w_q_a^T           [2048,1536], K=4096
    wgemm_nt<0><<<dim3(QLORA/128, SS/128, 1), 256>>>(
        h, w_q_a, qa, SS, QLORA, DD, DD, DD, QLORA, 0, 0, 0);
    // 2) rmsnorm(q_a)
    rmsnorm_rows<<<SS, 256>>>(qa, gq, QLORA);
    // 3) q = q_a @ w_q_b^T           [2048,6144], K=1536
    wgemm_nt<0><<<dim3((HH*QKH)/128, SS/128, 1), 256>>>(
        qa, w_q_b, q, SS, HH*QKH, QLORA, QLORA, QLORA, HH*QKH, 0, 0, 0);
    // 4) kv = h @ w_kv_a^T           [2048,576], K=4096
    wgemm_nt<0><<<dim3((KEFF+127)/128, SS/128, 1), 256>>>(
        h, w_kv_a, keff, SS, KEFF, DD, DD, DD, KEFF, 0, 0, 0);
    // 5) kv post: rmsnorm + rope -> k_eff
    kv_post<<<SS, 256>>>(keff, gkv, cosb, sinb);
    // 6) q_latent per head: q_eff[h][:,0:512] = q_nope_h @ w_uk_t[h], K=128
    wgemm_nn<0><<<dim3(KVLORA/128, SS/128, HH), 256>>>(
        q, w_uk, qeff, SS, KVLORA, NOPEW,
        HH*QKH, KVLORA, KEFF,
        (long long)QKH, (long long)NOPEW*KVLORA, (long long)SS*KEFF);
    // 7) q rope -> q_eff[h][:,512:576]
    {
        long long total = (long long)SS * HH * 32;
        q_rope<<<(unsigned)((total + 255) / 256), 256>>>(q, qeff, cosb, sinb);
    }
    // 8) scores[h] = q_eff[h] @ k_eff^T, K=576 (skip tiles above diagonal)
    wgemm_nt<1><<<dim3(SS/128, SS/128, HH), 256>>>(
        qeff, keff, sc, SS, SS, KEFF, KEFF, KEFF, SS,
        (long long)SS*KEFF, 0, (long long)SS*SS);
    // 9) causal softmax (+ zero pad to 128 boundary)
    softmax_causal<<<dim3(SS, HH), 256>>>(sc);
    // 10) ctx_latent[h] = P[h] @ kv_c   (K limited to (bm+1)*128)
    wgemm_nn<1><<<dim3(KVLORA/128, SS/128, HH), 256>>>(
        sc, keff, ctxl, SS, KVLORA, SS,
        SS, KEFF, KVLORA,
        (long long)SS*SS, 0, (long long)SS*KVLORA);
    // 11) ctx[s, h*128+v] = ctx_latent[h] @ w_uv[h], K=512
    wgemm_nn<0><<<dim3(1, SS/128, HH), 256>>>(
        ctxl, w_uv, ctx, SS, VH, KVLORA,
        KVLORA, VH, HH*VH,
        (long long)SS*KVLORA, (long long)KVLORA*VH, (long long)VH);
    // 12) out = ctx @ w_o^T           [2048,4096], K=4096
    wgemm_nt<0><<<dim3(DD/128, SS/128, 1), 256>>>(
        ctx, w_o, out, SS, DD, HH*VH, HH*VH, HH*VH, DD, 0, 0, 0);
}

// round 4
// speedup vs baseline: 1.5033x; 1.1625x over previous
#include <cuda_runtime.h>
#include <cuda_bf16.h>
#include <stdint.h>
#include <math.h>

// ---------------- problem constants ----------------
#define SS 2048
#define DD 4096
#define HH 32
#define QLORA 1536
#define KVLORA 512
#define ROPEW 64
#define NOPEW 128
#define QKH 192           // NOPE + ROPE
#define VH 128
#define KEFF 576          // KVLORA + ROPE
#define EPSV 1e-6f
#define SCALE 0.07216878364870322f   // 1/sqrt(192)

#define LDT 40            // smem row stride in bf16 elements (80B; conflict-free)

// ---------------- scratch (static device memory) ----
__device__ float g_qa[(size_t)SS * QLORA];
__device__ float g_q[(size_t)SS * HH * QKH];
__device__ float g_keff[(size_t)SS * KEFF];
__device__ float g_qeff[(size_t)HH * SS * KEFF];
__device__ float g_scores[(size_t)HH * SS * SS];
__device__ float g_ctxl[(size_t)HH * SS * KVLORA];
__device__ float g_ctx[(size_t)SS * HH * VH];

// ---------------- helpers ----------------
__device__ __forceinline__ void cvt_hilo4(float4 v, uint2& hi, uint2& lo) {
    __nv_bfloat16 h0 = __float2bfloat16(v.x), h1 = __float2bfloat16(v.y);
    __nv_bfloat16 h2 = __float2bfloat16(v.z), h3 = __float2bfloat16(v.w);
    __nv_bfloat16 l0 = __float2bfloat16(v.x - __bfloat162float(h0));
    __nv_bfloat16 l1 = __float2bfloat16(v.y - __bfloat162float(h1));
    __nv_bfloat16 l2 = __float2bfloat16(v.z - __bfloat162float(h2));
    __nv_bfloat16 l3 = __float2bfloat16(v.w - __bfloat162float(h3));
    hi.x = ((uint32_t)__bfloat16_as_ushort(h1) << 16) | __bfloat16_as_ushort(h0);
    hi.y = ((uint32_t)__bfloat16_as_ushort(h3) << 16) | __bfloat16_as_ushort(h2);
    lo.x = ((uint32_t)__bfloat16_as_ushort(l1) << 16) | __bfloat16_as_ushort(l0);
    lo.y = ((uint32_t)__bfloat16_as_ushort(l3) << 16) | __bfloat16_as_ushort(l2);
}

__device__ __forceinline__ void mma_bf16(float* c, const uint32_t* a, const uint32_t* b) {
    asm volatile(
        "mma.sync.aligned.m16n8k16.row.col.f32.bf16.bf16.f32 "
        "{%0,%1,%2,%3}, {%4,%5,%6,%7}, {%8,%9}, {%0,%1,%2,%3};"
        : "+f"(c[0]), "+f"(c[1]), "+f"(c[2]), "+f"(c[3])
        : "r"(a[0]), "r"(a[1]), "r"(a[2]), "r"(a[3]), "r"(b[0]), "r"(b[1]));
}

// ============================================================================
// warp-MMA bf16 hi/lo GEMM core pieces
// smem: A[128][32] and B[128][32] K-major, hi & lo, LDT-padded rows.
// ============================================================================
struct SmemTiles {
    __nv_bfloat16 Ah[128 * LDT];
    __nv_bfloat16 Al[128 * LDT];
    __nv_bfloat16 Bh[128 * LDT];
    __nv_bfloat16 Bl[128 * LDT];
};
#define TG_SMEM (2 * (int)sizeof(SmemTiles))

__device__ __forceinline__ void compute_chunk(SmemTiles* t, float acc[4][4][4],
                                              int wm, int wn, int lane) {
    const int qr = lane >> 2;
    const int qc = lane & 3;
    #pragma unroll
    for (int ks = 0; ks < 2; ks++) {
        const int kb = ks * 16 + qc * 2;
        uint32_t Ahf[4][4], Alf[4][4], Bhf[4][2], Blf[4][2];
        #pragma unroll
        for (int mi = 0; mi < 4; mi++) {
            int r0 = wm * 64 + mi * 16 + qr;
            Ahf[mi][0] = *(const uint32_t*)&t->Ah[r0 * LDT + kb];
            Ahf[mi][1] = *(const uint32_t*)&t->Ah[(r0 + 8) * LDT + kb];
            Ahf[mi][2] = *(const uint32_t*)&t->Ah[r0 * LDT + kb + 8];
            Ahf[mi][3] = *(const uint32_t*)&t->Ah[(r0 + 8) * LDT + kb + 8];
            Alf[mi][0] = *(const uint32_t*)&t->Al[r0 * LDT + kb];
            Alf[mi][1] = *(const uint32_t*)&t->Al[(r0 + 8) * LDT + kb];
            Alf[mi][2] = *(const uint32_t*)&t->Al[r0 * LDT + kb + 8];
            Alf[mi][3] = *(const uint32_t*)&t->Al[(r0 + 8) * LDT + kb + 8];
        }
        #pragma unroll
        for (int ni = 0; ni < 4; ni++) {
            int nr = wn * 32 + ni * 8 + qr;
            Bhf[ni][0] = *(const uint32_t*)&t->Bh[nr * LDT + kb];
            Bhf[ni][1] = *(const uint32_t*)&t->Bh[nr * LDT + kb + 8];
            Blf[ni][0] = *(const uint32_t*)&t->Bl[nr * LDT + kb];
            Blf[ni][1] = *(const uint32_t*)&t->Bl[nr * LDT + kb + 8];
        }
        #pragma unroll
        for (int mi = 0; mi < 4; mi++)
            #pragma unroll
            for (int ni = 0; ni < 4; ni++) {
                mma_bf16(acc[mi][ni], Ahf[mi], Bhf[ni]);
                mma_bf16(acc[mi][ni], Ahf[mi], Blf[ni]);
                mma_bf16(acc[mi][ni], Alf[mi], Bhf[ni]);
            }
    }
}

__device__ __forceinline__ void epilogue(float acc[4][4][4], float* C,
                                         int bm, int bn, int N, int ldc,
                                         int wm, int wn, int lane) {
    const int qr = lane >> 2;
    const int qc = lane & 3;
    #pragma unroll
    for (int mi = 0; mi < 4; mi++) {
        #pragma unroll
        for (int ni = 0; ni < 4; ni++) {
            int r = bm * 128 + wm * 64 + mi * 16 + qr;
            int cc = bn * 128 + wn * 32 + ni * 8 + qc * 2;
            if (cc < N) {
                float2 v0 = make_float2(acc[mi][ni][0], acc[mi][ni][1]);
                float2 v1 = make_float2(acc[mi][ni][2], acc[mi][ni][3]);
                *(float2*)(C + (long long)r * ldc + cc) = v0;
                *(float2*)(C + (long long)(r + 8) * ldc + cc) = v1;
            }
        }
    }
}

// ============================================================================
// NT:  C = A * B^T   (A:[M,K] lda, B:[N,K] ldb).  K%32==0. Double-buffered.
// CAUSAL_SKIP: skip tiles with bn > bm.
// ============================================================================
template<int CAUSAL_SKIP>
__global__ __launch_bounds__(256)
void wgemm_nt(const float* __restrict__ Ag, const float* __restrict__ Bg,
              float* __restrict__ Cg, int M, int N, int K,
              int lda, int ldb, int ldc, long long sA, long long sB, long long sC)
{
    const int bm = blockIdx.y, bn = blockIdx.x;
    if (CAUSAL_SKIP && bn > bm) return;
    extern __shared__ __align__(16) SmemTiles sm[];   // sm[0], sm[1]

    const float* A = Ag + (long long)blockIdx.z * sA;
    const float* B = Bg + (long long)blockIdx.z * sB;
    float*       C = Cg + (long long)blockIdx.z * sC;

    const int tid  = threadIdx.x;
    const int lane = tid & 31;
    const int wid  = tid >> 5;
    const int wm   = wid & 1;
    const int wn   = wid >> 1;

    const int fk = (tid & 7) * 4;
    const int fr = tid >> 3;

    float acc[4][4][4];
    #pragma unroll
    for (int a = 0; a < 4; a++)
        #pragma unroll
        for (int b = 0; b < 4; b++)
            #pragma unroll
            for (int cidx = 0; cidx < 4; cidx++) acc[a][b][cidx] = 0.f;

    uint2 pah[4], pal[4], pbh[4], pbl[4];

    auto fill_regs = [&](int k0) {
        #pragma unroll
        for (int p = 0; p < 4; p++) {
            int row = p * 32 + fr;
            float4 a = *(const float4*)(A + (long long)(bm * 128 + row) * lda + k0 + fk);
            cvt_hilo4(a, pah[p], pal[p]);
            int brow = bn * 128 + row;
            float4 b = (brow < N) ? *(const float4*)(B + (long long)brow * ldb + k0 + fk)
                                  : make_float4(0.f, 0.f, 0.f, 0.f);
            cvt_hilo4(b, pbh[p], pbl[p]);
        }
    };
    auto store_smem = [&](SmemTiles& t) {
        #pragma unroll
        for (int p = 0; p < 4; p++) {
            int row = p * 32 + fr;
            *(uint2*)&t.Ah[row * LDT + fk] = pah[p];
            *(uint2*)&t.Al[row * LDT + fk] = pal[p];
            *(uint2*)&t.Bh[row * LDT + fk] = pbh[p];
            *(uint2*)&t.Bl[row * LDT + fk] = pbl[p];
        }
    };

    const int nchunks = K / 32;
    fill_regs(0);
    store_smem(sm[0]);
    __syncthreads();
    if (nchunks > 1) fill_regs(32);

    for (int c = 0; c < nchunks; c++) {
        compute_chunk(&sm[c & 1], acc, wm, wn, lane);
        if (c + 1 < nchunks) store_smem(sm[(c + 1) & 1]);
        __syncthreads();
        if (c + 2 < nchunks) fill_regs((c + 2) * 32);
    }

    epilogue(acc, C, bm, bn, N, ldc, wm, wn, lane);
}

// ============================================================================
// NN:  C = A * B     (A:[M,K] lda, B:[K,N] ldb).  K%32==0. Double-buffered.
// CAUSAL_KEND: limit K to (bm+1)*128.
// ============================================================================
template<int CAUSAL_KEND>
__global__ __launch_bounds__(256)
void wgemm_nn(const float* __restrict__ Ag, const float* __restrict__ Bg,
              float* __restrict__ Cg, int M, int N, int K,
              int lda, int ldb, int ldc, long long sA, long long sB, long long sC)
{
    const int bm = blockIdx.y, bn = blockIdx.x;
    extern __shared__ __align__(16) SmemTiles sm[];

    const float* A = Ag + (long long)blockIdx.z * sA;
    const float* B = Bg + (long long)blockIdx.z * sB;
    float*       C = Cg + (long long)blockIdx.z * sC;

    const int Kend = CAUSAL_KEND ? min(K, (bm + 1) * 128) : K;

    const int tid  = threadIdx.x;
    const int lane = tid & 31;
    const int wid  = tid >> 5;
    const int wm   = wid & 1;
    const int wn   = wid >> 1;

    const int fk  = (tid & 7) * 4;
    const int fr  = tid >> 3;
    const int bn4 = (tid & 31) * 4;
    const int bkr = tid >> 5;

    float acc[4][4][4];
    #pragma unroll
    for (int a = 0; a < 4; a++)
        #pragma unroll
        for (int b = 0; b < 4; b++)
            #pragma unroll
            for (int cidx = 0; cidx < 4; cidx++) acc[a][b][cidx] = 0.f;

    uint2 pah[4], pal[4], pbh[4], pbl[4];

    auto fill_regs = [&](int k0) {
        #pragma unroll
        for (int p = 0; p < 4; p++) {
            int row = p * 32 + fr;
            float4 a = *(const float4*)(A + (long long)(bm * 128 + row) * lda + k0 + fk);
            cvt_hilo4(a, pah[p], pal[p]);
            int k = p * 8 + bkr;
            float4 b = *(const float4*)(B + (long long)(k0 + k) * ldb + bn * 128 + bn4);
            cvt_hilo4(b, pbh[p], pbl[p]);
        }
    };
    auto store_smem = [&](SmemTiles& t) {
        #pragma unroll
        for (int p = 0; p < 4; p++) {
            int row = p * 32 + fr;
            *(uint2*)&t.Ah[row * LDT + fk] = pah[p];
            *(uint2*)&t.Al[row * LDT + fk] = pal[p];
            int k = p * 8 + bkr;
            t.Bh[(bn4 + 0) * LDT + k] = __ushort_as_bfloat16((uint16_t)(pbh[p].x));
            t.Bh[(bn4 + 1) * LDT + k] = __ushort_as_bfloat16((uint16_t)(pbh[p].x >> 16));
            t.Bh[(bn4 + 2) * LDT + k] = __ushort_as_bfloat16((uint16_t)(pbh[p].y));
            t.Bh[(bn4 + 3) * LDT + k] = __ushort_as_bfloat16((uint16_t)(pbh[p].y >> 16));
            t.Bl[(bn4 + 0) * LDT + k] = __ushort_as_bfloat16((uint16_t)(pbl[p].x));
            t.Bl[(bn4 + 1) * LDT + k] = __ushort_as_bfloat16((uint16_t)(pbl[p].x >> 16));
            t.Bl[(bn4 + 2) * LDT + k] = __ushort_as_bfloat16((uint16_t)(pbl[p].y));
            t.Bl[(bn4 + 3) * LDT + k] = __ushort_as_bfloat16((uint16_t)(pbl[p].y >> 16));
        }
    };

    const int nchunks = Kend / 32;
    fill_regs(0);
    store_smem(sm[0]);
    __syncthreads();
    if (nchunks > 1) fill_regs(32);

    for (int c = 0; c < nchunks; c++) {
        compute_chunk(&sm[c & 1], acc, wm, wn, lane);
        if (c + 1 < nchunks) store_smem(sm[(c + 1) & 1]);
        __syncthreads();
        if (c + 2 < nchunks) fill_regs((c + 2) * 32);
    }

    epilogue(acc, C, bm, bn, N, ldc, wm, wn, lane);
}

// ============================================================================
// elementwise / normalization kernels (unchanged, proven correct)
// ============================================================================
__global__ void rmsnorm_rows(float* __restrict__ X, const float* __restrict__ g, int n)
{
    float* x = X + (long long)blockIdx.x * n;
    __shared__ float red[256];
    const int tid = threadIdx.x;
    float s = 0.f;
    for (int i = tid; i < n; i += 256) { float v = x[i]; s += v * v; }
    red[tid] = s; __syncthreads();
    for (int o = 128; o > 0; o >>= 1) {
        if (tid < o) red[tid] += red[tid + o];
        __syncthreads();
    }
    float inv = rsqrtf(red[0] / (float)n + EPSV);
    for (int i = tid; i < n; i += 256) x[i] = x[i] * inv * g[i];
}

__global__ void kv_post(float* __restrict__ KV, const float* __restrict__ g,
                        const float* __restrict__ cosb, const float* __restrict__ sinb)
{
    const int srow = blockIdx.x;
    float* x = KV + (long long)srow * KEFF;
    __shared__ float red[256];
    const int tid = threadIdx.x;
    float s = 0.f;
    for (int i = tid; i < KVLORA; i += 256) { float v = x[i]; s += v * v; }
    red[tid] = s; __syncthreads();
    for (int o = 128; o > 0; o >>= 1) {
        if (tid < o) red[tid] += red[tid + o];
        __syncthreads();
    }
    float inv = rsqrtf(red[0] / (float)KVLORA + EPSV);
    for (int i = tid; i < KVLORA; i += 256) x[i] = x[i] * inv * g[i];
    if (tid < 32) {
        float x1 = x[KVLORA + tid];
        float x2 = x[KVLORA + 32 + tid];
        float c1 = cosb[srow * ROPEW + tid];
        float c2 = cosb[srow * ROPEW + 32 + tid];
        float s1 = sinb[srow * ROPEW + tid];
        float s2 = sinb[srow * ROPEW + 32 + tid];
        x[KVLORA + tid]      = x1 * c1 - x2 * s1;
        x[KVLORA + 32 + tid] = x2 * c2 + x1 * s2;
    }
}

__global__ void q_rope(const float* __restrict__ Q, float* __restrict__ Qeff,
                       const float* __restrict__ cosb, const float* __restrict__ sinb)
{
    long long idx = (long long)blockIdx.x * blockDim.x + threadIdx.x;
    const long long total = (long long)SS * HH * 32;
    if (idx >= total) return;
    int j  = (int)(idx & 31);
    long long sh = idx >> 5;
    int h = (int)(sh & (HH - 1));
    int s = (int)(sh >> 5);
    const float* q = Q + ((long long)s * HH + h) * QKH + NOPEW;
    float x1 = q[j], x2 = q[j + 32];
    float c1 = cosb[s * ROPEW + j];
    float c2 = cosb[s * ROPEW + 32 + j];
    float s1 = sinb[s * ROPEW + j];
    float s2 = sinb[s * ROPEW + 32 + j];
    float* o = Qeff + ((long long)h * SS + s) * KEFF + KVLORA;
    o[j]      = x1 * c1 - x2 * s1;
    o[j + 32] = x2 * c2 + x1 * s2;
}

__global__ void softmax_causal(float* __restrict__ Sc)
{
    const int m = blockIdx.x;
    const int h = blockIdx.y;
    float* row = Sc + ((long long)h * SS + m) * SS;
    const int len = m + 1;
    const int pad = ((m >> 7) + 1) << 7;
    const int tid = threadIdx.x;
    __shared__ float red[256];

    float mx = -3.4e38f;
    for (int i = tid; i < len; i += 256) mx = fmaxf(mx, row[i]);
    red[tid] = mx; __syncthreads();
    for (int o = 128; o > 0; o >>= 1) {
        if (tid < o) red[tid] = fmaxf(red[tid], red[tid + o]);
        __syncthreads();
    }
    const float rowmax = red[0];
    __syncthreads();

    float sum = 0.f;
    for (int i = tid; i < len; i += 256) {
        float e = expf(SCALE * (row[i] - rowmax));
        row[i] = e;
        sum += e;
    }
    red[tid] = sum; __syncthreads();
    for (int o = 128; o > 0; o >>= 1) {
        if (tid < o) red[tid] += red[tid + o];
        __syncthreads();
    }
    const float rinv = 1.f / red[0];
    for (int i = tid; i < len; i += 256) row[i] *= rinv;
    for (int i = len + tid; i < pad; i += 256) row[i] = 0.f;
}

// ============================================================================
extern "C" void kernel_launch(void* const* d_in, const int* in_sizes, int n_in,
                              void* d_out, int out_size)
{
    (void)in_sizes; (void)n_in; (void)out_size;
    const float* h      = (const float*)d_in[0];
    const float* cosb   = (const float*)d_in[1];
    const float* sinb   = (const float*)d_in[2];
    const float* w_q_a  = (const float*)d_in[3];
    const float* gq     = (const float*)d_in[4];
    const float* w_q_b  = (const float*)d_in[5];
    const float* w_kv_a = (const float*)d_in[6];
    const float* gkv    = (const float*)d_in[7];
    const float* w_uk   = (const float*)d_in[8];
    const float* w_uv   = (const float*)d_in[9];
    const float* w_o    = (const float*)d_in[10];
    float* out = (float*)d_out;

    float *qa, *q, *keff, *qeff, *sc, *ctxl, *ctx;
    cudaGetSymbolAddress((void**)&qa,   g_qa);
    cudaGetSymbolAddress((void**)&q,    g_q);
    cudaGetSymbolAddress((void**)&keff, g_keff);
    cudaGetSymbolAddress((void**)&qeff, g_qeff);
    cudaGetSymbolAddress((void**)&sc,   g_scores);
    cudaGetSymbolAddress((void**)&ctxl, g_ctxl);
    cudaGetSymbolAddress((void**)&ctx,  g_ctx);

    static bool attr_done = false;
    if (!attr_done) {
        cudaFuncSetAttribute(wgemm_nt<0>, cudaFuncAttributeMaxDynamicSharedMemorySize, TG_SMEM);
        cudaFuncSetAttribute(wgemm_nt<1>, cudaFuncAttributeMaxDynamicSharedMemorySize, TG_SMEM);
        cudaFuncSetAttribute(wgemm_nn<0>, cudaFuncAttributeMaxDynamicSharedMemorySize, TG_SMEM);
        cudaFuncSetAttribute(wgemm_nn<1>, cudaFuncAttributeMaxDynamicSharedMemorySize, TG_SMEM);
        attr_done = true;
    }

    // 1) q_a = h @ w_q_a^T           [2048,1536], K=4096
    wgemm_nt<0><<<dim3(QLORA/128, SS/128, 1), 256, TG_SMEM>>>(
        h, w_q_a, qa, SS, QLORA, DD, DD, DD, QLORA, 0, 0, 0);
    // 2) rmsnorm(q_a)
    rmsnorm_rows<<<SS, 256>>>(qa, gq, QLORA);
    // 3) q = q_a @ w_q_b^T           [2048,6144], K=1536
    wgemm_nt<0><<<dim3((HH*QKH)/128, SS/128, 1), 256, TG_SMEM>>>(
        qa, w_q_b, q, SS, HH*QKH, QLORA, QLORA, QLORA, HH*QKH, 0, 0, 0);
    // 4) kv = h @ w_kv_a^T           [2048,576], K=4096
    wgemm_nt<0><<<dim3((KEFF+127)/128, SS/128, 1), 256, TG_SMEM>>>(
        h, w_kv_a, keff, SS, KEFF, DD, DD, DD, KEFF, 0, 0, 0);
    // 5) kv post: rmsnorm + rope -> k_eff
    kv_post<<<SS, 256>>>(keff, gkv, cosb, sinb);
    // 6) q_latent per head: q_eff[h][:,0:512] = q_nope_h @ w_uk_t[h], K=128
    wgemm_nn<0><<<dim3(KVLORA/128, SS/128, HH), 256, TG_SMEM>>>(
        q, w_uk, qeff, SS, KVLORA, NOPEW,
        HH*QKH, KVLORA, KEFF,
        (long long)QKH, (long long)NOPEW*KVLORA, (long long)SS*KEFF);
    // 7) q rope -> q_eff[h][:,512:576]
    {
        long long total = (long long)SS * HH * 32;
        q_rope<<<(unsigned)((total + 255) / 256), 256>>>(q, qeff, cosb, sinb);
    }
    // 8) scores[h] = q_eff[h] @ k_eff^T, K=576 (skip tiles above diagonal)
    wgemm_nt<1><<<dim3(SS/128, SS/128, HH), 256, TG_SMEM>>>(
        qeff, keff, sc, SS, SS, KEFF, KEFF, KEFF, SS,
        (long long)SS*KEFF, 0, (long long)SS*SS);
    // 9) causal softmax (+ zero pad to 128 boundary)
    softmax_causal<<<dim3(SS, HH), 256>>>(sc);
    // 10) ctx_latent[h] = P[h] @ kv_c   (K limited to (bm+1)*128)
    wgemm_nn<1><<<dim3(KVLORA/128, SS/128, HH), 256, TG_SMEM>>>(
        sc, keff, ctxl, SS, KVLORA, SS,
        SS, KEFF, KVLORA,
        (long long)SS*SS, 0, (long long)SS*KVLORA);
    // 11) ctx[s, h*128+v] = ctx_latent[h] @ w_uv[h], K=512
    wgemm_nn<0><<<dim3(1, SS/128, HH), 256, TG_SMEM>>>(
        ctxl, w_uv, ctx, SS, VH, KVLORA,
        KVLORA, VH, HH*VH,
        (long long)SS*KVLORA, (long long)KVLORA*VH, (long long)VH);
    // 12) out = ctx @ w_o^T           [2048,4096], K=4096
    wgemm_nt<0><<<dim3(DD/128, SS/128, 1), 256, TG_SMEM>>>(
        ctx, w_o, out, SS, DD, HH*VH, HH*VH, HH*VH, DD, 0, 0, 0);
}

// round 5
// speedup vs baseline: 2.9084x; 1.9346x over previous
#include <cuda_runtime.h>
#include <cuda_bf16.h>
#include <stdint.h>
#include <math.h>

// ---------------- problem constants ----------------
#define SS 2048
#define DD 4096
#define HH 32
#define QLORA 1536
#define KVLORA 512
#define ROPEW 64
#define NOPEW 128
#define QKH 192
#define VH 128
#define KEFF 576
#define EPSV 1e-6f
#define SCALE 0.07216878364870322f   // 1/sqrt(192)

typedef __nv_bfloat16 bf16;

// ---------------- scratch ----------------
// fp32
__device__ float g_qa_f[(size_t)SS * QLORA];
__device__ float g_keff_f[(size_t)SS * KEFF];
__device__ float g_scores[(size_t)HH * SS * SS];
// bf16 hi/lo pairs
__device__ bf16 g_hh[(size_t)SS * DD],            g_hl[(size_t)SS * DD];
__device__ bf16 g_wqa_h[(size_t)QLORA * DD],      g_wqa_l[(size_t)QLORA * DD];
__device__ bf16 g_wqb_h[(size_t)HH*QKH * QLORA],  g_wqb_l[(size_t)HH*QKH * QLORA];
__device__ bf16 g_wkva_h[(size_t)KEFF * DD],      g_wkva_l[(size_t)KEFF * DD];
__device__ bf16 g_wo_h[(size_t)DD * HH*VH],       g_wo_l[(size_t)DD * HH*VH];
__device__ bf16 g_wukt_h[(size_t)HH*KVLORA*NOPEW],g_wukt_l[(size_t)HH*KVLORA*NOPEW]; // [h][c=512][n=128]
__device__ bf16 g_wuvt_h[(size_t)HH*VH*KVLORA],   g_wuvt_l[(size_t)HH*VH*KVLORA];    // [h][v=128][c=512]
__device__ bf16 g_qa_h[(size_t)SS * QLORA],       g_qa_l[(size_t)SS * QLORA];
__device__ bf16 g_q_h[(size_t)SS * HH*QKH],       g_q_l[(size_t)SS * HH*QKH];
__device__ bf16 g_keff_h[(size_t)SS * KEFF],      g_keff_l[(size_t)SS * KEFF];
__device__ bf16 g_kvct_h[(size_t)KVLORA * SS],    g_kvct_l[(size_t)KVLORA * SS];     // [c=512][s=2048]
__device__ bf16 g_qeff_h[(size_t)HH*SS*KEFF],     g_qeff_l[(size_t)HH*SS*KEFF];
__device__ bf16 g_p_h[(size_t)HH*SS*SS],          g_p_l[(size_t)HH*SS*SS];
__device__ bf16 g_ctxl_h[(size_t)HH*SS*KVLORA],   g_ctxl_l[(size_t)HH*SS*KVLORA];
__device__ bf16 g_ctx_h[(size_t)SS * HH*VH],      g_ctx_l[(size_t)SS * HH*VH];

// ---------------- helpers ----------------
__device__ __forceinline__ uint32_t smem_u32(const void* p) {
    uint32_t a;
    asm("{ .reg .u64 t; cvta.to.shared.u64 t, %1; cvt.u32.u64 %0, t; }" : "=r"(a) : "l"(p));
    return a;
}

__device__ __forceinline__ void hilo1(float v, bf16& h, bf16& l) {
    h = __float2bfloat16(v);
    l = __float2bfloat16(v - __bfloat162float(h));
}
__device__ __forceinline__ void cvt_hilo4(float4 v, uint2& hi, uint2& lo) {
    bf16 h0, h1, h2, h3, l0, l1, l2, l3;
    hilo1(v.x, h0, l0); hilo1(v.y, h1, l1); hilo1(v.z, h2, l2); hilo1(v.w, h3, l3);
    hi.x = ((uint32_t)__bfloat16_as_ushort(h1) << 16) | __bfloat16_as_ushort(h0);
    hi.y = ((uint32_t)__bfloat16_as_ushort(h3) << 16) | __bfloat16_as_ushort(h2);
    lo.x = ((uint32_t)__bfloat16_as_ushort(l1) << 16) | __bfloat16_as_ushort(l0);
    lo.y = ((uint32_t)__bfloat16_as_ushort(l3) << 16) | __bfloat16_as_ushort(l2);
}
__device__ __forceinline__ void hilo2pack(float a, float b, uint32_t& h, uint32_t& l) {
    bf16 ha, hb, la, lb;
    hilo1(a, ha, la); hilo1(b, hb, lb);
    h = ((uint32_t)__bfloat16_as_ushort(hb) << 16) | __bfloat16_as_ushort(ha);
    l = ((uint32_t)__bfloat16_as_ushort(lb) << 16) | __bfloat16_as_ushort(la);
}

__device__ __forceinline__ void mma_bf16(float* c, const uint32_t* a, const uint32_t* b) {
    asm volatile(
        "mma.sync.aligned.m16n8k16.row.col.f32.bf16.bf16.f32 "
        "{%0,%1,%2,%3}, {%4,%5,%6,%7}, {%8,%9}, {%0,%1,%2,%3};"
        : "+f"(c[0]), "+f"(c[1]), "+f"(c[2]), "+f"(c[3])
        : "r"(a[0]), "r"(a[1]), "r"(a[2]), "r"(a[3]), "r"(b[0]), "r"(b[1]));
}

#define LDMX4(r0, r1, r2, r3, addr) \
    asm volatile("ldmatrix.sync.aligned.m8n8.x4.shared.b16 {%0,%1,%2,%3}, [%4];" \
        : "=r"(r0), "=r"(r1), "=r"(r2), "=r"(r3) : "r"(addr))

#define CPA16(dst, src, sz) \
    asm volatile("cp.async.cg.shared.global [%0], [%1], 16, %2;" \
        :: "r"(dst), "l"(src), "r"(sz))
#define CPA_COMMIT()  asm volatile("cp.async.commit_group;" ::: "memory")
#define CPA_WAIT1()   asm volatile("cp.async.wait_group 1;" ::: "memory")

// smem layout: per stage 4 arrays (Ah, Al, Bh, Bl), each 128 rows x 40 bf16 (80B rows)
#define LDT 40
#define ARR_B   (128 * LDT * 2)      // 10240
#define CHUNK_B (4 * ARR_B)          // 40960
#define NSTAGE  2
#define GSMEM   (NSTAGE * CHUNK_B)   // 81920

// ============================================================================
// Unified NT GEMM: C = A * B^T, A/B given as bf16 hi/lo [rows][K] K-major.
// 3-term emulation: Ah*Bh + Ah*Bl + Al*Bh, fp32 acc. M always full tiles.
// CSKIP: skip tiles bn > bm.  CKEND: K limited to (bm+1)*128.
// OUT_HILO: write Ch/Cl bf16 hi/lo, else write C fp32.
// ============================================================================
template<int CSKIP, int CKEND, int OUT_HILO>
__global__ void __launch_bounds__(256, 2)
hgemm(const bf16* __restrict__ Ah, const bf16* __restrict__ Al,
      const bf16* __restrict__ Bh, const bf16* __restrict__ Bl,
      float* __restrict__ C, bf16* __restrict__ Ch, bf16* __restrict__ Cl,
      int M, int N, int K, int lda, int ldb, int ldc,
      long long sA, long long sB, long long sC)
{
    const int bm = blockIdx.y, bn = blockIdx.x;
    if (CSKIP && bn > bm) return;
    extern __shared__ char smem[];
    const uint32_t sbase = smem_u32(smem);

    const int tid = threadIdx.x, lane = tid & 31, wid = tid >> 5;
    const int wm = wid & 1, wn = wid >> 1;

    Ah += (long long)blockIdx.z * sA;  Al += (long long)blockIdx.z * sA;
    Bh += (long long)blockIdx.z * sB;  Bl += (long long)blockIdx.z * sB;

    const int Kend = CKEND ? min(K, (bm + 1) * 128) : K;
    const int nch = Kend / 32;

    // ---- cp.async machinery: 8 x 16B per thread per chunk ----
    const int ch = tid & 3;            // 16B chunk within 64B row payload
    const int rr = tid >> 2;           // 0..63
    const int ar0 = bm * 128 + rr;
    const int br0 = bn * 128 + rr, br1 = br0 + 64;
    const uint32_t szB0 = (br0 < N) ? 16u : 0u;
    const uint32_t szB1 = (br1 < N) ? 16u : 0u;
    const bf16* pAh0 = Ah + (long long)ar0 * lda + ch * 8;
    const bf16* pAh1 = pAh0 + (long long)64 * lda;
    const bf16* pAl0 = Al + (long long)ar0 * lda + ch * 8;
    const bf16* pAl1 = pAl0 + (long long)64 * lda;
    const bf16* pBh0 = Bh + (long long)min(br0, N - 1) * ldb + ch * 8;
    const bf16* pBh1 = Bh + (long long)min(br1, N - 1) * ldb + ch * 8;
    const bf16* pBl0 = Bl + (long long)min(br0, N - 1) * ldb + ch * 8;
    const bf16* pBl1 = Bl + (long long)min(br1, N - 1) * ldb + ch * 8;
    const uint32_t d0 = (uint32_t)(rr * 80 + ch * 16);
    const uint32_t d1 = d0 + 64 * 80;

    auto issue = [&](int slot) {
        uint32_t st = sbase + slot * CHUNK_B;
        CPA16(st + 0 * ARR_B + d0, pAh0, 16u);
        CPA16(st + 0 * ARR_B + d1, pAh1, 16u);
        CPA16(st + 1 * ARR_B + d0, pAl0, 16u);
        CPA16(st + 1 * ARR_B + d1, pAl1, 16u);
        CPA16(st + 2 * ARR_B + d0, pBh0, szB0);
        CPA16(st + 2 * ARR_B + d1, pBh1, szB1);
        CPA16(st + 3 * ARR_B + d0, pBl0, szB0);
        CPA16(st + 3 * ARR_B + d1, pBl1, szB1);
        pAh0 += 32; pAh1 += 32; pAl0 += 32; pAl1 += 32;
        pBh0 += 32; pBh1 += 32; pBl0 += 32; pBl1 += 32;
    };

    // ---- ldmatrix per-lane base offsets ----
    const int arow_l = wm * 64 + ((lane >> 3) & 1) * 8 + (lane & 7);
    const int acol_l = (lane >> 4) * 8;
    const uint32_t aoff = (uint32_t)(arow_l * LDT + acol_l) * 2;   // + mi*1280 + ks*32
    const int brow_l = wn * 32 + ((lane >> 4) & 1) * 8 + (lane & 7);
    const int bcol_l = ((lane >> 3) & 1) * 8;
    const uint32_t boff = (uint32_t)(brow_l * LDT + bcol_l) * 2;   // + p*1280 + ks*32

    float acc[4][4][4];
    #pragma unroll
    for (int a = 0; a < 4; a++)
        #pragma unroll
        for (int b = 0; b < 4; b++)
            #pragma unroll
            for (int q = 0; q < 4; q++) acc[a][b][q] = 0.f;

    issue(0);
    CPA_COMMIT();

    for (int c = 0; c < nch; c++) {
        if (c + 1 < nch) issue((c + 1) & 1);
        CPA_COMMIT();
        CPA_WAIT1();                       // chunk c arrived
        __syncthreads();
        const uint32_t st = sbase + (c & 1) * CHUNK_B;
        #pragma unroll
        for (int ks = 0; ks < 2; ks++) {
            const uint32_t kof = ks * 32;
            uint32_t ah[4][4], al[4][4], bh[4][2], bl[4][2];
            #pragma unroll
            for (int mi = 0; mi < 4; mi++) {
                LDMX4(ah[mi][0], ah[mi][1], ah[mi][2], ah[mi][3],
                      st + 0 * ARR_B + aoff + mi * 1280 + kof);
                LDMX4(al[mi][0], al[mi][1], al[mi][2], al[mi][3],
                      st + 1 * ARR_B + aoff + mi * 1280 + kof);
            }
            #pragma unroll
            for (int p = 0; p < 2; p++) {
                LDMX4(bh[2*p][0], bh[2*p][1], bh[2*p+1][0], bh[2*p+1][1],
                      st + 2 * ARR_B + boff + p * 1280 + kof);
                LDMX4(bl[2*p][0], bl[2*p][1], bl[2*p+1][0], bl[2*p+1][1],
                      st + 3 * ARR_B + boff + p * 1280 + kof);
            }
            #pragma unroll
            for (int mi = 0; mi < 4; mi++)
                #pragma unroll
                for (int ni = 0; ni < 4; ni++) {
                    mma_bf16(acc[mi][ni], ah[mi], bh[ni]);
                    mma_bf16(acc[mi][ni], ah[mi], bl[ni]);
                    mma_bf16(acc[mi][ni], al[mi], bh[ni]);
                }
        }
        __syncthreads();
    }

    // ---- epilogue ----
    const int qr = lane >> 2, qc = lane & 3;
    if (OUT_HILO) {
        bf16* chp = Ch + (long long)blockIdx.z * sC;
        bf16* clp = Cl + (long long)blockIdx.z * sC;
        #pragma unroll
        for (int mi = 0; mi < 4; mi++)
            #pragma unroll
            for (int ni = 0; ni < 4; ni++) {
                int r = bm * 128 + wm * 64 + mi * 16 + qr;
                int cc = bn * 128 + wn * 32 + ni * 8 + qc * 2;
                if (cc < N) {
                    uint32_t h0, l0, h1, l1;
                    hilo2pack(acc[mi][ni][0], acc[mi][ni][1], h0, l0);
                    hilo2pack(acc[mi][ni][2], acc[mi][ni][3], h1, l1);
                    *(uint32_t*)(chp + (long long)r * ldc + cc) = h0;
                    *(uint32_t*)(clp + (long long)r * ldc + cc) = l0;
                    *(uint32_t*)(chp + (long long)(r + 8) * ldc + cc) = h1;
                    *(uint32_t*)(clp + (long long)(r + 8) * ldc + cc) = l1;
                }
            }
    } else {
        float* cp = C + (long long)blockIdx.z * sC;
        #pragma unroll
        for (int mi = 0; mi < 4; mi++)
            #pragma unroll
            for (int ni = 0; ni < 4; ni++) {
                int r = bm * 128 + wm * 64 + mi * 16 + qr;
                int cc = bn * 128 + wn * 32 + ni * 8 + qc * 2;
                if (cc < N) {
                    *(float2*)(cp + (long long)r * ldc + cc) =
                        make_float2(acc[mi][ni][0], acc[mi][ni][1]);
                    *(float2*)(cp + (long long)(r + 8) * ldc + cc) =
                        make_float2(acc[mi][ni][2], acc[mi][ni][3]);
                }
            }
    }
}

// ============================================================================
// conversion / elementwise kernels
// ============================================================================
__global__ void cvt_hilo_k(const float* __restrict__ in, bf16* __restrict__ oh,
                           bf16* __restrict__ ol, long long n)
{
    long long i = ((long long)blockIdx.x * 256 + threadIdx.x) * 4;
    if (i >= n) return;
    float4 v = *(const float4*)(in + i);
    uint2 h, l; cvt_hilo4(v, h, l);
    *(uint2*)(oh + i) = h;
    *(uint2*)(ol + i) = l;
}

// out[c][r] = in[r][c]; grid: (C/32, R/32, batch); 256 threads
__global__ void transcvt_k(const float* __restrict__ in, bf16* __restrict__ oh,
                           bf16* __restrict__ ol, int ld_in, int ld_out,
                           long long sIn, long long sOut)
{
    __shared__ float tile[32][33];
    const float* ip = in + (long long)blockIdx.z * sIn;
    int r0 = blockIdx.y * 32, c0 = blockIdx.x * 32;
    int tx = threadIdx.x & 31, ty = threadIdx.x >> 5;
    #pragma unroll
    for (int it = 0; it < 4; it++) {
        int r = ty + it * 8;
        tile[r][tx] = ip[(long long)(r0 + r) * ld_in + c0 + tx];
    }
    __syncthreads();
    #pragma unroll
    for (int it = 0; it < 4; it++) {
        int cr = ty + it * 8;
        float v = tile[tx][cr];
        bf16 hb, lb; hilo1(v, hb, lb);
        long long o = (long long)blockIdx.z * sOut + (long long)(c0 + cr) * ld_out + r0 + tx;
        oh[o] = hb; ol[o] = lb;
    }
}

__global__ void rmsnorm_hilo(const float* __restrict__ X, const float* __restrict__ g,
                             bf16* __restrict__ oh, bf16* __restrict__ ol, int n)
{
    const float* x = X + (long long)blockIdx.x * n;
    bf16* ph = oh + (long long)blockIdx.x * n;
    bf16* pl = ol + (long long)blockIdx.x * n;
    __shared__ float red[256];
    const int tid = threadIdx.x;
    float s = 0.f;
    for (int i = tid; i < n; i += 256) { float v = x[i]; s += v * v; }
    red[tid] = s; __syncthreads();
    for (int o = 128; o > 0; o >>= 1) {
        if (tid < o) red[tid] += red[tid + o];
        __syncthreads();
    }
    float inv = rsqrtf(red[0] / (float)n + EPSV);
    for (int i = tid; i < n; i += 256) {
        bf16 hb, lb; hilo1(x[i] * inv * g[i], hb, lb);
        ph[i] = hb; pl[i] = lb;
    }
}

__global__ void kv_post(float* __restrict__ KV, const float* __restrict__ g,
                        const float* __restrict__ cosb, const float* __restrict__ sinb,
                        bf16* __restrict__ oh, bf16* __restrict__ ol)
{
    const int srow = blockIdx.x;
    float* x = KV + (long long)srow * KEFF;
    bf16* ph = oh + (long long)srow * KEFF;
    bf16* pl = ol + (long long)srow * KEFF;
    __shared__ float red[256];
    const int tid = threadIdx.x;
    float s = 0.f;
    for (int i = tid; i < KVLORA; i += 256) { float v = x[i]; s += v * v; }
    red[tid] = s; __syncthreads();
    for (int o = 128; o > 0; o >>= 1) {
        if (tid < o) red[tid] += red[tid + o];
        __syncthreads();
    }
    float inv = rsqrtf(red[0] / (float)KVLORA + EPSV);
    for (int i = tid; i < KVLORA; i += 256) x[i] = x[i] * inv * g[i];
    if (tid < 32) {
        float x1 = x[KVLORA + tid];
        float x2 = x[KVLORA + 32 + tid];
        float c1 = cosb[srow * ROPEW + tid];
        float c2 = cosb[srow * ROPEW + 32 + tid];
        float s1 = sinb[srow * ROPEW + tid];
        float s2 = sinb[srow * ROPEW + 32 + tid];
        x[KVLORA + tid]      = x1 * c1 - x2 * s1;
        x[KVLORA + 32 + tid] = x2 * c2 + x1 * s2;
    }
    __syncthreads();
    for (int i = tid; i < KEFF; i += 256) {
        bf16 hb, lb; hilo1(x[i], hb, lb);
        ph[i] = hb; pl[i] = lb;
    }
}

__global__ void q_rope(const bf16* __restrict__ Qh, const bf16* __restrict__ Ql,
                       bf16* __restrict__ Eh, bf16* __restrict__ El,
                       const float* __restrict__ cosb, const float* __restrict__ sinb)
{
    long long idx = (long long)blockIdx.x * blockDim.x + threadIdx.x;
    const long long total = (long long)SS * HH * 32;
    if (idx >= total) return;
    int j  = (int)(idx & 31);
    long long sh = idx >> 5;
    int h = (int)(sh & (HH - 1));
    int s = (int)(sh >> 5);
    long long qb = ((long long)s * HH + h) * QKH + NOPEW;
    float x1 = __bfloat162float(Qh[qb + j]) + __bfloat162float(Ql[qb + j]);
    float x2 = __bfloat162float(Qh[qb + j + 32]) + __bfloat162float(Ql[qb + j + 32]);
    float c1 = cosb[s * ROPEW + j];
    float c2 = cosb[s * ROPEW + 32 + j];
    float s1 = sinb[s * ROPEW + j];
    float s2 = sinb[s * ROPEW + 32 + j];
    long long ob = ((long long)h * SS + s) * KEFF + KVLORA;
    bf16 hb, lb;
    hilo1(x1 * c1 - x2 * s1, hb, lb);   Eh[ob + j] = hb;      El[ob + j] = lb;
    hilo1(x2 * c2 + x1 * s2, hb, lb);   Eh[ob + j + 32] = hb; El[ob + j + 32] = lb;
}

__global__ void softmax_causal(const float* __restrict__ Sc,
                               bf16* __restrict__ Ph, bf16* __restrict__ Pl)
{
    __shared__ float buf[SS];
    __shared__ float red[256];
    const int m = blockIdx.x;
    const int h = blockIdx.y;
    const float* row = Sc + ((long long)h * SS + m) * SS;
    bf16* ph = Ph + ((long long)h * SS + m) * SS;
    bf16* pl = Pl + ((long long)h * SS + m) * SS;
    const int len = m + 1;
    const int pad = ((m >> 7) + 1) << 7;
    const int tid = threadIdx.x;

    float mx = -3.4e38f;
    for (int i = tid; i < len; i += 256) { float v = row[i]; buf[i] = v; mx = fmaxf(mx, v); }
    red[tid] = mx; __syncthreads();
    for (int o = 128; o > 0; o >>= 1) {
        if (tid < o) red[tid] = fmaxf(red[tid], red[tid + o]);
        __syncthreads();
    }
    const float rowmax = red[0];
    __syncthreads();

    float sum = 0.f;
    for (int i = tid; i < len; i += 256) {
        float e = expf(SCALE * (buf[i] - rowmax));
        buf[i] = e;
        sum += e;
    }
    red[tid] = sum; __syncthreads();
    for (int o = 128; o > 0; o >>= 1) {
        if (tid < o) red[tid] += red[tid + o];
        __syncthreads();
    }
    const float rinv = 1.f / red[0];
    for (int i = tid; i < len; i += 256) {
        bf16 hb, lb; hilo1(buf[i] * rinv, hb, lb);
        ph[i] = hb; pl[i] = lb;
    }
    const bf16 z = __float2bfloat16(0.f);
    for (int i = len + tid; i < pad; i += 256) { ph[i] = z; pl[i] = z; }
}

// ============================================================================
extern "C" void kernel_launch(void* const* d_in, const int* in_sizes, int n_in,
                              void* d_out, int out_size)
{
    (void)in_sizes; (void)n_in; (void)out_size;
    const float* h      = (const float*)d_in[0];
    const float* cosb   = (const float*)d_in[1];
    const float* sinb   = (const float*)d_in[2];
    const float* w_q_a  = (const float*)d_in[3];
    const float* gq     = (const float*)d_in[4];
    const float* w_q_b  = (const float*)d_in[5];
    const float* w_kv_a = (const float*)d_in[6];
    const float* gkv    = (const float*)d_in[7];
    const float* w_uk   = (const float*)d_in[8];
    const float* w_uv   = (const float*)d_in[9];
    const float* w_o    = (const float*)d_in[10];
    float* out = (float*)d_out;

    float *qa_f, *keff_f, *sc;
    bf16 *hh, *hl, *wqa_h, *wqa_l, *wqb_h, *wqb_l, *wkva_h, *wkva_l, *wo_h, *wo_l;
    bf16 *wukt_h, *wukt_l, *wuvt_h, *wuvt_l, *qa_h, *qa_l, *q_h, *q_l;
    bf16 *keff_h, *keff_l, *kvct_h, *kvct_l, *qeff_h, *qeff_l;
    bf16 *p_h, *p_l, *ctxl_h, *ctxl_l, *ctx_h, *ctx_l;
    cudaGetSymbolAddress((void**)&qa_f,   g_qa_f);
    cudaGetSymbolAddress((void**)&keff_f, g_keff_f);
    cudaGetSymbolAddress((void**)&sc,     g_scores);
    cudaGetSymbolAddress((void**)&hh,     g_hh);     cudaGetSymbolAddress((void**)&hl,     g_hl);
    cudaGetSymbolAddress((void**)&wqa_h,  g_wqa_h);  cudaGetSymbolAddress((void**)&wqa_l,  g_wqa_l);
    cudaGetSymbolAddress((void**)&wqb_h,  g_wqb_h);  cudaGetSymbolAddress((void**)&wqb_l,  g_wqb_l);
    cudaGetSymbolAddress((void**)&wkva_h, g_wkva_h); cudaGetSymbolAddress((void**)&wkva_l, g_wkva_l);
    cudaGetSymbolAddress((void**)&wo_h,   g_wo_h);   cudaGetSymbolAddress((void**)&wo_l,   g_wo_l);
    cudaGetSymbolAddress((void**)&wukt_h, g_wukt_h); cudaGetSymbolAddress((void**)&wukt_l, g_wukt_l);
    cudaGetSymbolAddress((void**)&wuvt_h, g_wuvt_h); cudaGetSymbolAddress((void**)&wuvt_l, g_wuvt_l);
    cudaGetSymbolAddress((void**)&qa_h,   g_qa_h);   cudaGetSymbolAddress((void**)&qa_l,   g_qa_l);
    cudaGetSymbolAddress((void**)&q_h,    g_q_h);    cudaGetSymbolAddress((void**)&q_l,    g_q_l);
    cudaGetSymbolAddress((void**)&keff_h, g_keff_h); cudaGetSymbolAddress((void**)&keff_l, g_keff_l);
    cudaGetSymbolAddress((void**)&kvct_h, g_kvct_h); cudaGetSymbolAddress((void**)&kvct_l, g_kvct_l);
    cudaGetSymbolAddress((void**)&qeff_h, g_qeff_h); cudaGetSymbolAddress((void**)&qeff_l, g_qeff_l);
    cudaGetSymbolAddress((void**)&p_h,    g_p_h);    cudaGetSymbolAddress((void**)&p_l,    g_p_l);
    cudaGetSymbolAddress((void**)&ctxl_h, g_ctxl_h); cudaGetSymbolAddress((void**)&ctxl_l, g_ctxl_l);
    cudaGetSymbolAddress((void**)&ctx_h,  g_ctx_h);  cudaGetSymbolAddress((void**)&ctx_l,  g_ctx_l);

    cudaFuncSetAttribute(hgemm<0,0,0>, cudaFuncAttributeMaxDynamicSharedMemorySize, GSMEM);
    cudaFuncSetAttribute(hgemm<0,0,1>, cudaFuncAttributeMaxDynamicSharedMemorySize, GSMEM);
    cudaFuncSetAttribute(hgemm<1,0,0>, cudaFuncAttributeMaxDynamicSharedMemorySize, GSMEM);
    cudaFuncSetAttribute(hgemm<0,1,1>, cudaFuncAttributeMaxDynamicSharedMemorySize, GSMEM);

    // --- operand conversions ---
    {
        long long n;
        n = (long long)SS * DD;
        cvt_hilo_k<<<(unsigned)((n/4 + 255)/256), 256>>>(h, hh, hl, n);
        n = (long long)QLORA * DD;
        cvt_hilo_k<<<(unsigned)((n/4 + 255)/256), 256>>>(w_q_a, wqa_h, wqa_l, n);
        n = (long long)HH * QKH * QLORA;
        cvt_hilo_k<<<(unsigned)((n/4 + 255)/256), 256>>>(w_q_b, wqb_h, wqb_l, n);
        n = (long long)KEFF * DD;
        cvt_hilo_k<<<(unsigned)((n/4 + 255)/256), 256>>>(w_kv_a, wkva_h, wkva_l, n);
        n = (long long)DD * HH * VH;
        cvt_hilo_k<<<(unsigned)((n/4 + 255)/256), 256>>>(w_o, wo_h, wo_l, n);
    }
    // w_uk [h][128][512] -> wukt [h][512][128]
    transcvt_k<<<dim3(KVLORA/32, NOPEW/32, HH), 256>>>(
        w_uk, wukt_h, wukt_l, KVLORA, NOPEW,
        (long long)NOPEW*KVLORA, (long long)KVLORA*NOPEW);
    // w_uv [h][512][128] -> wuvt [h][128][512]
    transcvt_k<<<dim3(VH/32, KVLORA/32, HH), 256>>>(
        w_uv, wuvt_h, wuvt_l, VH, KVLORA,
        (long long)KVLORA*VH, (long long)VH*KVLORA);

    // 1) q_a = h @ w_q_a^T  -> fp32
    hgemm<0,0,0><<<dim3(QLORA/128, SS/128, 1), 256, GSMEM>>>(
        hh, hl, wqa_h, wqa_l, qa_f, nullptr, nullptr,
        SS, QLORA, DD, DD, DD, QLORA, 0, 0, 0);
    // 2) rmsnorm -> hilo
    rmsnorm_hilo<<<SS, 256>>>(qa_f, gq, qa_h, qa_l, QLORA);
    // 3) q = q_a @ w_q_b^T  -> hilo
    hgemm<0,0,1><<<dim3((HH*QKH)/128, SS/128, 1), 256, GSMEM>>>(
        qa_h, qa_l, wqb_h, wqb_l, nullptr, q_h, q_l,
        SS, HH*QKH, QLORA, QLORA, QLORA, HH*QKH, 0, 0, 0);
    // 4) kv = h @ w_kv_a^T  -> fp32
    hgemm<0,0,0><<<dim3((KEFF+127)/128, SS/128, 1), 256, GSMEM>>>(
        hh, hl, wkva_h, wkva_l, keff_f, nullptr, nullptr,
        SS, KEFF, DD, DD, DD, KEFF, 0, 0, 0);
    // 5) kv post (rmsnorm + rope), write keff hilo
    kv_post<<<SS, 256>>>(keff_f, gkv, cosb, sinb, keff_h, keff_l);
    // 5b) kv_c transpose -> kvct [512][2048] hilo
    transcvt_k<<<dim3(KVLORA/32, SS/32, 1), 256>>>(
        keff_f, kvct_h, kvct_l, KEFF, SS, 0, 0);
    // 6) q_latent -> qeff[:, 0:512] hilo
    hgemm<0,0,1><<<dim3(KVLORA/128, SS/128, HH), 256, GSMEM>>>(
        q_h, q_l, wukt_h, wukt_l, nullptr, qeff_h, qeff_l,
        SS, KVLORA, NOPEW, HH*QKH, NOPEW, KEFF,
        (long long)QKH, (long long)KVLORA*NOPEW, (long long)SS*KEFF);
    // 7) q rope -> qeff[:, 512:576] hilo
    {
        long long total = (long long)SS * HH * 32;
        q_rope<<<(unsigned)((total + 255) / 256), 256>>>(q_h, q_l, qeff_h, qeff_l, cosb, sinb);
    }
    // 8) scores = qeff @ keff^T (causal tile skip) -> fp32
    hgemm<1,0,0><<<dim3(SS/128, SS/128, HH), 256, GSMEM>>>(
        qeff_h, qeff_l, keff_h, keff_l, sc, nullptr, nullptr,
        SS, SS, KEFF, KEFF, KEFF, SS,
        (long long)SS*KEFF, 0, (long long)SS*SS);
    // 9) causal softmax -> P hilo (+zero pad to 128 boundary)
    softmax_causal<<<dim3(SS, HH), 256>>>(sc, p_h, p_l);
    // 10) ctx_latent = P @ kvct^T (K limited) -> hilo
    hgemm<0,1,1><<<dim3(KVLORA/128, SS/128, HH), 256, GSMEM>>>(
        p_h, p_l, kvct_h, kvct_l, nullptr, ctxl_h, ctxl_l,
        SS, KVLORA, SS, SS, SS, KVLORA,
        (long long)SS*SS, 0, (long long)SS*KVLORA);
    // 11) ctx = ctx_latent @ wuvt^T -> hilo (column block per head)
    hgemm<0,0,1><<<dim3(1, SS/128, HH), 256, GSMEM>>>(
        ctxl_h, ctxl_l, wuvt_h, wuvt_l, nullptr, ctx_h, ctx_l,
        SS, VH, KVLORA, KVLORA, KVLORA, HH*VH,
        (long long)SS*KVLORA, (long long)VH*KVLORA, (long long)VH);
    // 12) out = ctx @ w_o^T -> fp32
    hgemm<0,0,0><<<dim3(DD/128, SS/128, 1), 256, GSMEM>>>(
        ctx_h, ctx_l, wo_h, wo_l, out, nullptr, nullptr,
        SS, DD, HH*VH, HH*VH, HH*VH, DD, 0, 0, 0);
}

// round 6
// speedup vs baseline: 3.3796x; 1.1620x over previous
#include <cuda_runtime.h>
#include <cuda_fp16.h>
#include <stdint.h>
#include <math.h>

// ---------------- problem constants ----------------
#define SS 2048
#define DD 4096
#define HH 32
#define QLORA 1536
#define KVLORA 512
#define ROPEW 64
#define NOPEW 128
#define QKH 192
#define VH 128
#define KEFF 576
#define EPSV 1e-6f
#define SCALE 0.07216878364870322f   // 1/sqrt(192)

typedef __half hf;

// ---------------- scratch ----------------
__device__ float g_qa_f[(size_t)SS * QLORA];
__device__ float g_keff_f[(size_t)SS * KEFF];
__device__ float g_scores[(size_t)HH * SS * SS];
__device__ hf g_hh[(size_t)SS * DD],            g_hl[(size_t)SS * DD];
__device__ hf g_wqa_h[(size_t)QLORA * DD],      g_wqa_l[(size_t)QLORA * DD];
__device__ hf g_wqb_h[(size_t)HH*QKH * QLORA],  g_wqb_l[(size_t)HH*QKH * QLORA];
__device__ hf g_wkva_h[(size_t)KEFF * DD],      g_wkva_l[(size_t)KEFF * DD];
__device__ hf g_wo_h[(size_t)DD * HH*VH],       g_wo_l[(size_t)DD * HH*VH];
__device__ hf g_wukt_h[(size_t)HH*KVLORA*NOPEW],g_wukt_l[(size_t)HH*KVLORA*NOPEW]; // [h][c=512][n=128]
__device__ hf g_wuvt_h[(size_t)HH*VH*KVLORA],   g_wuvt_l[(size_t)HH*VH*KVLORA];    // [h][v=128][c=512]
__device__ hf g_qa_h[(size_t)SS * QLORA],       g_qa_l[(size_t)SS * QLORA];
__device__ hf g_q_h[(size_t)SS * HH*QKH],       g_q_l[(size_t)SS * HH*QKH];
__device__ hf g_keff_h[(size_t)SS * KEFF],      g_keff_l[(size_t)SS * KEFF];
__device__ hf g_kvct_h[(size_t)KVLORA * SS],    g_kvct_l[(size_t)KVLORA * SS];     // [c=512][s=2048]
__device__ hf g_qeff_h[(size_t)HH*SS*KEFF],     g_qeff_l[(size_t)HH*SS*KEFF];
__device__ hf g_p_h[(size_t)HH*SS*SS],          g_p_l[(size_t)HH*SS*SS];
__device__ hf g_ctxl_h[(size_t)HH*SS*KVLORA],   g_ctxl_l[(size_t)HH*SS*KVLORA];
__device__ hf g_ctx_h[(size_t)SS * HH*VH],      g_ctx_l[(size_t)SS * HH*VH];

// ---------------- helpers ----------------
__device__ __forceinline__ uint32_t smem_u32(const void* p) {
    uint32_t a;
    asm("{ .reg .u64 t; cvta.to.shared.u64 t, %1; cvt.u32.u64 %0, t; }" : "=r"(a) : "l"(p));
    return a;
}

__device__ __forceinline__ void hilo1(float v, hf& h, hf& l) {
    h = __float2half_rn(v);
    l = __float2half_rn(v - __half2float(h));
}
__device__ __forceinline__ void cvt_hilo4(float4 v, uint2& hi, uint2& lo) {
    hf h0, h1, h2, h3, l0, l1, l2, l3;
    hilo1(v.x, h0, l0); hilo1(v.y, h1, l1); hilo1(v.z, h2, l2); hilo1(v.w, h3, l3);
    hi.x = ((uint32_t)__half_as_ushort(h1) << 16) | __half_as_ushort(h0);
    hi.y = ((uint32_t)__half_as_ushort(h3) << 16) | __half_as_ushort(h2);
    lo.x = ((uint32_t)__half_as_ushort(l1) << 16) | __half_as_ushort(l0);
    lo.y = ((uint32_t)__half_as_ushort(l3) << 16) | __half_as_ushort(l2);
}
__device__ __forceinline__ void hilo2pack(float a, float b, uint32_t& h, uint32_t& l) {
    hf ha, hb2, la, lb;
    hilo1(a, ha, la); hilo1(b, hb2, lb);
    h = ((uint32_t)__half_as_ushort(hb2) << 16) | __half_as_ushort(ha);
    l = ((uint32_t)__half_as_ushort(lb) << 16) | __half_as_ushort(la);
}

__device__ __forceinline__ void mma_f16(float* c, const uint32_t* a, const uint32_t* b) {
    asm volatile(
        "mma.sync.aligned.m16n8k16.row.col.f32.f16.f16.f32 "
        "{%0,%1,%2,%3}, {%4,%5,%6,%7}, {%8,%9}, {%0,%1,%2,%3};"
        : "+f"(c[0]), "+f"(c[1]), "+f"(c[2]), "+f"(c[3])
        : "r"(a[0]), "r"(a[1]), "r"(a[2]), "r"(a[3]), "r"(b[0]), "r"(b[1]));
}

#define LDMX4(r0, r1, r2, r3, addr) \
    asm volatile("ldmatrix.sync.aligned.m8n8.x4.shared.b16 {%0,%1,%2,%3}, [%4];" \
        : "=r"(r0), "=r"(r1), "=r"(r2), "=r"(r3) : "r"(addr))

#define CPA16(dst, src, sz) \
    asm volatile("cp.async.cg.shared.global [%0], [%1], 16, %2;" \
        :: "r"(dst), "l"(src), "r"(sz))
#define CPA_COMMIT()  asm volatile("cp.async.commit_group;" ::: "memory")
#define CPA_WAIT1()   asm volatile("cp.async.wait_group 1;" ::: "memory")

// smem layout: per stage 4 arrays (Ah, Al, Bh, Bl), each 128 rows x 40 hf (80B rows)
#define LDT 40
#define ARR_B   (128 * LDT * 2)      // 10240
#define CHUNK_B (4 * ARR_B)          // 40960
#define NSTAGE  2
#define GSMEM   (NSTAGE * CHUNK_B)   // 81920

// ============================================================================
// Unified NT GEMM: C = A * B^T, operands fp16 hi/lo [rows][K] K-major.
// TERMS==3: Ah*Bh + Ah*Bl + Al*Bh  (near-fp32)
// TERMS==2: Ah*Bh + Al*Bh          (A exact to 2^-22, B rounded to fp16)
// CSKIP: skip tiles bn > bm.  CKEND: K limited to (bm+1)*128.
// OUT_HILO: write Ch/Cl fp16 hi/lo, else write C fp32.
// ============================================================================
template<int CSKIP, int CKEND, int OUT_HILO, int TERMS>
__global__ void __launch_bounds__(256, 2)
hgemm(const hf* __restrict__ Ah, const hf* __restrict__ Al,
      const hf* __restrict__ Bh, const hf* __restrict__ Bl,
      float* __restrict__ C, hf* __restrict__ Ch, hf* __restrict__ Cl,
      int M, int N, int K, int lda, int ldb, int ldc,
      long long sA, long long sB, long long sC)
{
    const int bm = blockIdx.y, bn = blockIdx.x;
    if (CSKIP && bn > bm) return;
    extern __shared__ char smem[];
    const uint32_t sbase = smem_u32(smem);

    const int tid = threadIdx.x, lane = tid & 31, wid = tid >> 5;
    const int wm = wid & 1, wn = wid >> 1;

    Ah += (long long)blockIdx.z * sA;  Al += (long long)blockIdx.z * sA;
    Bh += (long long)blockIdx.z * sB;
    if (TERMS == 3) Bl += (long long)blockIdx.z * sB;

    const int Kend = CKEND ? min(K, (bm + 1) * 128) : K;
    const int nch = Kend / 32;

    // ---- cp.async: per thread 16B chunks ----
    const int ch = tid & 3;
    const int rr = tid >> 2;           // 0..63
    const int ar0 = bm * 128 + rr;
    const int br0 = bn * 128 + rr, br1 = br0 + 64;
    const uint32_t szB0 = (br0 < N) ? 16u : 0u;
    const uint32_t szB1 = (br1 < N) ? 16u : 0u;
    const hf* pAh0 = Ah + (long long)ar0 * lda + ch * 8;
    const hf* pAh1 = pAh0 + (long long)64 * lda;
    const hf* pAl0 = Al + (long long)ar0 * lda + ch * 8;
    const hf* pAl1 = pAl0 + (long long)64 * lda;
    const hf* pBh0 = Bh + (long long)min(br0, N - 1) * ldb + ch * 8;
    const hf* pBh1 = Bh + (long long)min(br1, N - 1) * ldb + ch * 8;
    const hf* pBl0 = (TERMS == 3) ? Bl + (long long)min(br0, N - 1) * ldb + ch * 8 : nullptr;
    const hf* pBl1 = (TERMS == 3) ? Bl + (long long)min(br1, N - 1) * ldb + ch * 8 : nullptr;
    const uint32_t d0 = (uint32_t)(rr * 80 + ch * 16);
    const uint32_t d1 = d0 + 64 * 80;

    auto issue = [&](int slot) {
        uint32_t st = sbase + slot * CHUNK_B;
        CPA16(st + 0 * ARR_B + d0, pAh0, 16u);
        CPA16(st + 0 * ARR_B + d1, pAh1, 16u);
        CPA16(st + 1 * ARR_B + d0, pAl0, 16u);
        CPA16(st + 1 * ARR_B + d1, pAl1, 16u);
        CPA16(st + 2 * ARR_B + d0, pBh0, szB0);
        CPA16(st + 2 * ARR_B + d1, pBh1, szB1);
        if (TERMS == 3) {
            CPA16(st + 3 * ARR_B + d0, pBl0, szB0);
            CPA16(st + 3 * ARR_B + d1, pBl1, szB1);
        }
        pAh0 += 32; pAh1 += 32; pAl0 += 32; pAl1 += 32;
        pBh0 += 32; pBh1 += 32;
        if (TERMS == 3) { pBl0 += 32; pBl1 += 32; }
    };

    // ---- ldmatrix lane offsets ----
    const int arow_l = wm * 64 + ((lane >> 3) & 1) * 8 + (lane & 7);
    const int acol_l = (lane >> 4) * 8;
    const uint32_t aoff = (uint32_t)(arow_l * LDT + acol_l) * 2;
    const int brow_l = wn * 32 + ((lane >> 4) & 1) * 8 + (lane & 7);
    const int bcol_l = ((lane >> 3) & 1) * 8;
    const uint32_t boff = (uint32_t)(brow_l * LDT + bcol_l) * 2;

    float acc[4][4][4];
    #pragma unroll
    for (int a = 0; a < 4; a++)
        #pragma unroll
        for (int b = 0; b < 4; b++)
            #pragma unroll
            for (int q = 0; q < 4; q++) acc[a][b][q] = 0.f;

    issue(0);
    CPA_COMMIT();

    for (int c = 0; c < nch; c++) {
        if (c + 1 < nch) issue((c + 1) & 1);
        CPA_COMMIT();
        CPA_WAIT1();
        __syncthreads();
        const uint32_t st = sbase + (c & 1) * CHUNK_B;
        #pragma unroll
        for (int ks = 0; ks < 2; ks++) {
            const uint32_t kof = ks * 32;
            uint32_t ah[4][4], al[4][4], bh[4][2], bl[4][2];
            #pragma unroll
            for (int mi = 0; mi < 4; mi++) {
                LDMX4(ah[mi][0], ah[mi][1], ah[mi][2], ah[mi][3],
                      st + 0 * ARR_B + aoff + mi * 1280 + kof);
                LDMX4(al[mi][0], al[mi][1], al[mi][2], al[mi][3],
                      st + 1 * ARR_B + aoff + mi * 1280 + kof);
            }
            #pragma unroll
            for (int p = 0; p < 2; p++) {
                LDMX4(bh[2*p][0], bh[2*p][1], bh[2*p+1][0], bh[2*p+1][1],
                      st + 2 * ARR_B + boff + p * 1280 + kof);
                if (TERMS == 3)
                    LDMX4(bl[2*p][0], bl[2*p][1], bl[2*p+1][0], bl[2*p+1][1],
                          st + 3 * ARR_B + boff + p * 1280 + kof);
            }
            #pragma unroll
            for (int mi = 0; mi < 4; mi++)
                #pragma unroll
                for (int ni = 0; ni < 4; ni++) {
                    mma_f16(acc[mi][ni], ah[mi], bh[ni]);
                    if (TERMS == 3) mma_f16(acc[mi][ni], ah[mi], bl[ni]);
                    mma_f16(acc[mi][ni], al[mi], bh[ni]);
                }
        }
        __syncthreads();
    }

    // ---- epilogue ----
    const int qr = lane >> 2, qc = lane & 3;
    if (OUT_HILO) {
        hf* chp = Ch + (long long)blockIdx.z * sC;
        hf* clp = Cl + (long long)blockIdx.z * sC;
        #pragma unroll
        for (int mi = 0; mi < 4; mi++)
            #pragma unroll
            for (int ni = 0; ni < 4; ni++) {
                int r = bm * 128 + wm * 64 + mi * 16 + qr;
                int cc = bn * 128 + wn * 32 + ni * 8 + qc * 2;
                if (cc < N) {
                    uint32_t h0, l0, h1, l1;
                    hilo2pack(acc[mi][ni][0], acc[mi][ni][1], h0, l0);
                    hilo2pack(acc[mi][ni][2], acc[mi][ni][3], h1, l1);
                    *(uint32_t*)(chp + (long long)r * ldc + cc) = h0;
                    *(uint32_t*)(clp + (long long)r * ldc + cc) = l0;
                    *(uint32_t*)(chp + (long long)(r + 8) * ldc + cc) = h1;
                    *(uint32_t*)(clp + (long long)(r + 8) * ldc + cc) = l1;
                }
            }
    } else {
        float* cp = C + (long long)blockIdx.z * sC;
        #pragma unroll
        for (int mi = 0; mi < 4; mi++)
            #pragma unroll
            for (int ni = 0; ni < 4; ni++) {
                int r = bm * 128 + wm * 64 + mi * 16 + qr;
                int cc = bn * 128 + wn * 32 + ni * 8 + qc * 2;
                if (cc < N) {
                    *(float2*)(cp + (long long)r * ldc + cc) =
                        make_float2(acc[mi][ni][0], acc[mi][ni][1]);
                    *(float2*)(cp + (long long)(r + 8) * ldc + cc) =
                        make_float2(acc[mi][ni][2], acc[mi][ni][3]);
                }
            }
    }
}

// ============================================================================
// conversion / elementwise kernels
// ============================================================================
__global__ void cvt_hilo_k(const float* __restrict__ in, hf* __restrict__ oh,
                           hf* __restrict__ ol, long long n)
{
    long long i = ((long long)blockIdx.x * 256 + threadIdx.x) * 4;
    if (i >= n) return;
    float4 v = *(const float4*)(in + i);
    uint2 h, l; cvt_hilo4(v, h, l);
    *(uint2*)(oh + i) = h;
    *(uint2*)(ol + i) = l;
}

// out[c][r] = in[r][c]; grid: (C/32, R/32, batch)
__global__ void transcvt_k(const float* __restrict__ in, hf* __restrict__ oh,
                           hf* __restrict__ ol, int ld_in, int ld_out,
                           long long sIn, long long sOut)
{
    __shared__ float tile[32][33];
    const float* ip = in + (long long)blockIdx.z * sIn;
    int r0 = blockIdx.y * 32, c0 = blockIdx.x * 32;
    int tx = threadIdx.x & 31, ty = threadIdx.x >> 5;
    #pragma unroll
    for (int it = 0; it < 4; it++) {
        int r = ty + it * 8;
        tile[r][tx] = ip[(long long)(r0 + r) * ld_in + c0 + tx];
    }
    __syncthreads();
    #pragma unroll
    for (int it = 0; it < 4; it++) {
        int cr = ty + it * 8;
        float v = tile[tx][cr];
        hf hb, lb; hilo1(v, hb, lb);
        long long o = (long long)blockIdx.z * sOut + (long long)(c0 + cr) * ld_out + r0 + tx;
        oh[o] = hb; ol[o] = lb;
    }
}

__global__ void rmsnorm_hilo(const float* __restrict__ X, const float* __restrict__ g,
                             hf* __restrict__ oh, hf* __restrict__ ol, int n)
{
    const float* x = X + (long long)blockIdx.x * n;
    hf* ph = oh + (long long)blockIdx.x * n;
    hf* pl = ol + (long long)blockIdx.x * n;
    __shared__ float red[256];
    const int tid = threadIdx.x;
    float s = 0.f;
    for (int i = tid; i < n; i += 256) { float v = x[i]; s += v * v; }
    red[tid] = s; __syncthreads();
    for (int o = 128; o > 0; o >>= 1) {
        if (tid < o) red[tid] += red[tid + o];
        __syncthreads();
    }
    float inv = rsqrtf(red[0] / (float)n + EPSV);
    for (int i = tid; i < n; i += 256) {
        hf hb, lb; hilo1(x[i] * inv * g[i], hb, lb);
        ph[i] = hb; pl[i] = lb;
    }
}

__global__ void kv_post(float* __restrict__ KV, const float* __restrict__ g,
                        const float* __restrict__ cosb, const float* __restrict__ sinb,
                        hf* __restrict__ oh, hf* __restrict__ ol)
{
    const int srow = blockIdx.x;
    float* x = KV + (long long)srow * KEFF;
    hf* ph = oh + (long long)srow * KEFF;
    hf* pl = ol + (long long)srow * KEFF;
    __shared__ float red[256];
    const int tid = threadIdx.x;
    float s = 0.f;
    for (int i = tid; i < KVLORA; i += 256) { float v = x[i]; s += v * v; }
    red[tid] = s; __syncthreads();
    for (int o = 128; o > 0; o >>= 1) {
        if (tid < o) red[tid] += red[tid + o];
        __syncthreads();
    }
    float inv = rsqrtf(red[0] / (float)KVLORA + EPSV);
    for (int i = tid; i < KVLORA; i += 256) x[i] = x[i] * inv * g[i];
    if (tid < 32) {
        float x1 = x[KVLORA + tid];
        float x2 = x[KVLORA + 32 + tid];
        float c1 = cosb[srow * ROPEW + tid];
        float c2 = cosb[srow * ROPEW + 32 + tid];
        float s1 = sinb[srow * ROPEW + tid];
        float s2 = sinb[srow * ROPEW + 32 + tid];
        x[KVLORA + tid]      = x1 * c1 - x2 * s1;
        x[KVLORA + 32 + tid] = x2 * c2 + x1 * s2;
    }
    __syncthreads();
    for (int i = tid; i < KEFF; i += 256) {
        hf hb, lb; hilo1(x[i], hb, lb);
        ph[i] = hb; pl[i] = lb;
    }
}

__global__ void q_rope(const hf* __restrict__ Qh, const hf* __restrict__ Ql,
                       hf* __restrict__ Eh, hf* __restrict__ El,
                       const float* __restrict__ cosb, const float* __restrict__ sinb)
{
    long long idx = (long long)blockIdx.x * blockDim.x + threadIdx.x;
    const long long total = (long long)SS * HH * 32;
    if (idx >= total) return;
    int j  = (int)(idx & 31);
    long long sh = idx >> 5;
    int h = (int)(sh & (HH - 1));
    int s = (int)(sh >> 5);
    long long qb = ((long long)s * HH + h) * QKH + NOPEW;
    float x1 = __half2float(Qh[qb + j]) + __half2float(Ql[qb + j]);
    float x2 = __half2float(Qh[qb + j + 32]) + __half2float(Ql[qb + j + 32]);
    float c1 = cosb[s * ROPEW + j];
    float c2 = cosb[s * ROPEW + 32 + j];
    float s1 = sinb[s * ROPEW + j];
    float s2 = sinb[s * ROPEW + 32 + j];
    long long ob = ((long long)h * SS + s) * KEFF + KVLORA;
    hf hb, lb;
    hilo1(x1 * c1 - x2 * s1, hb, lb);   Eh[ob + j] = hb;      El[ob + j] = lb;
    hilo1(x2 * c2 + x1 * s2, hb, lb);   Eh[ob + j + 32] = hb; El[ob + j + 32] = lb;
}

__global__ void softmax_causal(const float* __restrict__ Sc,
                               hf* __restrict__ Ph, hf* __restrict__ Pl)
{
    __shared__ float buf[SS];
    __shared__ float red[256];
    const int m = blockIdx.x;
    const int h = blockIdx.y;
    const float* row = Sc + ((long long)h * SS + m) * SS;
    hf* ph = Ph + ((long long)h * SS + m) * SS;
    hf* pl = Pl + ((long long)h * SS + m) * SS;
    const int len = m + 1;
    const int pad = ((m >> 7) + 1) << 7;
    const int tid = threadIdx.x;

    float mx = -3.4e38f;
    for (int i = tid; i < len; i += 256) { float v = row[i]; buf[i] = v; mx = fmaxf(mx, v); }
    red[tid] = mx; __syncthreads();
    for (int o = 128; o > 0; o >>= 1) {
        if (tid < o) red[tid] = fmaxf(red[tid], red[tid + o]);
        __syncthreads();
    }
    const float rowmax = red[0];
    __syncthreads();

    float sum = 0.f;
    for (int i = tid; i < len; i += 256) {
        float e = expf(SCALE * (buf[i] - rowmax));
        buf[i] = e;
        sum += e;
    }
    red[tid] = sum; __syncthreads();
    for (int o = 128; o > 0; o >>= 1) {
        if (tid < o) red[tid] += red[tid + o];
        __syncthreads();
    }
    const float rinv = 1.f / red[0];
    for (int i = tid; i < len; i += 256) {
        hf hb, lb; hilo1(buf[i] * rinv, hb, lb);
        ph[i] = hb; pl[i] = lb;
    }
    const hf z = __float2half(0.f);
    for (int i = len + tid; i < pad; i += 256) { ph[i] = z; pl[i] = z; }
}

// ============================================================================
extern "C" void kernel_launch(void* const* d_in, const int* in_sizes, int n_in,
                              void* d_out, int out_size)
{
    (void)in_sizes; (void)n_in; (void)out_size;
    const float* h      = (const float*)d_in[0];
    const float* cosb   = (const float*)d_in[1];
    const float* sinb   = (const float*)d_in[2];
    const float* w_q_a  = (const float*)d_in[3];
    const float* gq     = (const float*)d_in[4];
    const float* w_q_b  = (const float*)d_in[5];
    const float* w_kv_a = (const float*)d_in[6];
    const float* gkv    = (const float*)d_in[7];
    const float* w_uk   = (const float*)d_in[8];
    const float* w_uv   = (const float*)d_in[9];
    const float* w_o    = (const float*)d_in[10];
    float* out = (float*)d_out;

    float *qa_f, *keff_f, *sc;
    hf *hh, *hl, *wqa_h, *wqa_l, *wqb_h, *wqb_l, *wkva_h, *wkva_l, *wo_h, *wo_l;
    hf *wukt_h, *wukt_l, *wuvt_h, *wuvt_l, *qa_h, *qa_l, *q_h, *q_l;
    hf *keff_h, *keff_l, *kvct_h, *kvct_l, *qeff_h, *qeff_l;
    hf *p_h, *p_l, *ctxl_h, *ctxl_l, *ctx_h, *ctx_l;
    cudaGetSymbolAddress((void**)&qa_f,   g_qa_f);
    cudaGetSymbolAddress((void**)&keff_f, g_keff_f);
    cudaGetSymbolAddress((void**)&sc,     g_scores);
    cudaGetSymbolAddress((void**)&hh,     g_hh);     cudaGetSymbolAddress((void**)&hl,     g_hl);
    cudaGetSymbolAddress((void**)&wqa_h,  g_wqa_h);  cudaGetSymbolAddress((void**)&wqa_l,  g_wqa_l);
    cudaGetSymbolAddress((void**)&wqb_h,  g_wqb_h);  cudaGetSymbolAddress((void**)&wqb_l,  g_wqb_l);
    cudaGetSymbolAddress((void**)&wkva_h, g_wkva_h); cudaGetSymbolAddress((void**)&wkva_l, g_wkva_l);
    cudaGetSymbolAddress((void**)&wo_h,   g_wo_h);   cudaGetSymbolAddress((void**)&wo_l,   g_wo_l);
    cudaGetSymbolAddress((void**)&wukt_h, g_wukt_h); cudaGetSymbolAddress((void**)&wukt_l, g_wukt_l);
    cudaGetSymbolAddress((void**)&wuvt_h, g_wuvt_h); cudaGetSymbolAddress((void**)&wuvt_l, g_wuvt_l);
    cudaGetSymbolAddress((void**)&qa_h,   g_qa_h);   cudaGetSymbolAddress((void**)&qa_l,   g_qa_l);
    cudaGetSymbolAddress((void**)&q_h,    g_q_h);    cudaGetSymbolAddress((void**)&q_l,    g_q_l);
    cudaGetSymbolAddress((void**)&keff_h, g_keff_h); cudaGetSymbolAddress((void**)&keff_l, g_keff_l);
    cudaGetSymbolAddress((void**)&kvct_h, g_kvct_h); cudaGetSymbolAddress((void**)&kvct_l, g_kvct_l);
    cudaGetSymbolAddress((void**)&qeff_h, g_qeff_h); cudaGetSymbolAddress((void**)&qeff_l, g_qeff_l);
    cudaGetSymbolAddress((void**)&p_h,    g_p_h);    cudaGetSymbolAddress((void**)&p_l,    g_p_l);
    cudaGetSymbolAddress((void**)&ctxl_h, g_ctxl_h); cudaGetSymbolAddress((void**)&ctxl_l, g_ctxl_l);
    cudaGetSymbolAddress((void**)&ctx_h,  g_ctx_h);  cudaGetSymbolAddress((void**)&ctx_l,  g_ctx_l);

    cudaFuncSetAttribute(hgemm<0,0,0,3>, cudaFuncAttributeMaxDynamicSharedMemorySize, GSMEM);
    cudaFuncSetAttribute(hgemm<0,0,1,3>, cudaFuncAttributeMaxDynamicSharedMemorySize, GSMEM);
    cudaFuncSetAttribute(hgemm<1,0,0,2>, cudaFuncAttributeMaxDynamicSharedMemorySize, GSMEM);
    cudaFuncSetAttribute(hgemm<0,1,1,2>, cudaFuncAttributeMaxDynamicSharedMemorySize, GSMEM);
    cudaFuncSetAttribute(hgemm<0,0,0,2>, cudaFuncAttributeMaxDynamicSharedMemorySize, GSMEM);

    // --- operand conversions ---
    {
        long long n;
        n = (long long)SS * DD;
        cvt_hilo_k<<<(unsigned)((n/4 + 255)/256), 256>>>(h, hh, hl, n);
        n = (long long)QLORA * DD;
        cvt_hilo_k<<<(unsigned)((n/4 + 255)/256), 256>>>(w_q_a, wqa_h, wqa_l, n);
        n = (long long)HH * QKH * QLORA;
        cvt_hilo_k<<<(unsigned)((n/4 + 255)/256), 256>>>(w_q_b, wqb_h, wqb_l, n);
        n = (long long)KEFF * DD;
        cvt_hilo_k<<<(unsigned)((n/4 + 255)/256), 256>>>(w_kv_a, wkva_h, wkva_l, n);
        n = (long long)DD * HH * VH;
        cvt_hilo_k<<<(unsigned)((n/4 + 255)/256), 256>>>(w_o, wo_h, wo_l, n);
    }
    // w_uk [h][128][512] -> wukt [h][512][128]
    transcvt_k<<<dim3(KVLORA/32, NOPEW/32, HH), 256>>>(
        w_uk, wukt_h, wukt_l, KVLORA, NOPEW,
        (long long)NOPEW*KVLORA, (long long)KVLORA*NOPEW);
    // w_uv [h][512][128] -> wuvt [h][128][512]
    transcvt_k<<<dim3(VH/32, KVLORA/32, HH), 256>>>(
        w_uv, wuvt_h, wuvt_l, VH, KVLORA,
        (long long)KVLORA*VH, (long long)VH*KVLORA);

    // 1) q_a = h @ w_q_a^T  -> fp32          (3-term)
    hgemm<0,0,0,3><<<dim3(QLORA/128, SS/128, 1), 256, GSMEM>>>(
        hh, hl, wqa_h, wqa_l, qa_f, nullptr, nullptr,
        SS, QLORA, DD, DD, DD, QLORA, 0, 0, 0);
    // 2) rmsnorm -> hilo
    rmsnorm_hilo<<<SS, 256>>>(qa_f, gq, qa_h, qa_l, QLORA);
    // 3) q = q_a @ w_q_b^T -> hilo           (3-term)
    hgemm<0,0,1,3><<<dim3((HH*QKH)/128, SS/128, 1), 256, GSMEM>>>(
        qa_h, qa_l, wqb_h, wqb_l, nullptr, q_h, q_l,
        SS, HH*QKH, QLORA, QLORA, QLORA, HH*QKH, 0, 0, 0);
    // 4) kv = h @ w_kv_a^T -> fp32           (3-term)
    hgemm<0,0,0,3><<<dim3((KEFF+127)/128, SS/128, 1), 256, GSMEM>>>(
        hh, hl, wkva_h, wkva_l, keff_f, nullptr, nullptr,
        SS, KEFF, DD, DD, DD, KEFF, 0, 0, 0);
    // 5) kv post (rmsnorm + rope) -> keff hilo
    kv_post<<<SS, 256>>>(keff_f, gkv, cosb, sinb, keff_h, keff_l);
    // 5b) kv_c transpose -> kvct [512][2048] hilo
    transcvt_k<<<dim3(KVLORA/32, SS/32, 1), 256>>>(
        keff_f, kvct_h, kvct_l, KEFF, SS, 0, 0);
    // 6) q_latent -> qeff[:, 0:512] hilo     (3-term)
    hgemm<0,0,1,3><<<dim3(KVLORA/128, SS/128, HH), 256, GSMEM>>>(
        q_h, q_l, wukt_h, wukt_l, nullptr, qeff_h, qeff_l,
        SS, KVLORA, NOPEW, HH*QKH, NOPEW, KEFF,
        (long long)QKH, (long long)KVLORA*NOPEW, (long long)SS*KEFF);
    // 7) q rope -> qeff[:, 512:576] hilo
    {
        long long total = (long long)SS * HH * 32;
        q_rope<<<(unsigned)((total + 255) / 256), 256>>>(q_h, q_l, qeff_h, qeff_l, cosb, sinb);
    }
    // 8) scores = qeff @ keff^T (causal skip) -> fp32    (2-term)
    hgemm<1,0,0,2><<<dim3(SS/128, SS/128, HH), 256, GSMEM>>>(
        qeff_h, qeff_l, keff_h, keff_l, sc, nullptr, nullptr,
        SS, SS, KEFF, KEFF, KEFF, SS,
        (long long)SS*KEFF, 0, (long long)SS*SS);
    // 9) causal softmax -> P hilo (+zero pad)
    softmax_causal<<<dim3(SS, HH), 256>>>(sc, p_h, p_l);
    // 10) ctx_latent = P @ kvct^T (K limited) -> hilo    (2-term)
    hgemm<0,1,1,2><<<dim3(KVLORA/128, SS/128, HH), 256, GSMEM>>>(
        p_h, p_l, kvct_h, kvct_l, nullptr, ctxl_h, ctxl_l,
        SS, KVLORA, SS, SS, SS, KVLORA,
        (long long)SS*SS, 0, (long long)SS*KVLORA);
    // 11) ctx = ctx_latent @ wuvt^T -> hilo              (3-term)
    hgemm<0,0,1,3><<<dim3(1, SS/128, HH), 256, GSMEM>>>(
        ctxl_h, ctxl_l, wuvt_h, wuvt_l, nullptr, ctx_h, ctx_l,
        SS, VH, KVLORA, KVLORA, KVLORA, HH*VH,
        (long long)SS*KVLORA, (long long)VH*KVLORA, (long long)VH);
    // 12) out = ctx @ w_o^T -> fp32                      (2-term)
    hgemm<0,0,0,2><<<dim3(DD/128, SS/128, 1), 256, GSMEM>>>(
        ctx_h, ctx_l, wo_h, wo_l, out, nullptr, nullptr,
        SS, DD, HH*VH, HH*VH, HH*VH, DD, 0, 0, 0);
}

// round 7
// speedup vs baseline: 3.9888x; 1.1803x over previous
#include <cuda_runtime.h>
#include <cuda_fp16.h>
#include <stdint.h>
#include <math.h>

// ---------------- problem constants ----------------
#define SS 2048
#define DD 4096
#define HH 32
#define QLORA 1536
#define KVLORA 512
#define ROPEW 64
#define NOPEW 128
#define QKH 192
#define VH 128
#define KEFF 576
#define EPSV 1e-6f
#define SCALE 0.07216878364870322f   // 1/sqrt(192)

typedef __half hf;

// ---------------- scratch ----------------
__device__ float g_qa_f[(size_t)SS * QLORA];
__device__ float g_keff_f[(size_t)SS * KEFF];
__device__ float g_scores[(size_t)HH * SS * SS];
// A-side operands: hi/lo ; B-side (weights, keff, kvct): hi only
__device__ hf g_hh[(size_t)SS * DD],            g_hl[(size_t)SS * DD];
__device__ hf g_wqa_h[(size_t)QLORA * DD];
__device__ hf g_wqb_h[(size_t)HH*QKH * QLORA];
__device__ hf g_wkva_h[(size_t)KEFF * DD];
__device__ hf g_wo_h[(size_t)DD * HH*VH];
__device__ hf g_wukt_h[(size_t)HH*KVLORA*NOPEW];   // [h][c=512][n=128]
__device__ hf g_wuvt_h[(size_t)HH*VH*KVLORA];      // [h][v=128][c=512]
__device__ hf g_qa_h[(size_t)SS * QLORA],       g_qa_l[(size_t)SS * QLORA];
__device__ hf g_q_h[(size_t)SS * HH*QKH],       g_q_l[(size_t)SS * HH*QKH];
__device__ hf g_keff_h[(size_t)SS * KEFF];
__device__ hf g_kvct_h[(size_t)KVLORA * SS];       // [c=512][s=2048]
__device__ hf g_qeff_h[(size_t)HH*SS*KEFF],     g_qeff_l[(size_t)HH*SS*KEFF];
__device__ hf g_p_h[(size_t)HH*SS*SS],          g_p_l[(size_t)HH*SS*SS];
__device__ hf g_ctxl_h[(size_t)HH*SS*KVLORA],   g_ctxl_l[(size_t)HH*SS*KVLORA];
__device__ hf g_ctx_h[(size_t)SS * HH*VH],      g_ctx_l[(size_t)SS * HH*VH];

// ---------------- helpers ----------------
__device__ __forceinline__ uint32_t smem_u32(const void* p) {
    uint32_t a;
    asm("{ .reg .u64 t; cvta.to.shared.u64 t, %1; cvt.u32.u64 %0, t; }" : "=r"(a) : "l"(p));
    return a;
}

__device__ __forceinline__ void hilo1(float v, hf& h, hf& l) {
    h = __float2half_rn(v);
    l = __float2half_rn(v - __half2float(h));
}
__device__ __forceinline__ void cvt_hilo4(float4 v, uint2& hi, uint2& lo) {
    hf h0, h1, h2, h3, l0, l1, l2, l3;
    hilo1(v.x, h0, l0); hilo1(v.y, h1, l1); hilo1(v.z, h2, l2); hilo1(v.w, h3, l3);
    hi.x = ((uint32_t)__half_as_ushort(h1) << 16) | __half_as_ushort(h0);
    hi.y = ((uint32_t)__half_as_ushort(h3) << 16) | __half_as_ushort(h2);
    lo.x = ((uint32_t)__half_as_ushort(l1) << 16) | __half_as_ushort(l0);
    lo.y = ((uint32_t)__half_as_ushort(l3) << 16) | __half_as_ushort(l2);
}
__device__ __forceinline__ void hilo2pack(float a, float b, uint32_t& h, uint32_t& l) {
    hf ha, hb2, la, lb;
    hilo1(a, ha, la); hilo1(b, hb2, lb);
    h = ((uint32_t)__half_as_ushort(hb2) << 16) | __half_as_ushort(ha);
    l = ((uint32_t)__half_as_ushort(lb) << 16) | __half_as_ushort(la);
}

__device__ __forceinline__ void mma_f16(float* c, const uint32_t* a, const uint32_t* b) {
    asm volatile(
        "mma.sync.aligned.m16n8k16.row.col.f32.f16.f16.f32 "
        "{%0,%1,%2,%3}, {%4,%5,%6,%7}, {%8,%9}, {%0,%1,%2,%3};"
        : "+f"(c[0]), "+f"(c[1]), "+f"(c[2]), "+f"(c[3])
        : "r"(a[0]), "r"(a[1]), "r"(a[2]), "r"(a[3]), "r"(b[0]), "r"(b[1]));
}

#define LDMX4(r0, r1, r2, r3, addr) \
    asm volatile("ldmatrix.sync.aligned.m8n8.x4.shared.b16 {%0,%1,%2,%3}, [%4];" \
        : "=r"(r0), "=r"(r1), "=r"(r2), "=r"(r3) : "r"(addr))

#define CPA16(dst, src, sz) \
    asm volatile("cp.async.cg.shared.global [%0], [%1], 16, %2;" \
        :: "r"(dst), "l"(src), "r"(sz))
#define CPA_COMMIT()  asm volatile("cp.async.commit_group;" ::: "memory")
#define CPA_WAIT2()   asm volatile("cp.async.wait_group 2;" ::: "memory")

// smem: per stage 3 arrays (Ah, Al, Bh), each 128 rows x 40 hf (80B rows)
#define LDT 40
#define ARR_B   (128 * LDT * 2)      // 10240
#define CHUNK_B (3 * ARR_B)          // 30720
#define NSTAGE  3
#define GSMEM   (NSTAGE * CHUNK_B)   // 92160

// ============================================================================
// NT GEMM: C = A * B^T. A fp16 hi/lo [rows][K], B fp16 hi [rows][K] K-major.
// 2-term emulation: Ah*Bh + Al*Bh (A exact to 2^-22, B rounded to fp16).
// 3-stage cp.async pipeline. REQUIRES K/32 >= 3 at every call site (min is 4).
// CSKIP: skip tiles bn > bm.  CKEND: K limited to (bm+1)*128.
// OUT_HILO: write Ch/Cl fp16 hi/lo, else write C fp32.
// ============================================================================
template<int CSKIP, int CKEND, int OUT_HILO>
__global__ void __launch_bounds__(256, 2)
hgemm(const hf* __restrict__ Ah, const hf* __restrict__ Al,
      const hf* __restrict__ Bh,
      float* __restrict__ C, hf* __restrict__ Ch, hf* __restrict__ Cl,
      int M, int N, int K, int lda, int ldb, int ldc,
      long long sA, long long sB, long long sC)
{
    const int bm = blockIdx.y, bn = blockIdx.x;
    if (CSKIP && bn > bm) return;
    extern __shared__ char smem[];
    const uint32_t sbase = smem_u32(smem);

    const int tid = threadIdx.x, lane = tid & 31, wid = tid >> 5;
    const int wm = wid & 1, wn = wid >> 1;

    Ah += (long long)blockIdx.z * sA;  Al += (long long)blockIdx.z * sA;
    Bh += (long long)blockIdx.z * sB;

    const int Kend = CKEND ? min(K, (bm + 1) * 128) : K;
    const int nch = Kend / 32;

    // ---- cp.async: 6 x 16B per thread per chunk ----
    const int ch = tid & 3;
    const int rr = tid >> 2;           // 0..63
    const int ar0 = bm * 128 + rr;
    const int br0 = bn * 128 + rr, br1 = br0 + 64;
    const uint32_t szB0 = (br0 < N) ? 16u : 0u;
    const uint32_t szB1 = (br1 < N) ? 16u : 0u;
    const hf* pAh0 = Ah + (long long)ar0 * lda + ch * 8;
    const hf* pAh1 = pAh0 + (long long)64 * lda;
    const hf* pAl0 = Al + (long long)ar0 * lda + ch * 8;
    const hf* pAl1 = pAl0 + (long long)64 * lda;
    const hf* pBh0 = Bh + (long long)min(br0, N - 1) * ldb + ch * 8;
    const hf* pBh1 = Bh + (long long)min(br1, N - 1) * ldb + ch * 8;
    const uint32_t d0 = (uint32_t)(rr * 80 + ch * 16);
    const uint32_t d1 = d0 + 64 * 80;

    auto issue = [&](int slot) {
        uint32_t st = sbase + slot * CHUNK_B;
        CPA16(st + 0 * ARR_B + d0, pAh0, 16u);
        CPA16(st + 0 * ARR_B + d1, pAh1, 16u);
        CPA16(st + 1 * ARR_B + d0, pAl0, 16u);
        CPA16(st + 1 * ARR_B + d1, pAl1, 16u);
        CPA16(st + 2 * ARR_B + d0, pBh0, szB0);
        CPA16(st + 2 * ARR_B + d1, pBh1, szB1);
        pAh0 += 32; pAh1 += 32; pAl0 += 32; pAl1 += 32;
        pBh0 += 32; pBh1 += 32;
    };

    // ---- ldmatrix lane offsets ----
    const int arow_l = wm * 64 + ((lane >> 3) & 1) * 8 + (lane & 7);
    const int acol_l = (lane >> 4) * 8;
    const uint32_t aoff = (uint32_t)(arow_l * LDT + acol_l) * 2;
    const int brow_l = wn * 32 + ((lane >> 4) & 1) * 8 + (lane & 7);
    const int bcol_l = ((lane >> 3) & 1) * 8;
    const uint32_t boff = (uint32_t)(brow_l * LDT + bcol_l) * 2;

    float acc[4][4][4];
    #pragma unroll
    for (int a = 0; a < 4; a++)
        #pragma unroll
        for (int b = 0; b < 4; b++)
            #pragma unroll
            for (int q = 0; q < 4; q++) acc[a][b][q] = 0.f;

    issue(0); CPA_COMMIT();
    issue(1); CPA_COMMIT();

    int slot = 0;
    for (int c = 0; c < nch; c++) {
        if (c + 2 < nch) issue((slot + 2) % NSTAGE);
        CPA_COMMIT();
        CPA_WAIT2();                        // oldest group (chunk c) arrived
        __syncthreads();
        const uint32_t st = sbase + slot * CHUNK_B;
        #pragma unroll
        for (int ks = 0; ks < 2; ks++) {
            const uint32_t kof = ks * 32;
            uint32_t ah[4][4], al[4][4], bh[4][2];
            #pragma unroll
            for (int mi = 0; mi < 4; mi++) {
                LDMX4(ah[mi][0], ah[mi][1], ah[mi][2], ah[mi][3],
                      st + 0 * ARR_B + aoff + mi * 1280 + kof);
                LDMX4(al[mi][0], al[mi][1], al[mi][2], al[mi][3],
                      st + 1 * ARR_B + aoff + mi * 1280 + kof);
            }
            #pragma unroll
            for (int p = 0; p < 2; p++)
                LDMX4(bh[2*p][0], bh[2*p][1], bh[2*p+1][0], bh[2*p+1][1],
                      st + 2 * ARR_B + boff + p * 1280 + kof);
            #pragma unroll
            for (int mi = 0; mi < 4; mi++)
                #pragma unroll
                for (int ni = 0; ni < 4; ni++) {
                    mma_f16(acc[mi][ni], ah[mi], bh[ni]);
                    mma_f16(acc[mi][ni], al[mi], bh[ni]);
                }
        }
        __syncthreads();
        slot = (slot + 1) % NSTAGE;
    }

    // ---- epilogue ----
    const int qr = lane >> 2, qc = lane & 3;
    if (OUT_HILO) {
        hf* chp = Ch + (long long)blockIdx.z * sC;
        hf* clp = Cl + (long long)blockIdx.z * sC;
        #pragma unroll
        for (int mi = 0; mi < 4; mi++)
            #pragma unroll
            for (int ni = 0; ni < 4; ni++) {
                int r = bm * 128 + wm * 64 + mi * 16 + qr;
                int cc = bn * 128 + wn * 32 + ni * 8 + qc * 2;
                if (cc < N) {
                    uint32_t h0, l0, h1, l1;
                    hilo2pack(acc[mi][ni][0], acc[mi][ni][1], h0, l0);
                    hilo2pack(acc[mi][ni][2], acc[mi][ni][3], h1, l1);
                    *(uint32_t*)(chp + (long long)r * ldc + cc) = h0;
                    *(uint32_t*)(clp + (long long)r * ldc + cc) = l0;
                    *(uint32_t*)(chp + (long long)(r + 8) * ldc + cc) = h1;
                    *(uint32_t*)(clp + (long long)(r + 8) * ldc + cc) = l1;
                }
            }
    } else {
        float* cp = C + (long long)blockIdx.z * sC;
        #pragma unroll
        for (int mi = 0; mi < 4; mi++)
            #pragma unroll
            for (int ni = 0; ni < 4; ni++) {
                int r = bm * 128 + wm * 64 + mi * 16 + qr;
                int cc = bn * 128 + wn * 32 + ni * 8 + qc * 2;
                if (cc < N) {
                    *(float2*)(cp + (long long)r * ldc + cc) =
                        make_float2(acc[mi][ni][0], acc[mi][ni][1]);
                    *(float2*)(cp + (long long)(r + 8) * ldc + cc) =
                        make_float2(acc[mi][ni][2], acc[mi][ni][3]);
                }
            }
    }
}

// ============================================================================
// conversion / elementwise kernels
// ============================================================================
__global__ void cvt_hilo_k(const float* __restrict__ in, hf* __restrict__ oh,
                           hf* __restrict__ ol, long long n)
{
    long long i = ((long long)blockIdx.x * 256 + threadIdx.x) * 4;
    if (i >= n) return;
    float4 v = *(const float4*)(in + i);
    uint2 h, l; cvt_hilo4(v, h, l);
    *(uint2*)(oh + i) = h;
    *(uint2*)(ol + i) = l;
}

__global__ void cvt_hi_k(const float* __restrict__ in, hf* __restrict__ oh, long long n)
{
    long long i = ((long long)blockIdx.x * 256 + threadIdx.x) * 4;
    if (i >= n) return;
    float4 v = *(const float4*)(in + i);
    uint2 h;
    hf h0 = __float2half_rn(v.x), h1 = __float2half_rn(v.y);
    hf h2 = __float2half_rn(v.z), h3 = __float2half_rn(v.w);
    h.x = ((uint32_t)__half_as_ushort(h1) << 16) | __half_as_ushort(h0);
    h.y = ((uint32_t)__half_as_ushort(h3) << 16) | __half_as_ushort(h2);
    *(uint2*)(oh + i) = h;
}

// out[c][r] = half(in[r][c]); grid: (C/32, R/32, batch)
__global__ void transcvt_hi_k(const float* __restrict__ in, hf* __restrict__ oh,
                              int ld_in, int ld_out, long long sIn, long long sOut)
{
    __shared__ float tile[32][33];
    const float* ip = in + (long long)blockIdx.z * sIn;
    int r0 = blockIdx.y * 32, c0 = blockIdx.x * 32;
    int tx = threadIdx.x & 31, ty = threadIdx.x >> 5;
    #pragma unroll
    for (int it = 0; it < 4; it++) {
        int r = ty + it * 8;
        tile[r][tx] = ip[(long long)(r0 + r) * ld_in + c0 + tx];
    }
    __syncthreads();
    #pragma unroll
    for (int it = 0; it < 4; it++) {
        int cr = ty + it * 8;
        long long o = (long long)blockIdx.z * sOut + (long long)(c0 + cr) * ld_out + r0 + tx;
        oh[o] = __float2half_rn(tile[tx][cr]);
    }
}

__global__ void rmsnorm_hilo(const float* __restrict__ X, const float* __restrict__ g,
                             hf* __restrict__ oh, hf* __restrict__ ol, int n)
{
    const float* x = X + (long long)blockIdx.x * n;
    hf* ph = oh + (long long)blockIdx.x * n;
    hf* pl = ol + (long long)blockIdx.x * n;
    __shared__ float red[256];
    const int tid = threadIdx.x;
    float s = 0.f;
    for (int i = tid; i < n; i += 256) { float v = x[i]; s += v * v; }
    red[tid] = s; __syncthreads();
    for (int o = 128; o > 0; o >>= 1) {
        if (tid < o) red[tid] += red[tid + o];
        __syncthreads();
    }
    float inv = rsqrtf(red[0] / (float)n + EPSV);
    for (int i = tid; i < n; i += 256) {
        hf hb, lb; hilo1(x[i] * inv * g[i], hb, lb);
        ph[i] = hb; pl[i] = lb;
    }
}

__global__ void kv_post(float* __restrict__ KV, const float* __restrict__ g,
                        const float* __restrict__ cosb, const float* __restrict__ sinb,
                        hf* __restrict__ oh)
{
    const int srow = blockIdx.x;
    float* x = KV + (long long)srow * KEFF;
    hf* ph = oh + (long long)srow * KEFF;
    __shared__ float red[256];
    const int tid = threadIdx.x;
    float s = 0.f;
    for (int i = tid; i < KVLORA; i += 256) { float v = x[i]; s += v * v; }
    red[tid] = s; __syncthreads();
    for (int o = 128; o > 0; o >>= 1) {
        if (tid < o) red[tid] += red[tid + o];
        __syncthreads();
    }
    float inv = rsqrtf(red[0] / (float)KVLORA + EPSV);
    for (int i = tid; i < KVLORA; i += 256) x[i] = x[i] * inv * g[i];
    if (tid < 32) {
        float x1 = x[KVLORA + tid];
        float x2 = x[KVLORA + 32 + tid];
        float c1 = cosb[srow * ROPEW + tid];
        float c2 = cosb[srow * ROPEW + 32 + tid];
        float s1 = sinb[srow * ROPEW + tid];
        float s2 = sinb[srow * ROPEW + 32 + tid];
        x[KVLORA + tid]      = x1 * c1 - x2 * s1;
        x[KVLORA + 32 + tid] = x2 * c2 + x1 * s2;
    }
    __syncthreads();
    for (int i = tid; i < KEFF; i += 256)
        ph[i] = __float2half_rn(x[i]);
}

__global__ void q_rope(const hf* __restrict__ Qh, const hf* __restrict__ Ql,
                       hf* __restrict__ Eh, hf* __restrict__ El,
                       const float* __restrict__ cosb, const float* __restrict__ sinb)
{
    long long idx = (long long)blockIdx.x * blockDim.x + threadIdx.x;
    const long long total = (long long)SS * HH * 32;
    if (idx >= total) return;
    int j  = (int)(idx & 31);
    long long sh = idx >> 5;
    int h = (int)(sh & (HH - 1));
    int s = (int)(sh >> 5);
    long long qb = ((long long)s * HH + h) * QKH + NOPEW;
    float x1 = __half2float(Qh[qb + j]) + __half2float(Ql[qb + j]);
    float x2 = __half2float(Qh[qb + j + 32]) + __half2float(Ql[qb + j + 32]);
    float c1 = cosb[s * ROPEW + j];
    float c2 = cosb[s * ROPEW + 32 + j];
    float s1 = sinb[s * ROPEW + j];
    float s2 = sinb[s * ROPEW + 32 + j];
    long long ob = ((long long)h * SS + s) * KEFF + KVLORA;
    hf hb, lb;
    hilo1(x1 * c1 - x2 * s1, hb, lb);   Eh[ob + j] = hb;      El[ob + j] = lb;
    hilo1(x2 * c2 + x1 * s2, hb, lb);   Eh[ob + j + 32] = hb; El[ob + j + 32] = lb;
}

__global__ void softmax_causal(const float* __restrict__ Sc,
                               hf* __restrict__ Ph, hf* __restrict__ Pl)
{
    __shared__ float buf[SS];
    __shared__ float red[256];
    const int m = blockIdx.x;
    const int h = blockIdx.y;
    const float* row = Sc + ((long long)h * SS + m) * SS;
    hf* ph = Ph + ((long long)h * SS + m) * SS;
    hf* pl = Pl + ((long long)h * SS + m) * SS;
    const int len = m + 1;
    const int pad = ((m >> 7) + 1) << 7;
    const int tid = threadIdx.x;

    float mx = -3.4e38f;
    for (int i = tid; i < len; i += 256) { float v = row[i]; buf[i] = v; mx = fmaxf(mx, v); }
    red[tid] = mx; __syncthreads();
    for (int o = 128; o > 0; o >>= 1) {
        if (tid < o) red[tid] = fmaxf(red[tid], red[tid + o]);
        __syncthreads();
    }
    const float rowmax = red[0];
    __syncthreads();

    float sum = 0.f;
    for (int i = tid; i < len; i += 256) {
        float e = expf(SCALE * (buf[i] - rowmax));
        buf[i] = e;
        sum += e;
    }
    red[tid] = sum; __syncthreads();
    for (int o = 128; o > 0; o >>= 1) {
        if (tid < o) red[tid] += red[tid + o];
        __syncthreads();
    }
    const float rinv = 1.f / red[0];
    for (int i = tid; i < len; i += 256) {
        hf hb, lb; hilo1(buf[i] * rinv, hb, lb);
        ph[i] = hb; pl[i] = lb;
    }
    const hf z = __float2half(0.f);
    for (int i = len + tid; i < pad; i += 256) { ph[i] = z; pl[i] = z; }
}

// ============================================================================
extern "C" void kernel_launch(void* const* d_in, const int* in_sizes, int n_in,
                              void* d_out, int out_size)
{
    (void)in_sizes; (void)n_in; (void)out_size;
    const float* h      = (const float*)d_in[0];
    const float* cosb   = (const float*)d_in[1];
    const float* sinb   = (const float*)d_in[2];
    const float* w_q_a  = (const float*)d_in[3];
    const float* gq     = (const float*)d_in[4];
    const float* w_q_b  = (const float*)d_in[5];
    const float* w_kv_a = (const float*)d_in[6];
    const float* gkv    = (const float*)d_in[7];
    const float* w_uk   = (const float*)d_in[8];
    const float* w_uv   = (const float*)d_in[9];
    const float* w_o    = (const float*)d_in[10];
    float* out = (float*)d_out;

    float *qa_f, *keff_f, *sc;
    hf *hh, *hl, *wqa_h, *wqb_h, *wkva_h, *wo_h, *wukt_h, *wuvt_h;
    hf *qa_h, *qa_l, *q_h, *q_l, *keff_h, *kvct_h, *qeff_h, *qeff_l;
    hf *p_h, *p_l, *ctxl_h, *ctxl_l, *ctx_h, *ctx_l;
    cudaGetSymbolAddress((void**)&qa_f,   g_qa_f);
    cudaGetSymbolAddress((void**)&keff_f, g_keff_f);
    cudaGetSymbolAddress((void**)&sc,     g_scores);
    cudaGetSymbolAddress((void**)&hh,     g_hh);     cudaGetSymbolAddress((void**)&hl,     g_hl);
    cudaGetSymbolAddress((void**)&wqa_h,  g_wqa_h);
    cudaGetSymbolAddress((void**)&wqb_h,  g_wqb_h);
    cudaGetSymbolAddress((void**)&wkva_h, g_wkva_h);
    cudaGetSymbolAddress((void**)&wo_h,   g_wo_h);
    cudaGetSymbolAddress((void**)&wukt_h, g_wukt_h);
    cudaGetSymbolAddress((void**)&wuvt_h, g_wuvt_h);
    cudaGetSymbolAddress((void**)&qa_h,   g_qa_h);   cudaGetSymbolAddress((void**)&qa_l,   g_qa_l);
    cudaGetSymbolAddress((void**)&q_h,    g_q_h);    cudaGetSymbolAddress((void**)&q_l,    g_q_l);
    cudaGetSymbolAddress((void**)&keff_h, g_keff_h);
    cudaGetSymbolAddress((void**)&kvct_h, g_kvct_h);
    cudaGetSymbolAddress((void**)&qeff_h, g_qeff_h); cudaGetSymbolAddress((void**)&qeff_l, g_qeff_l);
    cudaGetSymbolAddress((void**)&p_h,    g_p_h);    cudaGetSymbolAddress((void**)&p_l,    g_p_l);
    cudaGetSymbolAddress((void**)&ctxl_h, g_ctxl_h); cudaGetSymbolAddress((void**)&ctxl_l, g_ctxl_l);
    cudaGetSymbolAddress((void**)&ctx_h,  g_ctx_h);  cudaGetSymbolAddress((void**)&ctx_l,  g_ctx_l);

    cudaFuncSetAttribute(hgemm<0,0,0>, cudaFuncAttributeMaxDynamicSharedMemorySize, GSMEM);
    cudaFuncSetAttribute(hgemm<0,0,1>, cudaFuncAttributeMaxDynamicSharedMemorySize, GSMEM);
    cudaFuncSetAttribute(hgemm<1,0,0>, cudaFuncAttributeMaxDynamicSharedMemorySize, GSMEM);
    cudaFuncSetAttribute(hgemm<0,1,1>, cudaFuncAttributeMaxDynamicSharedMemorySize, GSMEM);

    // --- operand conversions ---
    {
        long long n;
        n = (long long)SS * DD;
        cvt_hilo_k<<<(unsigned)((n/4 + 255)/256), 256>>>(h, hh, hl, n);
        n = (long long)QLORA * DD;
        cvt_hi_k<<<(unsigned)((n/4 + 255)/256), 256>>>(w_q_a, wqa_h, n);
        n = (long long)HH * QKH * QLORA;
        cvt_hi_k<<<(unsigned)((n/4 + 255)/256), 256>>>(w_q_b, wqb_h, n);
        n = (long long)KEFF * DD;
        cvt_hi_k<<<(unsigned)((n/4 + 255)/256), 256>>>(w_kv_a, wkva_h, n);
        n = (long long)DD * HH * VH;
        cvt_hi_k<<<(unsigned)((n/4 + 255)/256), 256>>>(w_o, wo_h, n);
    }
    // w_uk [h][128][512] -> wukt [h][512][128]
    transcvt_hi_k<<<dim3(KVLORA/32, NOPEW/32, HH), 256>>>(
        w_uk, wukt_h, KVLORA, NOPEW,
        (long long)NOPEW*KVLORA, (long long)KVLORA*NOPEW);
    // w_uv [h][512][128] -> wuvt [h][128][512]
    transcvt_hi_k<<<dim3(VH/32, KVLORA/32, HH), 256>>>(
        w_uv, wuvt_h, VH, KVLORA,
        (long long)KVLORA*VH, (long long)VH*KVLORA);

    // 1) q_a = h @ w_q_a^T -> fp32
    hgemm<0,0,0><<<dim3(QLORA/128, SS/128, 1), 256, GSMEM>>>(
        hh, hl, wqa_h, qa_f, nullptr, nullptr,
        SS, QLORA, DD, DD, DD, QLORA, 0, 0, 0);
    // 2) rmsnorm -> hilo
    rmsnorm_hilo<<<SS, 256>>>(qa_f, gq, qa_h, qa_l, QLORA);
    // 3) q = q_a @ w_q_b^T -> hilo
    hgemm<0,0,1><<<dim3((HH*QKH)/128, SS/128, 1), 256, GSMEM>>>(
        qa_h, qa_l, wqb_h, nullptr, q_h, q_l,
        SS, HH*QKH, QLORA, QLORA, QLORA, HH*QKH, 0, 0, 0);
    // 4) kv = h @ w_kv_a^T -> fp32
    hgemm<0,0,0><<<dim3((KEFF+127)/128, SS/128, 1), 256, GSMEM>>>(
        hh, hl, wkva_h, keff_f, nullptr, nullptr,
        SS, KEFF, DD, DD, DD, KEFF, 0, 0, 0);
    // 5) kv post (rmsnorm + rope) -> keff hi
    kv_post<<<SS, 256>>>(keff_f, gkv, cosb, sinb, keff_h);
    // 5b) kv_c transpose -> kvct [512][2048] hi
    transcvt_hi_k<<<dim3(KVLORA/32, SS/32, 1), 256>>>(
        keff_f, kvct_h, KEFF, SS, 0, 0);
    // 6) q_latent -> qeff[:, 0:512] hilo
    hgemm<0,0,1><<<dim3(KVLORA/128, SS/128, HH), 256, GSMEM>>>(
        q_h, q_l, wukt_h, nullptr, qeff_h, qeff_l,
        SS, KVLORA, NOPEW, HH*QKH, NOPEW, KEFF,
        (long long)QKH, (long long)KVLORA*NOPEW, (long long)SS*KEFF);
    // 7) q rope -> qeff[:, 512:576] hilo
    {
        long long total = (long long)SS * HH * 32;
        q_rope<<<(unsigned)((total + 255) / 256), 256>>>(q_h, q_l, qeff_h, qeff_l, cosb, sinb);
    }
    // 8) scores = qeff @ keff^T (causal skip) -> fp32
    hgemm<1,0,0><<<dim3(SS/128, SS/128, HH), 256, GSMEM>>>(
        qeff_h, qeff_l, keff_h, sc, nullptr, nullptr,
        SS, SS, KEFF, KEFF, KEFF, SS,
        (long long)SS*KEFF, 0, (long long)SS*SS);
    // 9) causal softmax -> P hilo (+zero pad)
    softmax_causal<<<dim3(SS, HH), 256>>>(sc, p_h, p_l);
    // 10) ctx_latent = P @ kvct^T (K limited) -> hilo
    hgemm<0,1,1><<<dim3(KVLORA/128, SS/128, HH), 256, GSMEM>>>(
        p_h, p_l, kvct_h, nullptr, ctxl_h, ctxl_l,
        SS, KVLORA, SS, SS, SS, KVLORA,
        (long long)SS*SS, 0, (long long)SS*KVLORA);
    // 11) ctx = ctx_latent @ wuvt^T -> hilo
    hgemm<0,0,1><<<dim3(1, SS/128, HH), 256, GSMEM>>>(
        ctxl_h, ctxl_l, wuvt_h, nullptr, ctx_h, ctx_l,
        SS, VH, KVLORA, KVLORA, KVLORA, HH*VH,
        (long long)SS*KVLORA, (long long)VH*KVLORA, (long long)VH);
    // 12) out = ctx @ w_o^T -> fp32
    hgemm<0,0,0><<<dim3(DD/128, SS/128, 1), 256, GSMEM>>>(
        ctx_h, ctx_l, wo_h, out, nullptr, nullptr,
        SS, DD, HH*VH, HH*VH, HH*VH, DD, 0, 0, 0);
}

// round 8
// speedup vs baseline: 4.6302x; 1.1608x over previous
#include <cuda_runtime.h>
#include <cuda_fp16.h>
#include <stdint.h>
#include <math.h>

// ---------------- problem constants ----------------
#define SS 2048
#define DD 4096
#define HH 32
#define QLORA 1536
#define KVLORA 512
#define ROPEW 64
#define NOPEW 128
#define QKH 192
#define VH 128
#define KEFF 576
#define EPSV 1e-6f
#define SCALE 0.07216878364870322f   // 1/sqrt(192)

typedef __half hf;

// ---------------- scratch ----------------
__device__ float g_qa_f[(size_t)SS * QLORA];
__device__ float g_keff_f[(size_t)SS * KEFF];
__device__ float g_scores[(size_t)HH * SS * SS];
__device__ hf g_hh[(size_t)SS * DD],            g_hl[(size_t)SS * DD];
__device__ hf g_wqa_h[(size_t)QLORA * DD];
__device__ hf g_wqb_h[(size_t)HH*QKH * QLORA];
__device__ hf g_wkva_h[(size_t)KEFF * DD];
__device__ hf g_wo_h[(size_t)DD * HH*VH];
__device__ hf g_wukt_h[(size_t)HH*KVLORA*NOPEW];   // [h][c=512][n=128]
__device__ hf g_wuvt_h[(size_t)HH*VH*KVLORA];      // [h][v=128][c=512]
__device__ hf g_qa_h[(size_t)SS * QLORA],       g_qa_l[(size_t)SS * QLORA];
__device__ hf g_q_h[(size_t)SS * HH*QKH],       g_q_l[(size_t)SS * HH*QKH];
__device__ hf g_keff_h[(size_t)SS * KEFF];
__device__ hf g_kvct_h[(size_t)KVLORA * SS];       // [c=512][s=2048]
__device__ hf g_qeff_h[(size_t)HH*SS*KEFF],     g_qeff_l[(size_t)HH*SS*KEFF];
__device__ hf g_p_h[(size_t)HH*SS*SS];
__device__ hf g_ctxl_h[(size_t)HH*SS*KVLORA],   g_ctxl_l[(size_t)HH*SS*KVLORA];
__device__ hf g_ctx_h[(size_t)SS * HH*VH],      g_ctx_l[(size_t)SS * HH*VH];

// ---------------- helpers ----------------
__device__ __forceinline__ uint32_t smem_u32(const void* p) {
    uint32_t a;
    asm("{ .reg .u64 t; cvta.to.shared.u64 t, %1; cvt.u32.u64 %0, t; }" : "=r"(a) : "l"(p));
    return a;
}

__device__ __forceinline__ void hilo1(float v, hf& h, hf& l) {
    h = __float2half_rn(v);
    l = __float2half_rn(v - __half2float(h));
}
__device__ __forceinline__ void cvt_hilo4(float4 v, uint2& hi, uint2& lo) {
    hf h0, h1, h2, h3, l0, l1, l2, l3;
    hilo1(v.x, h0, l0); hilo1(v.y, h1, l1); hilo1(v.z, h2, l2); hilo1(v.w, h3, l3);
    hi.x = ((uint32_t)__half_as_ushort(h1) << 16) | __half_as_ushort(h0);
    hi.y = ((uint32_t)__half_as_ushort(h3) << 16) | __half_as_ushort(h2);
    lo.x = ((uint32_t)__half_as_ushort(l1) << 16) | __half_as_ushort(l0);
    lo.y = ((uint32_t)__half_as_ushort(l3) << 16) | __half_as_ushort(l2);
}
__device__ __forceinline__ void hilo2pack(float a, float b, uint32_t& h, uint32_t& l) {
    hf ha, hb2, la, lb;
    hilo1(a, ha, la); hilo1(b, hb2, lb);
    h = ((uint32_t)__half_as_ushort(hb2) << 16) | __half_as_ushort(ha);
    l = ((uint32_t)__half_as_ushort(lb) << 16) | __half_as_ushort(la);
}

__device__ __forceinline__ void mma_f16(float* c, const uint32_t* a, const uint32_t* b) {
    asm volatile(
        "mma.sync.aligned.m16n8k16.row.col.f32.f16.f16.f32 "
        "{%0,%1,%2,%3}, {%4,%5,%6,%7}, {%8,%9}, {%0,%1,%2,%3};"
        : "+f"(c[0]), "+f"(c[1]), "+f"(c[2]), "+f"(c[3])
        : "r"(a[0]), "r"(a[1]), "r"(a[2]), "r"(a[3]), "r"(b[0]), "r"(b[1]));
}

#define LDMX4(r0, r1, r2, r3, addr) \
    asm volatile("ldmatrix.sync.aligned.m8n8.x4.shared.b16 {%0,%1,%2,%3}, [%4];" \
        : "=r"(r0), "=r"(r1), "=r"(r2), "=r"(r3) : "r"(addr))

#define CPA16(dst, src, sz) \
    asm volatile("cp.async.cg.shared.global [%0], [%1], 16, %2;" \
        :: "r"(dst), "l"(src), "r"(sz))
#define CPA_COMMIT()  asm volatile("cp.async.commit_group;" ::: "memory")
#define CPA_WAIT2()   asm volatile("cp.async.wait_group 2;" ::: "memory")

// smem: per stage (TERMS+1) arrays, each 128 rows x 40 hf (80B rows)
#define LDT 40
#define ARR_B   (128 * LDT * 2)      // 10240
#define NSTAGE  3
#define GSMEM2  (NSTAGE * 3 * ARR_B) // 92160  (2-term: Ah, Al, Bh)
#define GSMEM1  (NSTAGE * 2 * ARR_B) // 61440  (1-term: Ah, Bh)

// ============================================================================
// NT GEMM: C = A * B^T. K-major fp16 operands.
// TERMS==2: Ah*Bh + Al*Bh (A exact to 2^-22, B rounded)
// TERMS==1: Ah*Bh        (both rounded to fp16)
// 3-stage cp.async pipeline. REQUIRES K/32 >= 3 (min at call sites is 4).
// CSKIP: skip tiles bn > bm.  CKEND: K limited to (bm+1)*128.
// OUT_HILO: write Ch/Cl fp16 hi/lo, else write C fp32.
// ============================================================================
template<int CSKIP, int CKEND, int OUT_HILO, int TERMS>
__global__ void __launch_bounds__(256, 2)
hgemm(const hf* __restrict__ Ah, const hf* __restrict__ Al,
      const hf* __restrict__ Bh,
      float* __restrict__ C, hf* __restrict__ Ch, hf* __restrict__ Cl,
      int M, int N, int K, int lda, int ldb, int ldc,
      long long sA, long long sB, long long sC)
{
    constexpr int NARR = TERMS + 1;
    constexpr int CHUNK_B = NARR * ARR_B;
    constexpr int BARR = (TERMS == 2) ? 2 : 1;   // index of B array

    const int bm = blockIdx.y, bn = blockIdx.x;
    if (CSKIP && bn > bm) return;
    extern __shared__ char smem[];
    const uint32_t sbase = smem_u32(smem);

    const int tid = threadIdx.x, lane = tid & 31, wid = tid >> 5;
    const int wm = wid & 1, wn = wid >> 1;

    Ah += (long long)blockIdx.z * sA;
    if (TERMS == 2) Al += (long long)blockIdx.z * sA;
    Bh += (long long)blockIdx.z * sB;

    const int Kend = CKEND ? min(K, (bm + 1) * 128) : K;
    const int nch = Kend / 32;

    // ---- cp.async: (2*NARR) x 16B per thread per chunk ----
    const int ch = tid & 3;
    const int rr = tid >> 2;           // 0..63
    const int ar0 = bm * 128 + rr;
    const int br0 = bn * 128 + rr, br1 = br0 + 64;
    const uint32_t szB0 = (br0 < N) ? 16u : 0u;
    const uint32_t szB1 = (br1 < N) ? 16u : 0u;
    const hf* pAh0 = Ah + (long long)ar0 * lda + ch * 8;
    const hf* pAh1 = pAh0 + (long long)64 * lda;
    const hf* pAl0 = (TERMS == 2) ? Al + (long long)ar0 * lda + ch * 8 : nullptr;
    const hf* pAl1 = (TERMS == 2) ? pAl0 + (long long)64 * lda : nullptr;
    const hf* pBh0 = Bh + (long long)min(br0, N - 1) * ldb + ch * 8;
    const hf* pBh1 = Bh + (long long)min(br1, N - 1) * ldb + ch * 8;
    const uint32_t d0 = (uint32_t)(rr * 80 + ch * 16);
    const uint32_t d1 = d0 + 64 * 80;

    auto issue = [&](int slot) {
        uint32_t st = sbase + slot * CHUNK_B;
        CPA16(st + 0 * ARR_B + d0, pAh0, 16u);
        CPA16(st + 0 * ARR_B + d1, pAh1, 16u);
        if (TERMS == 2) {
            CPA16(st + 1 * ARR_B + d0, pAl0, 16u);
            CPA16(st + 1 * ARR_B + d1, pAl1, 16u);
            pAl0 += 32; pAl1 += 32;
        }
        CPA16(st + BARR * ARR_B + d0, pBh0, szB0);
        CPA16(st + BARR * ARR_B + d1, pBh1, szB1);
        pAh0 += 32; pAh1 += 32;
        pBh0 += 32; pBh1 += 32;
    };

    // ---- ldmatrix lane offsets ----
    const int arow_l = wm * 64 + ((lane >> 3) & 1) * 8 + (lane & 7);
    const int acol_l = (lane >> 4) * 8;
    const uint32_t aoff = (uint32_t)(arow_l * LDT + acol_l) * 2;
    const int brow_l = wn * 32 + ((lane >> 4) & 1) * 8 + (lane & 7);
    const int bcol_l = ((lane >> 3) & 1) * 8;
    const uint32_t boff = (uint32_t)(brow_l * LDT + bcol_l) * 2;

    float acc[4][4][4];
    #pragma unroll
    for (int a = 0; a < 4; a++)
        #pragma unroll
        for (int b = 0; b < 4; b++)
            #pragma unroll
            for (int q = 0; q < 4; q++) acc[a][b][q] = 0.f;

    issue(0); CPA_COMMIT();
    issue(1); CPA_COMMIT();

    int slot = 0;
    for (int c = 0; c < nch; c++) {
        if (c + 2 < nch) issue((slot + 2) % NSTAGE);
        CPA_COMMIT();
        CPA_WAIT2();                        // oldest group (chunk c) arrived
        __syncthreads();
        const uint32_t st = sbase + slot * CHUNK_B;
        #pragma unroll
        for (int ks = 0; ks < 2; ks++) {
            const uint32_t kof = ks * 32;
            uint32_t ah[4][4], al[4][4], bh[4][2];
            #pragma unroll
            for (int mi = 0; mi < 4; mi++) {
                LDMX4(ah[mi][0], ah[mi][1], ah[mi][2], ah[mi][3],
                      st + 0 * ARR_B + aoff + mi * 1280 + kof);
                if (TERMS == 2)
                    LDMX4(al[mi][0], al[mi][1], al[mi][2], al[mi][3],
                          st + 1 * ARR_B + aoff + mi * 1280 + kof);
            }
            #pragma unroll
            for (int p = 0; p < 2; p++)
                LDMX4(bh[2*p][0], bh[2*p][1], bh[2*p+1][0], bh[2*p+1][1],
                      st + BARR * ARR_B + boff + p * 1280 + kof);
            #pragma unroll
            for (int mi = 0; mi < 4; mi++)
                #pragma unroll
                for (int ni = 0; ni < 4; ni++) {
                    mma_f16(acc[mi][ni], ah[mi], bh[ni]);
                    if (TERMS == 2) mma_f16(acc[mi][ni], al[mi], bh[ni]);
                }
        }
        __syncthreads();
        slot = (slot + 1) % NSTAGE;
    }

    // ---- epilogue ----
    const int qr = lane >> 2, qc = lane & 3;
    if (OUT_HILO) {
        hf* chp = Ch + (long long)blockIdx.z * sC;
        hf* clp = Cl + (long long)blockIdx.z * sC;
        #pragma unroll
        for (int mi = 0; mi < 4; mi++)
            #pragma unroll
            for (int ni = 0; ni < 4; ni++) {
                int r = bm * 128 + wm * 64 + mi * 16 + qr;
                int cc = bn * 128 + wn * 32 + ni * 8 + qc * 2;
                if (cc < N) {
                    uint32_t h0, l0, h1, l1;
                    hilo2pack(acc[mi][ni][0], acc[mi][ni][1], h0, l0);
                    hilo2pack(acc[mi][ni][2], acc[mi][ni][3], h1, l1);
                    *(uint32_t*)(chp + (long long)r * ldc + cc) = h0;
                    *(uint32_t*)(clp + (long long)r * ldc + cc) = l0;
                    *(uint32_t*)(chp + (long long)(r + 8) * ldc + cc) = h1;
                    *(uint32_t*)(clp + (long long)(r + 8) * ldc + cc) = l1;
                }
            }
    } else {
        float* cp = C + (long long)blockIdx.z * sC;
        #pragma unroll
        for (int mi = 0; mi < 4; mi++)
            #pragma unroll
            for (int ni = 0; ni < 4; ni++) {
                int r = bm * 128 + wm * 64 + mi * 16 + qr;
                int cc = bn * 128 + wn * 32 + ni * 8 + qc * 2;
                if (cc < N) {
                    *(float2*)(cp + (long long)r * ldc + cc) =
                        make_float2(acc[mi][ni][0], acc[mi][ni][1]);
                    *(float2*)(cp + (long long)(r + 8) * ldc + cc) =
                        make_float2(acc[mi][ni][2], acc[mi][ni][3]);
                }
            }
    }
}

// ============================================================================
// conversion / elementwise kernels
// ============================================================================
__global__ void cvt_hilo_k(const float* __restrict__ in, hf* __restrict__ oh,
                           hf* __restrict__ ol, long long n)
{
    long long i = ((long long)blockIdx.x * 256 + threadIdx.x) * 4;
    if (i >= n) return;
    float4 v = *(const float4*)(in + i);
    uint2 h, l; cvt_hilo4(v, h, l);
    *(uint2*)(oh + i) = h;
    *(uint2*)(ol + i) = l;
}

__global__ void cvt_hi_k(const float* __restrict__ in, hf* __restrict__ oh, long long n)
{
    long long i = ((long long)blockIdx.x * 256 + threadIdx.x) * 4;
    if (i >= n) return;
    float4 v = *(const float4*)(in + i);
    uint2 h;
    hf h0 = __float2half_rn(v.x), h1 = __float2half_rn(v.y);
    hf h2 = __float2half_rn(v.z), h3 = __float2half_rn(v.w);
    h.x = ((uint32_t)__half_as_ushort(h1) << 16) | __half_as_ushort(h0);
    h.y = ((uint32_t)__half_as_ushort(h3) << 16) | __half_as_ushort(h2);
    *(uint2*)(oh + i) = h;
}

// out[c][r] = half(in[r][c]); grid: (C/32, R/32, batch)
__global__ void transcvt_hi_k(const float* __restrict__ in, hf* __restrict__ oh,
                              int ld_in, int ld_out, long long sIn, long long sOut)
{
    __shared__ float tile[32][33];
    const float* ip = in + (long long)blockIdx.z * sIn;
    int r0 = blockIdx.y * 32, c0 = blockIdx.x * 32;
    int tx = threadIdx.x & 31, ty = threadIdx.x >> 5;
    #pragma unroll
    for (int it = 0; it < 4; it++) {
        int r = ty + it * 8;
        tile[r][tx] = ip[(long long)(r0 + r) * ld_in + c0 + tx];
    }
    __syncthreads();
    #pragma unroll
    for (int it = 0; it < 4; it++) {
        int cr = ty + it * 8;
        long long o = (long long)blockIdx.z * sOut + (long long)(c0 + cr) * ld_out + r0 + tx;
        oh[o] = __float2half_rn(tile[tx][cr]);
    }
}

__global__ void rmsnorm_hilo(const float* __restrict__ X, const float* __restrict__ g,
                             hf* __restrict__ oh, hf* __restrict__ ol, int n)
{
    const float* x = X + (long long)blockIdx.x * n;
    hf* ph = oh + (long long)blockIdx.x * n;
    hf* pl = ol + (long long)blockIdx.x * n;
    __shared__ float red[256];
    const int tid = threadIdx.x;
    float s = 0.f;
    for (int i = tid; i < n; i += 256) { float v = x[i]; s += v * v; }
    red[tid] = s; __syncthreads();
    for (int o = 128; o > 0; o >>= 1) {
        if (tid < o) red[tid] += red[tid + o];
        __syncthreads();
    }
    float inv = rsqrtf(red[0] / (float)n + EPSV);
    for (int i = tid; i < n; i += 256) {
        hf hb, lb; hilo1(x[i] * inv * g[i], hb, lb);
        ph[i] = hb; pl[i] = lb;
    }
}

__global__ void kv_post(float* __restrict__ KV, const float* __restrict__ g,
                        const float* __restrict__ cosb, const float* __restrict__ sinb,
                        hf* __restrict__ oh)
{
    const int srow = blockIdx.x;
    float* x = KV + (long long)srow * KEFF;
    hf* ph = oh + (long long)srow * KEFF;
    __shared__ float red[256];
    const int tid = threadIdx.x;
    float s = 0.f;
    for (int i = tid; i < KVLORA; i += 256) { float v = x[i]; s += v * v; }
    red[tid] = s; __syncthreads();
    for (int o = 128; o > 0; o >>= 1) {
        if (tid < o) red[tid] += red[tid + o];
        __syncthreads();
    }
    float inv = rsqrtf(red[0] / (float)KVLORA + EPSV);
    for (int i = tid; i < KVLORA; i += 256) x[i] = x[i] * inv * g[i];
    if (tid < 32) {
        float x1 = x[KVLORA + tid];
        float x2 = x[KVLORA + 32 + tid];
        float c1 = cosb[srow * ROPEW + tid];
        float c2 = cosb[srow * ROPEW + 32 + tid];
        float s1 = sinb[srow * ROPEW + tid];
        float s2 = sinb[srow * ROPEW + 32 + tid];
        x[KVLORA + tid]      = x1 * c1 - x2 * s1;
        x[KVLORA + 32 + tid] = x2 * c2 + x1 * s2;
    }
    __syncthreads();
    for (int i = tid; i < KEFF; i += 256)
        ph[i] = __float2half_rn(x[i]);
}

__global__ void q_rope(const hf* __restrict__ Qh, const hf* __restrict__ Ql,
                       hf* __restrict__ Eh, hf* __restrict__ El,
                       const float* __restrict__ cosb, const float* __restrict__ sinb)
{
    long long idx = (long long)blockIdx.x * blockDim.x + threadIdx.x;
    const long long total = (long long)SS * HH * 32;
    if (idx >= total) return;
    int j  = (int)(idx & 31);
    long long sh = idx >> 5;
    int h = (int)(sh & (HH - 1));
    int s = (int)(sh >> 5);
    long long qb = ((long long)s * HH + h) * QKH + NOPEW;
    float x1 = __half2float(Qh[qb + j]) + __half2float(Ql[qb + j]);
    float x2 = __half2float(Qh[qb + j + 32]) + __half2float(Ql[qb + j + 32]);
    float c1 = cosb[s * ROPEW + j];
    float c2 = cosb[s * ROPEW + 32 + j];
    float s1 = sinb[s * ROPEW + j];
    float s2 = sinb[s * ROPEW + 32 + j];
    long long ob = ((long long)h * SS + s) * KEFF + KVLORA;
    hf hb, lb;
    hilo1(x1 * c1 - x2 * s1, hb, lb);   Eh[ob + j] = hb;      El[ob + j] = lb;
    hilo1(x2 * c2 + x1 * s2, hb, lb);   Eh[ob + j + 32] = hb; El[ob + j + 32] = lb;
}

// softmax: P written as fp16 hi ONLY (consumed by 1-term PV GEMM)
__global__ void softmax_causal(const float* __restrict__ Sc, hf* __restrict__ Ph)
{
    __shared__ float buf[SS];
    __shared__ float red[256];
    const int m = blockIdx.x;
    const int h = blockIdx.y;
    const float* row = Sc + ((long long)h * SS + m) * SS;
    hf* ph = Ph + ((long long)h * SS + m) * SS;
    const int len = m + 1;
    const int pad = ((m >> 7) + 1) << 7;
    const int tid = threadIdx.x;

    float mx = -3.4e38f;
    for (int i = tid; i < len; i += 256) { float v = row[i]; buf[i] = v; mx = fmaxf(mx, v); }
    red[tid] = mx; __syncthreads();
    for (int o = 128; o > 0; o >>= 1) {
        if (tid < o) red[tid] = fmaxf(red[tid], red[tid + o]);
        __syncthreads();
    }
    const float rowmax = red[0];
    __syncthreads();

    float sum = 0.f;
    for (int i = tid; i < len; i += 256) {
        float e = expf(SCALE * (buf[i] - rowmax));
        buf[i] = e;
        sum += e;
    }
    red[tid] = sum; __syncthreads();
    for (int o = 128; o > 0; o >>= 1) {
        if (tid < o) red[tid] += red[tid + o];
        __syncthreads();
    }
    const float rinv = 1.f / red[0];
    for (int i = tid; i < len; i += 256)
        ph[i] = __float2half_rn(buf[i] * rinv);
    const hf z = __float2half(0.f);
    for (int i = len + tid; i < pad; i += 256) ph[i] = z;
}

// ============================================================================
extern "C" void kernel_launch(void* const* d_in, const int* in_sizes, int n_in,
                              void* d_out, int out_size)
{
    (void)in_sizes; (void)n_in; (void)out_size;
    const float* h      = (const float*)d_in[0];
    const float* cosb   = (const float*)d_in[1];
    const float* sinb   = (const float*)d_in[2];
    const float* w_q_a  = (const float*)d_in[3];
    const float* gq     = (const float*)d_in[4];
    const float* w_q_b  = (const float*)d_in[5];
    const float* w_kv_a = (const float*)d_in[6];
    const float* gkv    = (const float*)d_in[7];
    const float* w_uk   = (const float*)d_in[8];
    const float* w_uv   = (const float*)d_in[9];
    const float* w_o    = (const float*)d_in[10];
    float* out = (float*)d_out;

    float *qa_f, *keff_f, *sc;
    hf *hh, *hl, *wqa_h, *wqb_h, *wkva_h, *wo_h, *wukt_h, *wuvt_h;
    hf *qa_h, *qa_l, *q_h, *q_l, *keff_h, *kvct_h, *qeff_h, *qeff_l;
    hf *p_h, *ctxl_h, *ctxl_l, *ctx_h, *ctx_l;
    cudaGetSymbolAddress((void**)&qa_f,   g_qa_f);
    cudaGetSymbolAddress((void**)&keff_f, g_keff_f);
    cudaGetSymbolAddress((void**)&sc,     g_scores);
    cudaGetSymbolAddress((void**)&hh,     g_hh);     cudaGetSymbolAddress((void**)&hl,     g_hl);
    cudaGetSymbolAddress((void**)&wqa_h,  g_wqa_h);
    cudaGetSymbolAddress((void**)&wqb_h,  g_wqb_h);
    cudaGetSymbolAddress((void**)&wkva_h, g_wkva_h);
    cudaGetSymbolAddress((void**)&wo_h,   g_wo_h);
    cudaGetSymbolAddress((void**)&wukt_h, g_wukt_h);
    cudaGetSymbolAddress((void**)&wuvt_h, g_wuvt_h);
    cudaGetSymbolAddress((void**)&qa_h,   g_qa_h);   cudaGetSymbolAddress((void**)&qa_l,   g_qa_l);
    cudaGetSymbolAddress((void**)&q_h,    g_q_h);    cudaGetSymbolAddress((void**)&q_l,    g_q_l);
    cudaGetSymbolAddress((void**)&keff_h, g_keff_h);
    cudaGetSymbolAddress((void**)&kvct_h, g_kvct_h);
    cudaGetSymbolAddress((void**)&qeff_h, g_qeff_h); cudaGetSymbolAddress((void**)&qeff_l, g_qeff_l);
    cudaGetSymbolAddress((void**)&p_h,    g_p_h);
    cudaGetSymbolAddress((void**)&ctxl_h, g_ctxl_h); cudaGetSymbolAddress((void**)&ctxl_l, g_ctxl_l);
    cudaGetSymbolAddress((void**)&ctx_h,  g_ctx_h);  cudaGetSymbolAddress((void**)&ctx_l,  g_ctx_l);

    cudaFuncSetAttribute(hgemm<0,0,0,2>, cudaFuncAttributeMaxDynamicSharedMemorySize, GSMEM2);
    cudaFuncSetAttribute(hgemm<0,0,1,2>, cudaFuncAttributeMaxDynamicSharedMemorySize, GSMEM2);
    cudaFuncSetAttribute(hgemm<1,0,0,2>, cudaFuncAttributeMaxDynamicSharedMemorySize, GSMEM2);
    cudaFuncSetAttribute(hgemm<0,1,1,1>, cudaFuncAttributeMaxDynamicSharedMemorySize, GSMEM1);
    cudaFuncSetAttribute(hgemm<0,0,0,1>, cudaFuncAttributeMaxDynamicSharedMemorySize, GSMEM1);

    // --- operand conversions ---
    {
        long long n;
        n = (long long)SS * DD;
        cvt_hilo_k<<<(unsigned)((n/4 + 255)/256), 256>>>(h, hh, hl, n);
        n = (long long)QLORA * DD;
        cvt_hi_k<<<(unsigned)((n/4 + 255)/256), 256>>>(w_q_a, wqa_h, n);
        n = (long long)HH * QKH * QLORA;
        cvt_hi_k<<<(unsigned)((n/4 + 255)/256), 256>>>(w_q_b, wqb_h, n);
        n = (long long)KEFF * DD;
        cvt_hi_k<<<(unsigned)((n/4 + 255)/256), 256>>>(w_kv_a, wkva_h, n);
        n = (long long)DD * HH * VH;
        cvt_hi_k<<<(unsigned)((n/4 + 255)/256), 256>>>(w_o, wo_h, n);
    }
    // w_uk [h][128][512] -> wukt [h][512][128]
    transcvt_hi_k<<<dim3(KVLORA/32, NOPEW/32, HH), 256>>>(
        w_uk, wukt_h, KVLORA, NOPEW,
        (long long)NOPEW*KVLORA, (long long)KVLORA*NOPEW);
    // w_uv [h][512][128] -> wuvt [h][128][512]
    transcvt_hi_k<<<dim3(VH/32, KVLORA/32, HH), 256>>>(
        w_uv, wuvt_h, VH, KVLORA,
        (long long)KVLORA*VH, (long long)VH*KVLORA);

    // 1) q_a = h @ w_q_a^T -> fp32                      (2-term)
    hgemm<0,0,0,2><<<dim3(QLORA/128, SS/128, 1), 256, GSMEM2>>>(
        hh, hl, wqa_h, qa_f, nullptr, nullptr,
        SS, QLORA, DD, DD, DD, QLORA, 0, 0, 0);
    // 2) rmsnorm -> hilo
    rmsnorm_hilo<<<SS, 256>>>(qa_f, gq, qa_h, qa_l, QLORA);
    // 3) q = q_a @ w_q_b^T -> hilo                      (2-term)
    hgemm<0,0,1,2><<<dim3((HH*QKH)/128, SS/128, 1), 256, GSMEM2>>>(
        qa_h, qa_l, wqb_h, nullptr, q_h, q_l,
        SS, HH*QKH, QLORA, QLORA, QLORA, HH*QKH, 0, 0, 0);
    // 4) kv = h @ w_kv_a^T -> fp32                      (2-term)
    hgemm<0,0,0,2><<<dim3((KEFF+127)/128, SS/128, 1), 256, GSMEM2>>>(
        hh, hl, wkva_h, keff_f, nullptr, nullptr,
        SS, KEFF, DD, DD, DD, KEFF, 0, 0, 0);
    // 5) kv post (rmsnorm + rope) -> keff hi
    kv_post<<<SS, 256>>>(keff_f, gkv, cosb, sinb, keff_h);
    // 5b) kv_c transpose -> kvct [512][2048] hi
    transcvt_hi_k<<<dim3(KVLORA/32, SS/32, 1), 256>>>(
        keff_f, kvct_h, KEFF, SS, 0, 0);
    // 6) q_latent -> qeff[:, 0:512] hilo                (2-term)
    hgemm<0,0,1,2><<<dim3(KVLORA/128, SS/128, HH), 256, GSMEM2>>>(
        q_h, q_l, wukt_h, nullptr, qeff_h, qeff_l,
        SS, KVLORA, NOPEW, HH*QKH, NOPEW, KEFF,
        (long long)QKH, (long long)KVLORA*NOPEW, (long long)SS*KEFF);
    // 7) q rope -> qeff[:, 512:576] hilo
    {
        long long total = (long long)SS * HH * 32;
        q_rope<<<(unsigned)((total + 255) / 256), 256>>>(q_h, q_l, qeff_h, qeff_l, cosb, sinb);
    }
    // 8) scores = qeff @ keff^T (causal skip) -> fp32   (2-term)
    hgemm<1,0,0,2><<<dim3(SS/128, SS/128, HH), 256, GSMEM2>>>(
        qeff_h, qeff_l, keff_h, sc, nullptr, nullptr,
        SS, SS, KEFF, KEFF, KEFF, SS,
        (long long)SS*KEFF, 0, (long long)SS*SS);
    // 9) causal softmax -> P hi only (+zero pad)
    softmax_causal<<<dim3(SS, HH), 256>>>(sc, p_h);
    // 10) ctx_latent = P @ kvct^T (K limited) -> hilo   (1-term)
    hgemm<0,1,1,1><<<dim3(KVLORA/128, SS/128, HH), 256, GSMEM1>>>(
        p_h, nullptr, kvct_h, nullptr, ctxl_h, ctxl_l,
        SS, KVLORA, SS, SS, SS, KVLORA,
        (long long)SS*SS, 0, (long long)SS*KVLORA);
    // 11) ctx = ctxl @ wuvt^T -> hilo                   (2-term)
    hgemm<0,0,1,2><<<dim3(1, SS/128, HH), 256, GSMEM2>>>(
        ctxl_h, ctxl_l, wuvt_h, nullptr, ctx_h, ctx_l,
        SS, VH, KVLORA, KVLORA, KVLORA, HH*VH,
        (long long)SS*KVLORA, (long long)VH*KVLORA, (long long)VH);
    // 12) out = ctx @ w_o^T -> fp32                     (1-term, ctx hi only)
    hgemm<0,0,0,1><<<dim3(DD/128, SS/128, 1), 256, GSMEM1>>>(
        ctx_h, nullptr, wo_h, out, nullptr, nullptr,
        SS, DD, HH*VH, HH*VH, HH*VH, DD, 0, 0, 0);
}

// round 9
// speedup vs baseline: 4.9010x; 1.0585x over previous
#include <cuda_runtime.h>
#include <cuda_fp16.h>
#include <stdint.h>
#include <math.h>

// ---------------- problem constants ----------------
#define SS 2048
#define DD 4096
#define HH 32
#define QLORA 1536
#define KVLORA 512
#define ROPEW 64
#define NOPEW 128
#define QKH 192
#define VH 128
#define KEFF 576
#define EPSV 1e-6f
#define SCALE 0.07216878364870322f   // 1/sqrt(192)

typedef __half hf;

// ---------------- scratch ----------------
__device__ float g_qa_f[(size_t)SS * QLORA];
__device__ float g_keff_f[(size_t)SS * KEFF];
__device__ float g_scores[(size_t)HH * SS * SS];
__device__ hf g_hh[(size_t)SS * DD],            g_hl[(size_t)SS * DD];
__device__ hf g_wqa_h[(size_t)QLORA * DD];
__device__ hf g_wqb_h[(size_t)HH*QKH * QLORA];
__device__ hf g_wkva_h[(size_t)KEFF * DD];
__device__ hf g_wo_h[(size_t)DD * HH*VH];
__device__ hf g_wukt_h[(size_t)HH*KVLORA*NOPEW];   // [h][c=512][n=128]
__device__ hf g_wuvt_h[(size_t)HH*VH*KVLORA];      // [h][v=128][c=512]
__device__ hf g_qa_h[(size_t)SS * QLORA],       g_qa_l[(size_t)SS * QLORA];
__device__ hf g_q_h[(size_t)SS * HH*QKH],       g_q_l[(size_t)SS * HH*QKH];
__device__ hf g_keff_h[(size_t)SS * KEFF];
__device__ hf g_kvct_h[(size_t)KVLORA * SS];       // [c=512][s=2048]
__device__ hf g_qeff_h[(size_t)HH*SS*KEFF],     g_qeff_l[(size_t)HH*SS*KEFF];
__device__ hf g_p_h[(size_t)HH*SS*SS];
__device__ hf g_ctxl_h[(size_t)HH*SS*KVLORA],   g_ctxl_l[(size_t)HH*SS*KVLORA];
__device__ hf g_ctx_h[(size_t)SS * HH*VH],      g_ctx_l[(size_t)SS * HH*VH];

// ---------------- helpers ----------------
__device__ __forceinline__ uint32_t smem_u32(const void* p) {
    uint32_t a;
    asm("{ .reg .u64 t; cvta.to.shared.u64 t, %1; cvt.u32.u64 %0, t; }" : "=r"(a) : "l"(p));
    return a;
}

__device__ __forceinline__ void hilo1(float v, hf& h, hf& l) {
    h = __float2half_rn(v);
    l = __float2half_rn(v - __half2float(h));
}
__device__ __forceinline__ void cvt_hilo4(float4 v, uint2& hi, uint2& lo) {
    hf h0, h1, h2, h3, l0, l1, l2, l3;
    hilo1(v.x, h0, l0); hilo1(v.y, h1, l1); hilo1(v.z, h2, l2); hilo1(v.w, h3, l3);
    hi.x = ((uint32_t)__half_as_ushort(h1) << 16) | __half_as_ushort(h0);
    hi.y = ((uint32_t)__half_as_ushort(h3) << 16) | __half_as_ushort(h2);
    lo.x = ((uint32_t)__half_as_ushort(l1) << 16) | __half_as_ushort(l0);
    lo.y = ((uint32_t)__half_as_ushort(l3) << 16) | __half_as_ushort(l2);
}
__device__ __forceinline__ void hilo2pack(float a, float b, uint32_t& h, uint32_t& l) {
    hf ha, hb2, la, lb;
    hilo1(a, ha, la); hilo1(b, hb2, lb);
    h = ((uint32_t)__half_as_ushort(hb2) << 16) | __half_as_ushort(ha);
    l = ((uint32_t)__half_as_ushort(lb) << 16) | __half_as_ushort(la);
}

__device__ __forceinline__ void mma_f16(float* c, const uint32_t* a, const uint32_t* b) {
    asm volatile(
        "mma.sync.aligned.m16n8k16.row.col.f32.f16.f16.f32 "
        "{%0,%1,%2,%3}, {%4,%5,%6,%7}, {%8,%9}, {%0,%1,%2,%3};"
        : "+f"(c[0]), "+f"(c[1]), "+f"(c[2]), "+f"(c[3])
        : "r"(a[0]), "r"(a[1]), "r"(a[2]), "r"(a[3]), "r"(b[0]), "r"(b[1]));
}

#define LDMX4(r0, r1, r2, r3, addr) \
    asm volatile("ldmatrix.sync.aligned.m8n8.x4.shared.b16 {%0,%1,%2,%3}, [%4];" \
        : "=r"(r0), "=r"(r1), "=r"(r2), "=r"(r3) : "r"(addr))

#define CPA16(dst, src, sz) \
    asm volatile("cp.async.cg.shared.global [%0], [%1], 16, %2;" \
        :: "r"(dst), "l"(src), "r"(sz))
#define CPA_COMMIT()  asm volatile("cp.async.commit_group;" ::: "memory")
#define CPA_WAIT1()   asm volatile("cp.async.wait_group 1;" ::: "memory")

// smem: per stage (TERMS+1) arrays, each 128 rows x 40 hf (80B rows)
#define LDT 40
#define ARR_B   (128 * LDT * 2)      // 10240
#define NSTAGE  3
#define GSMEM2  (NSTAGE * 3 * ARR_B) // 92160  (2-term: Ah, Al, Bh)
#define GSMEM1  (NSTAGE * 2 * ARR_B) // 61440  (1-term: Ah, Bh)

// ============================================================================
// NT GEMM: C = A * B^T. K-major fp16 operands.
// TERMS==2: Ah*Bh + Al*Bh   TERMS==1: Ah*Bh
// Single-barrier 3-stage cp.async pipeline. REQUIRES K/32 >= 3 (min is 4).
// TRI: grid.x is a compacted lower-triangle index (scores GEMM).
// CKEND: K limited to (bm+1)*128.  OUT_HILO: write fp16 hi/lo, else fp32.
// ============================================================================
template<int TRI, int CKEND, int OUT_HILO, int TERMS>
__global__ void __launch_bounds__(256, 2)
hgemm(const hf* __restrict__ Ah, const hf* __restrict__ Al,
      const hf* __restrict__ Bh,
      float* __restrict__ C, hf* __restrict__ Ch, hf* __restrict__ Cl,
      int M, int N, int K, int lda, int ldb, int ldc,
      long long sA, long long sB, long long sC)
{
    constexpr int NARR = TERMS + 1;
    constexpr int CHUNK_B = NARR * ARR_B;
    constexpr int BARR = (TERMS == 2) ? 2 : 1;   // index of B array

    int bm, bn;
    if (TRI) {
        // decode lower-triangle linear index -> (bm, bn), bn <= bm
        int bi = blockIdx.x;
        bm = (int)((sqrtf(8.f * (float)bi + 1.f) - 1.f) * 0.5f);
        while ((bm + 1) * (bm + 2) / 2 <= bi) bm++;
        while (bm * (bm + 1) / 2 > bi) bm--;
        bn = bi - bm * (bm + 1) / 2;
        if (bn > bm) return;   // safety net
    } else {
        bm = blockIdx.y; bn = blockIdx.x;
    }
    extern __shared__ char smem[];
    const uint32_t sbase = smem_u32(smem);

    const int tid = threadIdx.x, lane = tid & 31, wid = tid >> 5;
    const int wm = wid & 1, wn = wid >> 1;

    Ah += (long long)blockIdx.z * sA;
    if (TERMS == 2) Al += (long long)blockIdx.z * sA;
    Bh += (long long)blockIdx.z * sB;

    const int Kend = CKEND ? min(K, (bm + 1) * 128) : K;
    const int nch = Kend / 32;

    // ---- cp.async: (2*NARR) x 16B per thread per chunk ----
    const int ch = tid & 3;
    const int rr = tid >> 2;           // 0..63
    const int ar0 = bm * 128 + rr;
    const int br0 = bn * 128 + rr, br1 = br0 + 64;
    const uint32_t szB0 = (br0 < N) ? 16u : 0u;
    const uint32_t szB1 = (br1 < N) ? 16u : 0u;
    const hf* pAh0 = Ah + (long long)ar0 * lda + ch * 8;
    const hf* pAh1 = pAh0 + (long long)64 * lda;
    const hf* pAl0 = (TERMS == 2) ? Al + (long long)ar0 * lda + ch * 8 : nullptr;
    const hf* pAl1 = (TERMS == 2) ? pAl0 + (long long)64 * lda : nullptr;
    const hf* pBh0 = Bh + (long long)min(br0, N - 1) * ldb + ch * 8;
    const hf* pBh1 = Bh + (long long)min(br1, N - 1) * ldb + ch * 8;
    const uint32_t d0 = (uint32_t)(rr * 80 + ch * 16);
    const uint32_t d1 = d0 + 64 * 80;

    auto issue = [&](int slot) {
        uint32_t st = sbase + slot * CHUNK_B;
        CPA16(st + 0 * ARR_B + d0, pAh0, 16u);
        CPA16(st + 0 * ARR_B + d1, pAh1, 16u);
        if (TERMS == 2) {
            CPA16(st + 1 * ARR_B + d0, pAl0, 16u);
            CPA16(st + 1 * ARR_B + d1, pAl1, 16u);
            pAl0 += 32; pAl1 += 32;
        }
        CPA16(st + BARR * ARR_B + d0, pBh0, szB0);
        CPA16(st + BARR * ARR_B + d1, pBh1, szB1);
        pAh0 += 32; pAh1 += 32;
        pBh0 += 32; pBh1 += 32;
    };

    // ---- ldmatrix lane offsets ----
    const int arow_l = wm * 64 + ((lane >> 3) & 1) * 8 + (lane & 7);
    const int acol_l = (lane >> 4) * 8;
    const uint32_t aoff = (uint32_t)(arow_l * LDT + acol_l) * 2;
    const int brow_l = wn * 32 + ((lane >> 4) & 1) * 8 + (lane & 7);
    const int bcol_l = ((lane >> 3) & 1) * 8;
    const uint32_t boff = (uint32_t)(brow_l * LDT + bcol_l) * 2;

    float acc[4][4][4];
    #pragma unroll
    for (int a = 0; a < 4; a++)
        #pragma unroll
        for (int b = 0; b < 4; b++)
            #pragma unroll
            for (int q = 0; q < 4; q++) acc[a][b][q] = 0.f;

    issue(0); CPA_COMMIT();
    issue(1); CPA_COMMIT();

    int slot = 0;
    for (int c = 0; c < nch; c++) {
        CPA_WAIT1();                        // own copies of chunk c done
        __syncthreads();                    // all threads' chunk c visible;
                                            // also: all reads of slot (c-1) done
        if (c + 2 < nch) issue((slot + 2) % NSTAGE);   // into slot (c-1)%3
        CPA_COMMIT();
        const uint32_t st = sbase + slot * CHUNK_B;
        #pragma unroll
        for (int ks = 0; ks < 2; ks++) {
            const uint32_t kof = ks * 32;
            uint32_t ah[4][4], al[4][4], bh[4][2];
            #pragma unroll
            for (int mi = 0; mi < 4; mi++) {
                LDMX4(ah[mi][0], ah[mi][1], ah[mi][2], ah[mi][3],
                      st + 0 * ARR_B + aoff + mi * 1280 + kof);
                if (TERMS == 2)
                    LDMX4(al[mi][0], al[mi][1], al[mi][2], al[mi][3],
                          st + 1 * ARR_B + aoff + mi * 1280 + kof);
            }
            #pragma unroll
            for (int p = 0; p < 2; p++)
                LDMX4(bh[2*p][0], bh[2*p][1], bh[2*p+1][0], bh[2*p+1][1],
                      st + BARR * ARR_B + boff + p * 1280 + kof);
            #pragma unroll
            for (int mi = 0; mi < 4; mi++)
                #pragma unroll
                for (int ni = 0; ni < 4; ni++) {
                    mma_f16(acc[mi][ni], ah[mi], bh[ni]);
                    if (TERMS == 2) mma_f16(acc[mi][ni], al[mi], bh[ni]);
                }
        }
        slot = (slot + 1) % NSTAGE;
    }

    // ---- epilogue ----
    const int qr = lane >> 2, qc = lane & 3;
    if (OUT_HILO) {
        hf* chp = Ch + (long long)blockIdx.z * sC;
        hf* clp = Cl + (long long)blockIdx.z * sC;
        #pragma unroll
        for (int mi = 0; mi < 4; mi++)
            #pragma unroll
            for (int ni = 0; ni < 4; ni++) {
                int r = bm * 128 + wm * 64 + mi * 16 + qr;
                int cc = bn * 128 + wn * 32 + ni * 8 + qc * 2;
                if (cc < N) {
                    uint32_t h0, l0, h1, l1;
                    hilo2pack(acc[mi][ni][0], acc[mi][ni][1], h0, l0);
                    hilo2pack(acc[mi][ni][2], acc[mi][ni][3], h1, l1);
                    *(uint32_t*)(chp + (long long)r * ldc + cc) = h0;
                    *(uint32_t*)(clp + (long long)r * ldc + cc) = l0;
                    *(uint32_t*)(chp + (long long)(r + 8) * ldc + cc) = h1;
                    *(uint32_t*)(clp + (long long)(r + 8) * ldc + cc) = l1;
                }
            }
    } else {
        float* cp = C + (long long)blockIdx.z * sC;
        #pragma unroll
        for (int mi = 0; mi < 4; mi++)
            #pragma unroll
            for (int ni = 0; ni < 4; ni++) {
                int r = bm * 128 + wm * 64 + mi * 16 + qr;
                int cc = bn * 128 + wn * 32 + ni * 8 + qc * 2;
                if (cc < N) {
                    *(float2*)(cp + (long long)r * ldc + cc) =
                        make_float2(acc[mi][ni][0], acc[mi][ni][1]);
                    *(float2*)(cp + (long long)(r + 8) * ldc + cc) =
                        make_float2(acc[mi][ni][2], acc[mi][ni][3]);
                }
            }
    }
}

// ============================================================================
// conversion / elementwise kernels
// ============================================================================
__global__ void cvt_hilo_k(const float* __restrict__ in, hf* __restrict__ oh,
                           hf* __restrict__ ol, long long n)
{
    long long i = ((long long)blockIdx.x * 256 + threadIdx.x) * 4;
    if (i >= n) return;
    float4 v = *(const float4*)(in + i);
    uint2 h, l; cvt_hilo4(v, h, l);
    *(uint2*)(oh + i) = h;
    *(uint2*)(ol + i) = l;
}

__global__ void cvt_hi_k(const float* __restrict__ in, hf* __restrict__ oh, long long n)
{
    long long i = ((long long)blockIdx.x * 256 + threadIdx.x) * 4;
    if (i >= n) return;
    float4 v = *(const float4*)(in + i);
    uint2 h;
    hf h0 = __float2half_rn(v.x), h1 = __float2half_rn(v.y);
    hf h2 = __float2half_rn(v.z), h3 = __float2half_rn(v.w);
    h.x = ((uint32_t)__half_as_ushort(h1) << 16) | __half_as_ushort(h0);
    h.y = ((uint32_t)__half_as_ushort(h3) << 16) | __half_as_ushort(h2);
    *(uint2*)(oh + i) = h;
}

// out[c][r] = half(in[r][c]); grid: (C/32, R/32, batch)
__global__ void transcvt_hi_k(const float* __restrict__ in, hf* __restrict__ oh,
                              int ld_in, int ld_out, long long sIn, long long sOut)
{
    __shared__ float tile[32][33];
    const float* ip = in + (long long)blockIdx.z * sIn;
    int r0 = blockIdx.y * 32, c0 = blockIdx.x * 32;
    int tx = threadIdx.x & 31, ty = threadIdx.x >> 5;
    #pragma unroll
    for (int it = 0; it < 4; it++) {
        int r = ty + it * 8;
        tile[r][tx] = ip[(long long)(r0 + r) * ld_in + c0 + tx];
    }
    __syncthreads();
    #pragma unroll
    for (int it = 0; it < 4; it++) {
        int cr = ty + it * 8;
        long long o = (long long)blockIdx.z * sOut + (long long)(c0 + cr) * ld_out + r0 + tx;
        oh[o] = __float2half_rn(tile[tx][cr]);
    }
}

__global__ void rmsnorm_hilo(const float* __restrict__ X, const float* __restrict__ g,
                             hf* __restrict__ oh, hf* __restrict__ ol, int n)
{
    const float* x = X + (long long)blockIdx.x * n;
    hf* ph = oh + (long long)blockIdx.x * n;
    hf* pl = ol + (long long)blockIdx.x * n;
    __shared__ float red[256];
    const int tid = threadIdx.x;
    float s = 0.f;
    for (int i = tid; i < n; i += 256) { float v = x[i]; s += v * v; }
    red[tid] = s; __syncthreads();
    for (int o = 128; o > 0; o >>= 1) {
        if (tid < o) red[tid] += red[tid + o];
        __syncthreads();
    }
    float inv = rsqrtf(red[0] / (float)n + EPSV);
    for (int i = tid; i < n; i += 256) {
        hf hb, lb; hilo1(x[i] * inv * g[i], hb, lb);
        ph[i] = hb; pl[i] = lb;
    }
}

__global__ void kv_post(float* __restrict__ KV, const float* __restrict__ g,
                        const float* __restrict__ cosb, const float* __restrict__ sinb,
                        hf* __restrict__ oh)
{
    const int srow = blockIdx.x;
    float* x = KV + (long long)srow * KEFF;
    hf* ph = oh + (long long)srow * KEFF;
    __shared__ float red[256];
    const int tid = threadIdx.x;
    float s = 0.f;
    for (int i = tid; i < KVLORA; i += 256) { float v = x[i]; s += v * v; }
    red[tid] = s; __syncthreads();
    for (int o = 128; o > 0; o >>= 1) {
        if (tid < o) red[tid] += red[tid + o];
        __syncthreads();
    }
    float inv = rsqrtf(red[0] / (float)KVLORA + EPSV);
    for (int i = tid; i < KVLORA; i += 256) x[i] = x[i] * inv * g[i];
    if (tid < 32) {
        float x1 = x[KVLORA + tid];
        float x2 = x[KVLORA + 32 + tid];
        float c1 = cosb[srow * ROPEW + tid];
        float c2 = cosb[srow * ROPEW + 32 + tid];
        float s1 = sinb[srow * ROPEW + tid];
        float s2 = sinb[srow * ROPEW + 32 + tid];
        x[KVLORA + tid]      = x1 * c1 - x2 * s1;
        x[KVLORA + 32 + tid] = x2 * c2 + x1 * s2;
    }
    __syncthreads();
    for (int i = tid; i < KEFF; i += 256)
        ph[i] = __float2half_rn(x[i]);
}

__global__ void q_rope(const hf* __restrict__ Qh, const hf* __restrict__ Ql,
                       hf* __restrict__ Eh, hf* __restrict__ El,
                       const float* __restrict__ cosb, const float* __restrict__ sinb)
{
    long long idx = (long long)blockIdx.x * blockDim.x + threadIdx.x;
    const long long total = (long long)SS * HH * 32;
    if (idx >= total) return;
    int j  = (int)(idx & 31);
    long long sh = idx >> 5;
    int h = (int)(sh & (HH - 1));
    int s = (int)(sh >> 5);
    long long qb = ((long long)s * HH + h) * QKH + NOPEW;
    float x1 = __half2float(Qh[qb + j]) + __half2float(Ql[qb + j]);
    float x2 = __half2float(Qh[qb + j + 32]) + __half2float(Ql[qb + j + 32]);
    float c1 = cosb[s * ROPEW + j];
    float c2 = cosb[s * ROPEW + 32 + j];
    float s1 = sinb[s * ROPEW + j];
    float s2 = sinb[s * ROPEW + 32 + j];
    long long ob = ((long long)h * SS + s) * KEFF + KVLORA;
    hf hb, lb;
    hilo1(x1 * c1 - x2 * s1, hb, lb);   Eh[ob + j] = hb;      El[ob + j] = lb;
    hilo1(x2 * c2 + x1 * s2, hb, lb);   Eh[ob + j + 32] = hb; El[ob + j + 32] = lb;
}

// softmax: P written as fp16 hi ONLY (consumed by 1-term PV GEMM)
__global__ void softmax_causal(const float* __restrict__ Sc, hf* __restrict__ Ph)
{
    __shared__ float buf[SS];
    __shared__ float red[256];
    const int m = blockIdx.x;
    const int h = blockIdx.y;
    const float* row = Sc + ((long long)h * SS + m) * SS;
    hf* ph = Ph + ((long long)h * SS + m) * SS;
    const int len = m + 1;
    const int pad = ((m >> 7) + 1) << 7;
    const int tid = threadIdx.x;

    float mx = -3.4e38f;
    for (int i = tid; i < len; i += 256) { float v = row[i]; buf[i] = v; mx = fmaxf(mx, v); }
    red[tid] = mx; __syncthreads();
    for (int o = 128; o > 0; o >>= 1) {
        if (tid < o) red[tid] = fmaxf(red[tid], red[tid + o]);
        __syncthreads();
    }
    const float rowmax = red[0];
    __syncthreads();

    float sum = 0.f;
    for (int i = tid; i < len; i += 256) {
        float e = expf(SCALE * (buf[i] - rowmax));
        buf[i] = e;
        sum += e;
    }
    red[tid] = sum; __syncthreads();
    for (int o = 128; o > 0; o >>= 1) {
        if (tid < o) red[tid] += red[tid + o];
        __syncthreads();
    }
    const float rinv = 1.f / red[0];
    for (int i = tid; i < len; i += 256)
        ph[i] = __float2half_rn(buf[i] * rinv);
    const hf z = __float2half(0.f);
    for (int i = len + tid; i < pad; i += 256) ph[i] = z;
}

// ============================================================================
extern "C" void kernel_launch(void* const* d_in, const int* in_sizes, int n_in,
                              void* d_out, int out_size)
{
    (void)in_sizes; (void)n_in; (void)out_size;
    const float* h      = (const float*)d_in[0];
    const float* cosb   = (const float*)d_in[1];
    const float* sinb   = (const float*)d_in[2];
    const float* w_q_a  = (const float*)d_in[3];
    const float* gq     = (const float*)d_in[4];
    const float* w_q_b  = (const float*)d_in[5];
    const float* w_kv_a = (const float*)d_in[6];
    const float* gkv    = (const float*)d_in[7];
    const float* w_uk   = (const float*)d_in[8];
    const float* w_uv   = (const float*)d_in[9];
    const float* w_o    = (const float*)d_in[10];
    float* out = (float*)d_out;

    float *qa_f, *keff_f, *sc;
    hf *hh, *hl, *wqa_h, *wqb_h, *wkva_h, *wo_h, *wukt_h, *wuvt_h;
    hf *qa_h, *qa_l, *q_h, *q_l, *keff_h, *kvct_h, *qeff_h, *qeff_l;
    hf *p_h, *ctxl_h, *ctxl_l, *ctx_h, *ctx_l;
    cudaGetSymbolAddress((void**)&qa_f,   g_qa_f);
    cudaGetSymbolAddress((void**)&keff_f, g_keff_f);
    cudaGetSymbolAddress((void**)&sc,     g_scores);
    cudaGetSymbolAddress((void**)&hh,     g_hh);     cudaGetSymbolAddress((void**)&hl,     g_hl);
    cudaGetSymbolAddress((void**)&wqa_h,  g_wqa_h);
    cudaGetSymbolAddress((void**)&wqb_h,  g_wqb_h);
    cudaGetSymbolAddress((void**)&wkva_h, g_wkva_h);
    cudaGetSymbolAddress((void**)&wo_h,   g_wo_h);
    cudaGetSymbolAddress((void**)&wukt_h, g_wukt_h);
    cudaGetSymbolAddress((void**)&wuvt_h, g_wuvt_h);
    cudaGetSymbolAddress((void**)&qa_h,   g_qa_h);   cudaGetSymbolAddress((void**)&qa_l,   g_qa_l);
    cudaGetSymbolAddress((void**)&q_h,    g_q_h);    cudaGetSymbolAddress((void**)&q_l,    g_q_l);
    cudaGetSymbolAddress((void**)&keff_h, g_keff_h);
    cudaGetSymbolAddress((void**)&kvct_h, g_kvct_h);
    cudaGetSymbolAddress((void**)&qeff_h, g_qeff_h); cudaGetSymbolAddress((void**)&qeff_l, g_qeff_l);
    cudaGetSymbolAddress((void**)&p_h,    g_p_h);
    cudaGetSymbolAddress((void**)&ctxl_h, g_ctxl_h); cudaGetSymbolAddress((void**)&ctxl_l, g_ctxl_l);
    cudaGetSymbolAddress((void**)&ctx_h,  g_ctx_h);  cudaGetSymbolAddress((void**)&ctx_l,  g_ctx_l);

    cudaFuncSetAttribute(hgemm<0,0,0,2>, cudaFuncAttributeMaxDynamicSharedMemorySize, GSMEM2);
    cudaFuncSetAttribute(hgemm<0,0,1,2>, cudaFuncAttributeMaxDynamicSharedMemorySize, GSMEM2);
    cudaFuncSetAttribute(hgemm<1,0,0,2>, cudaFuncAttributeMaxDynamicSharedMemorySize, GSMEM2);
    cudaFuncSetAttribute(hgemm<0,1,1,1>, cudaFuncAttributeMaxDynamicSharedMemorySize, GSMEM1);
    cudaFuncSetAttribute(hgemm<0,0,0,1>, cudaFuncAttributeMaxDynamicSharedMemorySize, GSMEM1);

    // --- operand conversions ---
    {
        long long n;
        n = (long long)SS * DD;
        cvt_hilo_k<<<(unsigned)((n/4 + 255)/256), 256>>>(h, hh, hl, n);
        n = (long long)QLORA * DD;
        cvt_hi_k<<<(unsigned)((n/4 + 255)/256), 256>>>(w_q_a, wqa_h, n);
        n = (long long)HH * QKH * QLORA;
        cvt_hi_k<<<(unsigned)((n/4 + 255)/256), 256>>>(w_q_b, wqb_h, n);
        n = (long long)KEFF * DD;
        cvt_hi_k<<<(unsigned)((n/4 + 255)/256), 256>>>(w_kv_a, wkva_h, n);
        n = (long long)DD * HH * VH;
        cvt_hi_k<<<(unsigned)((n/4 + 255)/256), 256>>>(w_o, wo_h, n);
    }
    // w_uk [h][128][512] -> wukt [h][512][128]
    transcvt_hi_k<<<dim3(KVLORA/32, NOPEW/32, HH), 256>>>(
        w_uk, wukt_h, KVLORA, NOPEW,
        (long long)NOPEW*KVLORA, (long long)KVLORA*NOPEW);
    // w_uv [h][512][128] -> wuvt [h][128][512]
    transcvt_hi_k<<<dim3(VH/32, KVLORA/32, HH), 256>>>(
        w_uv, wuvt_h, VH, KVLORA,
        (long long)KVLORA*VH, (long long)VH*KVLORA);

    // 1) q_a = h @ w_q_a^T -> fp32                      (2-term)
    hgemm<0,0,0,2><<<dim3(QLORA/128, SS/128, 1), 256, GSMEM2>>>(
        hh, hl, wqa_h, qa_f, nullptr, nullptr,
        SS, QLORA, DD, DD, DD, QLORA, 0, 0, 0);
    // 2) rmsnorm -> hilo
    rmsnorm_hilo<<<SS, 256>>>(qa_f, gq, qa_h, qa_l, QLORA);
    // 3) q = q_a @ w_q_b^T -> hilo                      (2-term)
    hgemm<0,0,1,2><<<dim3((HH*QKH)/128, SS/128, 1), 256, GSMEM2>>>(
        qa_h, qa_l, wqb_h, nullptr, q_h, q_l,
        SS, HH*QKH, QLORA, QLORA, QLORA, HH*QKH, 0, 0, 0);
    // 4) kv = h @ w_kv_a^T -> fp32                      (2-term)
    hgemm<0,0,0,2><<<dim3((KEFF+127)/128, SS/128, 1), 256, GSMEM2>>>(
        hh, hl, wkva_h, keff_f, nullptr, nullptr,
        SS, KEFF, DD, DD, DD, KEFF, 0, 0, 0);
    // 5) kv post (rmsnorm + rope) -> keff hi
    kv_post<<<SS, 256>>>(keff_f, gkv, cosb, sinb, keff_h);
    // 5b) kv_c transpose -> kvct [512][2048] hi
    transcvt_hi_k<<<dim3(KVLORA/32, SS/32, 1), 256>>>(
        keff_f, kvct_h, KEFF, SS, 0, 0);
    // 6) q_latent -> qeff[:, 0:512] hilo                (2-term)
    hgemm<0,0,1,2><<<dim3(KVLORA/128, SS/128, HH), 256, GSMEM2>>>(
        q_h, q_l, wukt_h, nullptr, qeff_h, qeff_l,
        SS, KVLORA, NOPEW, HH*QKH, NOPEW, KEFF,
        (long long)QKH, (long long)KVLORA*NOPEW, (long long)SS*KEFF);
    // 7) q rope -> qeff[:, 512:576] hilo
    {
        long long total = (long long)SS * HH * 32;
        q_rope<<<(unsigned)((total + 255) / 256), 256>>>(q_h, q_l, qeff_h, qeff_l, cosb, sinb);
    }
    // 8) scores = qeff @ keff^T -> fp32  (2-term, triangle-compacted grid)
    {
        const int NT = SS / 128;                    // 16
        const int NTRI = NT * (NT + 1) / 2;         // 136
        hgemm<1,0,0,2><<<dim3(NTRI, 1, HH), 256, GSMEM2>>>(
            qeff_h, qeff_l, keff_h, sc, nullptr, nullptr,
            SS, SS, KEFF, KEFF, KEFF, SS,
            (long long)SS*KEFF, 0, (long long)SS*SS);
    }
    // 9) causal softmax -> P hi only (+zero pad)
    softmax_causal<<<dim3(SS, HH), 256>>>(sc, p_h);
    // 10) ctx_latent = P @ kvct^T (K limited) -> hilo   (1-term)
    hgemm<0,1,1,1><<<dim3(KVLORA/128, SS/128, HH), 256, GSMEM1>>>(
        p_h, nullptr, kvct_h, nullptr, ctxl_h, ctxl_l,
        SS, KVLORA, SS, SS, SS, KVLORA,
        (long long)SS*SS, 0, (long long)SS*KVLORA);
    // 11) ctx = ctxl @ wuvt^T -> hilo                   (2-term)
    hgemm<0,0,1,2><<<dim3(1, SS/128, HH), 256, GSMEM2>>>(
        ctxl_h, ctxl_l, wuvt_h, nullptr, ctx_h, ctx_l,
        SS, VH, KVLORA, KVLORA, KVLORA, HH*VH,
        (long long)SS*KVLORA, (long long)VH*KVLORA, (long long)VH);
    // 12) out = ctx @ w_o^T -> fp32                     (1-term, ctx hi only)
    hgemm<0,0,0,1><<<dim3(DD/128, SS/128, 1), 256, GSMEM1>>>(
        ctx_h, nullptr, wo_h, out, nullptr, nullptr,
        SS, DD, HH*VH, HH*VH, HH*VH, DD, 0, 0, 0);
}

// round 10
// speedup vs baseline: 5.2631x; 1.0739x over previous
#include <cuda_runtime.h>
#include <cuda_fp16.h>
#include <stdint.h>
#include <math.h>

// ---------------- problem constants ----------------
#define SS 2048
#define DD 4096
#define HH 32
#define QLORA 1536
#define KVLORA 512
#define ROPEW 64
#define NOPEW 128
#define QKH 192
#define VH 128
#define KEFF 576
#define NCOMB (QLORA + KEFF)   // 2112: combined q_a | kv projection width
#define EPSV 1e-6f
#define SCALE 0.07216878364870322f   // 1/sqrt(192)

typedef __half hf;

// ---------------- scratch ----------------
__device__ float g_qakv_f[(size_t)SS * NCOMB];     // combined q_a | kv fp32
__device__ float g_scores[(size_t)HH * SS * SS];
__device__ hf g_hh[(size_t)SS * DD],            g_hl[(size_t)SS * DD];
__device__ hf g_wcomb_h[(size_t)NCOMB * DD];       // w_q_a rows | w_kv_a rows
__device__ hf g_wqb_h[(size_t)HH*QKH * QLORA];
__device__ hf g_wo_h[(size_t)DD * HH*VH];
__device__ hf g_wukt_h[(size_t)HH*KVLORA*NOPEW];   // [h][c=512][n=128]
__device__ hf g_wuvt_h[(size_t)HH*VH*KVLORA];      // [h][v=128][c=512]
__device__ hf g_qa_h[(size_t)SS * QLORA],       g_qa_l[(size_t)SS * QLORA];
__device__ hf g_q_h[(size_t)SS * HH*QKH],       g_q_l[(size_t)SS * HH*QKH];
__device__ hf g_keff_h[(size_t)SS * KEFF];
__device__ hf g_kvct_h[(size_t)KVLORA * SS];       // [c=512][s=2048]
__device__ hf g_qeff_h[(size_t)HH*SS*KEFF],     g_qeff_l[(size_t)HH*SS*KEFF];
__device__ hf g_p_h[(size_t)HH*SS*SS];
__device__ hf g_ctxl_h[(size_t)HH*SS*KVLORA],   g_ctxl_l[(size_t)HH*SS*KVLORA];
__device__ hf g_ctx_h[(size_t)SS * HH*VH],      g_ctx_l[(size_t)SS * HH*VH];

// ---------------- helpers ----------------
__device__ __forceinline__ uint32_t smem_u32(const void* p) {
    uint32_t a;
    asm("{ .reg .u64 t; cvta.to.shared.u64 t, %1; cvt.u32.u64 %0, t; }" : "=r"(a) : "l"(p));
    return a;
}

__device__ __forceinline__ void hilo1(float v, hf& h, hf& l) {
    h = __float2half_rn(v);
    l = __float2half_rn(v - __half2float(h));
}
__device__ __forceinline__ void cvt_hilo4(float4 v, uint2& hi, uint2& lo) {
    hf h0, h1, h2, h3, l0, l1, l2, l3;
    hilo1(v.x, h0, l0); hilo1(v.y, h1, l1); hilo1(v.z, h2, l2); hilo1(v.w, h3, l3);
    hi.x = ((uint32_t)__half_as_ushort(h1) << 16) | __half_as_ushort(h0);
    hi.y = ((uint32_t)__half_as_ushort(h3) << 16) | __half_as_ushort(h2);
    lo.x = ((uint32_t)__half_as_ushort(l1) << 16) | __half_as_ushort(l0);
    lo.y = ((uint32_t)__half_as_ushort(l3) << 16) | __half_as_ushort(l2);
}
__device__ __forceinline__ void hilo2pack(float a, float b, uint32_t& h, uint32_t& l) {
    hf ha, hb2, la, lb;
    hilo1(a, ha, la); hilo1(b, hb2, lb);
    h = ((uint32_t)__half_as_ushort(hb2) << 16) | __half_as_ushort(ha);
    l = ((uint32_t)__half_as_ushort(lb) << 16) | __half_as_ushort(la);
}

__device__ __forceinline__ void mma_f16(float* c, const uint32_t* a, const uint32_t* b) {
    asm volatile(
        "mma.sync.aligned.m16n8k16.row.col.f32.f16.f16.f32 "
        "{%0,%1,%2,%3}, {%4,%5,%6,%7}, {%8,%9}, {%0,%1,%2,%3};"
        : "+f"(c[0]), "+f"(c[1]), "+f"(c[2]), "+f"(c[3])
        : "r"(a[0]), "r"(a[1]), "r"(a[2]), "r"(a[3]), "r"(b[0]), "r"(b[1]));
}

#define LDMX4(r0, r1, r2, r3, addr) \
    asm volatile("ldmatrix.sync.aligned.m8n8.x4.shared.b16 {%0,%1,%2,%3}, [%4];" \
        : "=r"(r0), "=r"(r1), "=r"(r2), "=r"(r3) : "r"(addr))

#define CPA16(dst, src, sz) \
    asm volatile("cp.async.cg.shared.global [%0], [%1], 16, %2;" \
        :: "r"(dst), "l"(src), "r"(sz))
#define CPA_COMMIT()  asm volatile("cp.async.commit_group;" ::: "memory")
#define CPA_WAIT1()   asm volatile("cp.async.wait_group 1;" ::: "memory")

#define LDT 40
#define ARR_B   (128 * LDT * 2)      // 10240
#define NSTAGE  3
#define GSMEM2  (NSTAGE * 3 * ARR_B) // 92160
#define GSMEM1  (NSTAGE * 2 * ARR_B) // 61440

// ============================================================================
// NT GEMM: C = A * B^T. K-major fp16 operands.  (same as round-9 core)
// TERMS==2: Ah*Bh + Al*Bh   TERMS==1: Ah*Bh
// Single-barrier 3-stage cp.async pipeline. REQUIRES K/32 >= 3.
// TRI: compacted lower-triangle grid.x.  CKEND: K limited to (bm+1)*128.
// ============================================================================
template<int TRI, int CKEND, int OUT_HILO, int TERMS>
__global__ void __launch_bounds__(256, 2)
hgemm(const hf* __restrict__ Ah, const hf* __restrict__ Al,
      const hf* __restrict__ Bh,
      float* __restrict__ C, hf* __restrict__ Ch, hf* __restrict__ Cl,
      int M, int N, int K, int lda, int ldb, int ldc,
      long long sA, long long sB, long long sC)
{
    constexpr int NARR = TERMS + 1;
    constexpr int CHUNK_B = NARR * ARR_B;
    constexpr int BARR = (TERMS == 2) ? 2 : 1;

    int bm, bn;
    if (TRI) {
        int bi = blockIdx.x;
        bm = (int)((sqrtf(8.f * (float)bi + 1.f) - 1.f) * 0.5f);
        while ((bm + 1) * (bm + 2) / 2 <= bi) bm++;
        while (bm * (bm + 1) / 2 > bi) bm--;
        bn = bi - bm * (bm + 1) / 2;
        if (bn > bm) return;
    } else {
        bm = blockIdx.y; bn = blockIdx.x;
    }
    extern __shared__ char smem[];
    const uint32_t sbase = smem_u32(smem);

    const int tid = threadIdx.x, lane = tid & 31, wid = tid >> 5;
    const int wm = wid & 1, wn = wid >> 1;

    Ah += (long long)blockIdx.z * sA;
    if (TERMS == 2) Al += (long long)blockIdx.z * sA;
    Bh += (long long)blockIdx.z * sB;

    const int Kend = CKEND ? min(K, (bm + 1) * 128) : K;
    const int nch = Kend / 32;

    const int ch = tid & 3;
    const int rr = tid >> 2;
    const int ar0 = bm * 128 + rr;
    const int br0 = bn * 128 + rr, br1 = br0 + 64;
    const uint32_t szB0 = (br0 < N) ? 16u : 0u;
    const uint32_t szB1 = (br1 < N) ? 16u : 0u;
    const hf* pAh0 = Ah + (long long)ar0 * lda + ch * 8;
    const hf* pAh1 = pAh0 + (long long)64 * lda;
    const hf* pAl0 = (TERMS == 2) ? Al + (long long)ar0 * lda + ch * 8 : nullptr;
    const hf* pAl1 = (TERMS == 2) ? pAl0 + (long long)64 * lda : nullptr;
    const hf* pBh0 = Bh + (long long)min(br0, N - 1) * ldb + ch * 8;
    const hf* pBh1 = Bh + (long long)min(br1, N - 1) * ldb + ch * 8;
    const uint32_t d0 = (uint32_t)(rr * 80 + ch * 16);
    const uint32_t d1 = d0 + 64 * 80;

    auto issue = [&](int slot) {
        uint32_t st = sbase + slot * CHUNK_B;
        CPA16(st + 0 * ARR_B + d0, pAh0, 16u);
        CPA16(st + 0 * ARR_B + d1, pAh1, 16u);
        if (TERMS == 2) {
            CPA16(st + 1 * ARR_B + d0, pAl0, 16u);
            CPA16(st + 1 * ARR_B + d1, pAl1, 16u);
            pAl0 += 32; pAl1 += 32;
        }
        CPA16(st + BARR * ARR_B + d0, pBh0, szB0);
        CPA16(st + BARR * ARR_B + d1, pBh1, szB1);
        pAh0 += 32; pAh1 += 32;
        pBh0 += 32; pBh1 += 32;
    };

    const int arow_l = wm * 64 + ((lane >> 3) & 1) * 8 + (lane & 7);
    const int acol_l = (lane >> 4) * 8;
    const uint32_t aoff = (uint32_t)(arow_l * LDT + acol_l) * 2;
    const int brow_l = wn * 32 + ((lane >> 4) & 1) * 8 + (lane & 7);
    const int bcol_l = ((lane >> 3) & 1) * 8;
    const uint32_t boff = (uint32_t)(brow_l * LDT + bcol_l) * 2;

    float acc[4][4][4];
    #pragma unroll
    for (int a = 0; a < 4; a++)
        #pragma unroll
        for (int b = 0; b < 4; b++)
            #pragma unroll
            for (int q = 0; q < 4; q++) acc[a][b][q] = 0.f;

    issue(0); CPA_COMMIT();
    issue(1); CPA_COMMIT();

    int slot = 0;
    for (int c = 0; c < nch; c++) {
        CPA_WAIT1();
        __syncthreads();
        if (c + 2 < nch) issue((slot + 2) % NSTAGE);
        CPA_COMMIT();
        const uint32_t st = sbase + slot * CHUNK_B;
        #pragma unroll
        for (int ks = 0; ks < 2; ks++) {
            const uint32_t kof = ks * 32;
            uint32_t ah[4][4], al[4][4], bh[4][2];
            #pragma unroll
            for (int mi = 0; mi < 4; mi++) {
                LDMX4(ah[mi][0], ah[mi][1], ah[mi][2], ah[mi][3],
                      st + 0 * ARR_B + aoff + mi * 1280 + kof);
                if (TERMS == 2)
                    LDMX4(al[mi][0], al[mi][1], al[mi][2], al[mi][3],
                          st + 1 * ARR_B + aoff + mi * 1280 + kof);
            }
            #pragma unroll
            for (int p = 0; p < 2; p++)
                LDMX4(bh[2*p][0], bh[2*p][1], bh[2*p+1][0], bh[2*p+1][1],
                      st + BARR * ARR_B + boff + p * 1280 + kof);
            #pragma unroll
            for (int mi = 0; mi < 4; mi++)
                #pragma unroll
                for (int ni = 0; ni < 4; ni++) {
                    mma_f16(acc[mi][ni], ah[mi], bh[ni]);
                    if (TERMS == 2) mma_f16(acc[mi][ni], al[mi], bh[ni]);
                }
        }
        slot = (slot + 1) % NSTAGE;
    }

    const int qr = lane >> 2, qc = lane & 3;
    if (OUT_HILO) {
        hf* chp = Ch + (long long)blockIdx.z * sC;
        hf* clp = Cl + (long long)blockIdx.z * sC;
        #pragma unroll
        for (int mi = 0; mi < 4; mi++)
            #pragma unroll
            for (int ni = 0; ni < 4; ni++) {
                int r = bm * 128 + wm * 64 + mi * 16 + qr;
                int cc = bn * 128 + wn * 32 + ni * 8 + qc * 2;
                if (cc < N) {
                    uint32_t h0, l0, h1, l1;
                    hilo2pack(acc[mi][ni][0], acc[mi][ni][1], h0, l0);
                    hilo2pack(acc[mi][ni][2], acc[mi][ni][3], h1, l1);
                    *(uint32_t*)(chp + (long long)r * ldc + cc) = h0;
                    *(uint32_t*)(clp + (long long)r * ldc + cc) = l0;
                    *(uint32_t*)(chp + (long long)(r + 8) * ldc + cc) = h1;
                    *(uint32_t*)(clp + (long long)(r + 8) * ldc + cc) = l1;
                }
            }
    } else {
        float* cp = C + (long long)blockIdx.z * sC;
        #pragma unroll
        for (int mi = 0; mi < 4; mi++)
            #pragma unroll
            for (int ni = 0; ni < 4; ni++) {
                int r = bm * 128 + wm * 64 + mi * 16 + qr;
                int cc = bn * 128 + wn * 32 + ni * 8 + qc * 2;
                if (cc < N) {
                    *(float2*)(cp + (long long)r * ldc + cc) =
                        make_float2(acc[mi][ni][0], acc[mi][ni][1]);
                    *(float2*)(cp + (long long)(r + 8) * ldc + cc) =
                        make_float2(acc[mi][ni][2], acc[mi][ni][3]);
                }
            }
    }
}

// ============================================================================
// conversion / elementwise kernels
// ============================================================================
__global__ void cvt_hilo_k(const float* __restrict__ in, hf* __restrict__ oh,
                           hf* __restrict__ ol, long long n)
{
    long long i = ((long long)blockIdx.x * 256 + threadIdx.x) * 4;
    if (i >= n) return;
    float4 v = *(const float4*)(in + i);
    uint2 h, l; cvt_hilo4(v, h, l);
    *(uint2*)(oh + i) = h;
    *(uint2*)(ol + i) = l;
}

// 4 flat fp32->fp16 conversions fused in one launch (segmented by block id)
__global__ void cvt_hi_multi(const float* __restrict__ s0, hf* __restrict__ d0, long long n0,
                             const float* __restrict__ s1, hf* __restrict__ d1, long long n1,
                             const float* __restrict__ s2, hf* __restrict__ d2, long long n2,
                             const float* __restrict__ s3, hf* __restrict__ d3, long long n3,
                             int b1, int b2, int b3)
{
    int b = blockIdx.x;
    const float* s; hf* d; long long n; int lb;
    if (b < b1)      { s = s0; d = d0; n = n0; lb = b; }
    else if (b < b2) { s = s1; d = d1; n = n1; lb = b - b1; }
    else if (b < b3) { s = s2; d = d2; n = n2; lb = b - b2; }
    else             { s = s3; d = d3; n = n3; lb = b - b3; }
    long long i = ((long long)lb * 256 + threadIdx.x) * 4;
    if (i >= n) return;
    float4 v = *(const float4*)(s + i);
    uint2 h;
    hf h0 = __float2half_rn(v.x), h1 = __float2half_rn(v.y);
    hf h2 = __float2half_rn(v.z), h3 = __float2half_rn(v.w);
    h.x = ((uint32_t)__half_as_ushort(h1) << 16) | __half_as_ushort(h0);
    h.y = ((uint32_t)__half_as_ushort(h3) << 16) | __half_as_ushort(h2);
    *(uint2*)(d + i) = h;
}

// out[c][r] = half(in[r][c]); grid: (C/32, R/32, batch)
__global__ void transcvt_hi_k(const float* __restrict__ in, hf* __restrict__ oh,
                              int ld_in, int ld_out, long long sIn, long long sOut)
{
    __shared__ float tile[32][33];
    const float* ip = in + (long long)blockIdx.z * sIn;
    int r0 = blockIdx.y * 32, c0 = blockIdx.x * 32;
    int tx = threadIdx.x & 31, ty = threadIdx.x >> 5;
    #pragma unroll
    for (int it = 0; it < 4; it++) {
        int r = ty + it * 8;
        tile[r][tx] = ip[(long long)(r0 + r) * ld_in + c0 + tx];
    }
    __syncthreads();
    #pragma unroll
    for (int it = 0; it < 4; it++) {
        int cr = ty + it * 8;
        long long o = (long long)blockIdx.z * sOut + (long long)(c0 + cr) * ld_out + r0 + tx;
        oh[o] = __float2half_rn(tile[tx][cr]);
    }
}

// rmsnorm over first n cols of a row with row stride ldx -> hilo
__global__ void rmsnorm_hilo(const float* __restrict__ X, const float* __restrict__ g,
                             hf* __restrict__ oh, hf* __restrict__ ol, int n, int ldx)
{
    const float* x = X + (long long)blockIdx.x * ldx;
    hf* ph = oh + (long long)blockIdx.x * n;
    hf* pl = ol + (long long)blockIdx.x * n;
    __shared__ float red[256];
    const int tid = threadIdx.x;
    float s = 0.f;
    for (int i = tid; i < n; i += 256) { float v = x[i]; s += v * v; }
    red[tid] = s; __syncthreads();
    for (int o = 128; o > 0; o >>= 1) {
        if (tid < o) red[tid] += red[tid + o];
        __syncthreads();
    }
    float inv = rsqrtf(red[0] / (float)n + EPSV);
    for (int i = tid; i < n; i += 256) {
        hf hb, lb; hilo1(x[i] * inv * g[i], hb, lb);
        ph[i] = hb; pl[i] = lb;
    }
}

// kv rows live at KV + row*ld + off (combined buffer); in-place norm+rope, out hi
__global__ void kv_post(float* __restrict__ KV, int ld, int off,
                        const float* __restrict__ g,
                        const float* __restrict__ cosb, const float* __restrict__ sinb,
                        hf* __restrict__ oh)
{
    const int srow = blockIdx.x;
    float* x = KV + (long long)srow * ld + off;
    hf* ph = oh + (long long)srow * KEFF;
    __shared__ float red[256];
    const int tid = threadIdx.x;
    float s = 0.f;
    for (int i = tid; i < KVLORA; i += 256) { float v = x[i]; s += v * v; }
    red[tid] = s; __syncthreads();
    for (int o = 128; o > 0; o >>= 1) {
        if (tid < o) red[tid] += red[tid + o];
        __syncthreads();
    }
    float inv = rsqrtf(red[0] / (float)KVLORA + EPSV);
    for (int i = tid; i < KVLORA; i += 256) x[i] = x[i] * inv * g[i];
    if (tid < 32) {
        float x1 = x[KVLORA + tid];
        float x2 = x[KVLORA + 32 + tid];
        float c1 = cosb[srow * ROPEW + tid];
        float c2 = cosb[srow * ROPEW + 32 + tid];
        float s1 = sinb[srow * ROPEW + tid];
        float s2 = sinb[srow * ROPEW + 32 + tid];
        x[KVLORA + tid]      = x1 * c1 - x2 * s1;
        x[KVLORA + 32 + tid] = x2 * c2 + x1 * s2;
    }
    __syncthreads();
    for (int i = tid; i < KEFF; i += 256)
        ph[i] = __float2half_rn(x[i]);
}

__global__ void q_rope(const hf* __restrict__ Qh, const hf* __restrict__ Ql,
                       hf* __restrict__ Eh, hf* __restrict__ El,
                       const float* __restrict__ cosb, const float* __restrict__ sinb)
{
    long long idx = (long long)blockIdx.x * blockDim.x + threadIdx.x;
    const long long total = (long long)SS * HH * 32;
    if (idx >= total) return;
    int j  = (int)(idx & 31);
    long long sh = idx >> 5;
    int h = (int)(sh & (HH - 1));
    int s = (int)(sh >> 5);
    long long qb = ((long long)s * HH + h) * QKH + NOPEW;
    float x1 = __half2float(Qh[qb + j]) + __half2float(Ql[qb + j]);
    float x2 = __half2float(Qh[qb + j + 32]) + __half2float(Ql[qb + j + 32]);
    float c1 = cosb[s * ROPEW + j];
    float c2 = cosb[s * ROPEW + 32 + j];
    float s1 = sinb[s * ROPEW + j];
    float s2 = sinb[s * ROPEW + 32 + j];
    long long ob = ((long long)h * SS + s) * KEFF + KVLORA;
    hf hb, lb;
    hilo1(x1 * c1 - x2 * s1, hb, lb);   Eh[ob + j] = hb;      El[ob + j] = lb;
    hilo1(x2 * c2 + x1 * s2, hb, lb);   Eh[ob + j + 32] = hb; El[ob + j + 32] = lb;
}

// vectorized causal softmax: fp32 scores (float4 loads) -> fp16 P (uint2 stores)
__global__ void softmax_causal(const float* __restrict__ Sc, hf* __restrict__ Ph)
{
    __shared__ float4 buf4[SS / 4];
    __shared__ float red[256];
    float* buf = (float*)buf4;
    const int m = blockIdx.x;
    const int h = blockIdx.y;
    const float* row = Sc + ((long long)h * SS + m) * SS;
    hf* ph = Ph + ((long long)h * SS + m) * SS;
    const int len = m + 1;
    const int n4 = len >> 2;
    const int pad = ((m >> 7) + 1) << 7;
    const int tid = threadIdx.x;

    float mx = -3.4e38f;
    for (int i = tid; i < n4; i += 256) {
        float4 v = *(const float4*)(row + i * 4);
        buf4[i] = v;
        mx = fmaxf(fmaxf(mx, fmaxf(v.x, v.y)), fmaxf(v.z, v.w));
    }
    for (int i = n4 * 4 + tid; i < len; i += 256) {
        float v = row[i]; buf[i] = v; mx = fmaxf(mx, v);
    }
    red[tid] = mx; __syncthreads();
    for (int o = 128; o > 0; o >>= 1) {
        if (tid < o) red[tid] = fmaxf(red[tid], red[tid + o]);
        __syncthreads();
    }
    const float rowmax = red[0];
    __syncthreads();

    float sum = 0.f;
    for (int i = tid; i < n4; i += 256) {
        float4 v = buf4[i];
        v.x = __expf(SCALE * (v.x - rowmax));
        v.y = __expf(SCALE * (v.y - rowmax));
        v.z = __expf(SCALE * (v.z - rowmax));
        v.w = __expf(SCALE * (v.w - rowmax));
        buf4[i] = v;
        sum += (v.x + v.y) + (v.z + v.w);
    }
    for (int i = n4 * 4 + tid; i < len; i += 256) {
        float e = __expf(SCALE * (buf[i] - rowmax));
        buf[i] = e; sum += e;
    }
    red[tid] = sum; __syncthreads();
    for (int o = 128; o > 0; o >>= 1) {
        if (tid < o) red[tid] += red[tid + o];
        __syncthreads();
    }
    const float rinv = 1.f / red[0];
    for (int i = tid; i < n4; i += 256) {
        float4 v = buf4[i];
        hf a = __float2half_rn(v.x * rinv), b = __float2half_rn(v.y * rinv);
        hf c = __float2half_rn(v.z * rinv), d = __float2half_rn(v.w * rinv);
        uint2 o2;
        o2.x = ((uint32_t)__half_as_ushort(b) << 16) | __half_as_ushort(a);
        o2.y = ((uint32_t)__half_as_ushort(d) << 16) | __half_as_ushort(c);
        *(uint2*)(ph + i * 4) = o2;
    }
    for (int i = n4 * 4 + tid; i < len; i += 256)
        ph[i] = __float2half_rn(buf[i] * rinv);
    const hf z = __float2half(0.f);
    for (int i = len + tid; i < pad; i += 256) ph[i] = z;
}

// ============================================================================
extern "C" void kernel_launch(void* const* d_in, const int* in_sizes, int n_in,
                              void* d_out, int out_size)
{
    (void)in_sizes; (void)n_in; (void)out_size;
    const float* h      = (const float*)d_in[0];
    const float* cosb   = (const float*)d_in[1];
    const float* sinb   = (const float*)d_in[2];
    const float* w_q_a  = (const float*)d_in[3];
    const float* gq     = (const float*)d_in[4];
    const float* w_q_b  = (const float*)d_in[5];
    const float* w_kv_a = (const float*)d_in[6];
    const float* gkv    = (const float*)d_in[7];
    const float* w_uk   = (const float*)d_in[8];
    const float* w_uv   = (const float*)d_in[9];
    const float* w_o    = (const float*)d_in[10];
    float* out = (float*)d_out;

    float *qakv_f, *sc;
    hf *hh, *hl, *wcomb_h, *wqb_h, *wo_h, *wukt_h, *wuvt_h;
    hf *qa_h, *qa_l, *q_h, *q_l, *keff_h, *kvct_h, *qeff_h, *qeff_l;
    hf *p_h, *ctxl_h, *ctxl_l, *ctx_h, *ctx_l;
    cudaGetSymbolAddress((void**)&qakv_f, g_qakv_f);
    cudaGetSymbolAddress((void**)&sc,     g_scores);
    cudaGetSymbolAddress((void**)&hh,     g_hh);     cudaGetSymbolAddress((void**)&hl,     g_hl);
    cudaGetSymbolAddress((void**)&wcomb_h, g_wcomb_h);
    cudaGetSymbolAddress((void**)&wqb_h,  g_wqb_h);
    cudaGetSymbolAddress((void**)&wo_h,   g_wo_h);
    cudaGetSymbolAddress((void**)&wukt_h, g_wukt_h);
    cudaGetSymbolAddress((void**)&wuvt_h, g_wuvt_h);
    cudaGetSymbolAddress((void**)&qa_h,   g_qa_h);   cudaGetSymbolAddress((void**)&qa_l,   g_qa_l);
    cudaGetSymbolAddress((void**)&q_h,    g_q_h);    cudaGetSymbolAddress((void**)&q_l,    g_q_l);
    cudaGetSymbolAddress((void**)&keff_h, g_keff_h);
    cudaGetSymbolAddress((void**)&kvct_h, g_kvct_h);
    cudaGetSymbolAddress((void**)&qeff_h, g_qeff_h); cudaGetSymbolAddress((void**)&qeff_l, g_qeff_l);
    cudaGetSymbolAddress((void**)&p_h,    g_p_h);
    cudaGetSymbolAddress((void**)&ctxl_h, g_ctxl_h); cudaGetSymbolAddress((void**)&ctxl_l, g_ctxl_l);
    cudaGetSymbolAddress((void**)&ctx_h,  g_ctx_h);  cudaGetSymbolAddress((void**)&ctx_l,  g_ctx_l);

    cudaFuncSetAttribute(hgemm<0,0,0,2>, cudaFuncAttributeMaxDynamicSharedMemorySize, GSMEM2);
    cudaFuncSetAttribute(hgemm<0,0,1,2>, cudaFuncAttributeMaxDynamicSharedMemorySize, GSMEM2);
    cudaFuncSetAttribute(hgemm<1,0,0,2>, cudaFuncAttributeMaxDynamicSharedMemorySize, GSMEM2);
    cudaFuncSetAttribute(hgemm<0,1,1,1>, cudaFuncAttributeMaxDynamicSharedMemorySize, GSMEM1);
    cudaFuncSetAttribute(hgemm<0,0,0,1>, cudaFuncAttributeMaxDynamicSharedMemorySize, GSMEM1);

    // --- operand conversions ---
    {
        long long n = (long long)SS * DD;
        cvt_hilo_k<<<(unsigned)((n/4 + 255)/256), 256>>>(h, hh, hl, n);
    }
    {   // fused: w_q_a -> wcomb[0:1536], w_kv_a -> wcomb[1536:2112], w_q_b, w_o
        long long n0 = (long long)QLORA * DD;
        long long n1 = (long long)KEFF * DD;
        long long n2 = (long long)HH * QKH * QLORA;
        long long n3 = (long long)DD * HH * VH;
        int c0 = (int)((n0/4 + 255)/256), c1 = (int)((n1/4 + 255)/256);
        int c2 = (int)((n2/4 + 255)/256), c3 = (int)((n3/4 + 255)/256);
        cvt_hi_multi<<<(unsigned)(c0 + c1 + c2 + c3), 256>>>(
            w_q_a,  wcomb_h,               n0,
            w_kv_a, wcomb_h + n0,          n1,
            w_q_b,  wqb_h,                 n2,
            w_o,    wo_h,                  n3,
            c0, c0 + c1, c0 + c1 + c2);
    }
    transcvt_hi_k<<<dim3(KVLORA/32, NOPEW/32, HH), 256>>>(
        w_uk, wukt_h, KVLORA, NOPEW,
        (long long)NOPEW*KVLORA, (long long)KVLORA*NOPEW);
    transcvt_hi_k<<<dim3(VH/32, KVLORA/32, HH), 256>>>(
        w_uv, wuvt_h, VH, KVLORA,
        (long long)KVLORA*VH, (long long)VH*KVLORA);

    // 1) [q_a | kv] = h @ [w_q_a | w_kv_a]^T -> fp32 combined  (2-term, 272 CTAs)
    hgemm<0,0,0,2><<<dim3((NCOMB + 127)/128, SS/128, 1), 256, GSMEM2>>>(
        hh, hl, wcomb_h, qakv_f, nullptr, nullptr,
        SS, NCOMB, DD, DD, DD, NCOMB, 0, 0, 0);
    // 2) rmsnorm(q_a cols 0:1536) -> hilo
    rmsnorm_hilo<<<SS, 256>>>(qakv_f, gq, qa_h, qa_l, QLORA, NCOMB);
    // 3) q = q_a @ w_q_b^T -> hilo                      (2-term)
    hgemm<0,0,1,2><<<dim3((HH*QKH)/128, SS/128, 1), 256, GSMEM2>>>(
        qa_h, qa_l, wqb_h, nullptr, q_h, q_l,
        SS, HH*QKH, QLORA, QLORA, QLORA, HH*QKH, 0, 0, 0);
    // 5) kv post (cols 1536:2112): rmsnorm + rope -> keff hi
    kv_post<<<SS, 256>>>(qakv_f, NCOMB, QLORA, gkv, cosb, sinb, keff_h);
    // 5b) kv_c transpose (cols 1536:2048 of combined) -> kvct [512][2048] hi
    transcvt_hi_k<<<dim3(KVLORA/32, SS/32, 1), 256>>>(
        qakv_f + QLORA, kvct_h, NCOMB, SS, 0, 0);
    // 6) q_latent -> qeff[:, 0:512] hilo                (2-term)
    hgemm<0,0,1,2><<<dim3(KVLORA/128, SS/128, HH), 256, GSMEM2>>>(
        q_h, q_l, wukt_h, nullptr, qeff_h, qeff_l,
        SS, KVLORA, NOPEW, HH*QKH, NOPEW, KEFF,
        (long long)QKH, (long long)KVLORA*NOPEW, (long long)SS*KEFF);
    // 7) q rope -> qeff[:, 512:576] hilo
    {
        long long total = (long long)SS * HH * 32;
        q_rope<<<(unsigned)((total + 255) / 256), 256>>>(q_h, q_l, qeff_h, qeff_l, cosb, sinb);
    }
    // 8) scores = qeff @ keff^T -> fp32  (2-term, triangle grid)
    {
        const int NT = SS / 128;
        const int NTRI = NT * (NT + 1) / 2;   // 136
        hgemm<1,0,0,2><<<dim3(NTRI, 1, HH), 256, GSMEM2>>>(
            qeff_h, qeff_l, keff_h, sc, nullptr, nullptr,
            SS, SS, KEFF, KEFF, KEFF, SS,
            (long long)SS*KEFF, 0, (long long)SS*SS);
    }
    // 9) causal softmax (vectorized) -> P hi only (+zero pad)
    softmax_causal<<<dim3(SS, HH), 256>>>(sc, p_h);
    // 10) ctx_latent = P @ kvct^T (K limited) -> hilo   (1-term)
    hgemm<0,1,1,1><<<dim3(KVLORA/128, SS/128, HH), 256, GSMEM1>>>(
        p_h, nullptr, kvct_h, nullptr, ctxl_h, ctxl_l,
        SS, KVLORA, SS, SS, SS, KVLORA,
        (long long)SS*SS, 0, (long long)SS*KVLORA);
    // 11) ctx = ctxl @ wuvt^T -> hilo                   (2-term)
    hgemm<0,0,1,2><<<dim3(1, SS/128, HH), 256, GSMEM2>>>(
        ctxl_h, ctxl_l, wuvt_h, nullptr, ctx_h, ctx_l,
        SS, VH, KVLORA, KVLORA, KVLORA, HH*VH,
        (long long)SS*KVLORA, (long long)VH*KVLORA, (long long)VH);
    // 12) out = ctx @ w_o^T -> fp32                     (1-term)
    hgemm<0,0,0,1><<<dim3(DD/128, SS/128, 1), 256, GSMEM1>>>(
        ctx_h, nullptr, wo_h, out, nullptr, nullptr,
        SS, DD, HH*VH, HH*VH, HH*VH, DD, 0, 0, 0);
}

// round 11
// speedup vs baseline: 5.3534x; 1.0172x over previous
#include <cuda_runtime.h>
#include <cuda_fp16.h>
#include <stdint.h>
#include <math.h>

// ---------------- problem constants ----------------
#define SS 2048
#define DD 4096
#define HH 32
#define QLORA 1536
#define KVLORA 512
#define ROPEW 64
#define NOPEW 128
#define QKH 192
#define VH 128
#define KEFF 576
#define NCOMB (QLORA + KEFF)   // 2112
#define EPSV 1e-6f
#define SCALE 0.07216878364870322f   // 1/sqrt(192)

typedef __half hf;

// ---------------- scratch ----------------
__device__ float g_qakv_f[(size_t)SS * NCOMB];
__device__ float g_scores[(size_t)HH * SS * SS];
__device__ hf g_hh[(size_t)SS * DD],            g_hl[(size_t)SS * DD];
__device__ hf g_wcomb_h[(size_t)NCOMB * DD];
__device__ hf g_wqb_h[(size_t)HH*QKH * QLORA];
__device__ hf g_wo_h[(size_t)DD * HH*VH];
__device__ hf g_wukt_h[(size_t)HH*KVLORA*NOPEW];
__device__ hf g_wuvt_h[(size_t)HH*VH*KVLORA];
__device__ hf g_qa_h[(size_t)SS * QLORA],       g_qa_l[(size_t)SS * QLORA];
__device__ hf g_q_h[(size_t)SS * HH*QKH],       g_q_l[(size_t)SS * HH*QKH];
__device__ hf g_keff_h[(size_t)SS * KEFF];
__device__ hf g_kvct_h[(size_t)KVLORA * SS];
__device__ hf g_qeff_h[(size_t)HH*SS*KEFF],     g_qeff_l[(size_t)HH*SS*KEFF];
__device__ hf g_p_h[(size_t)HH*SS*SS];
__device__ hf g_ctxl_h[(size_t)HH*SS*KVLORA],   g_ctxl_l[(size_t)HH*SS*KVLORA];
__device__ hf g_ctx_h[(size_t)SS * HH*VH],      g_ctx_l[(size_t)SS * HH*VH];

// ---------------- helpers ----------------
__device__ __forceinline__ uint32_t smem_u32(const void* p) {
    uint32_t a;
    asm("{ .reg .u64 t; cvta.to.shared.u64 t, %1; cvt.u32.u64 %0, t; }" : "=r"(a) : "l"(p));
    return a;
}

__device__ __forceinline__ void hilo1(float v, hf& h, hf& l) {
    h = __float2half_rn(v);
    l = __float2half_rn(v - __half2float(h));
}
__device__ __forceinline__ void cvt_hilo4(float4 v, uint2& hi, uint2& lo) {
    hf h0, h1, h2, h3, l0, l1, l2, l3;
    hilo1(v.x, h0, l0); hilo1(v.y, h1, l1); hilo1(v.z, h2, l2); hilo1(v.w, h3, l3);
    hi.x = ((uint32_t)__half_as_ushort(h1) << 16) | __half_as_ushort(h0);
    hi.y = ((uint32_t)__half_as_ushort(h3) << 16) | __half_as_ushort(h2);
    lo.x = ((uint32_t)__half_as_ushort(l1) << 16) | __half_as_ushort(l0);
    lo.y = ((uint32_t)__half_as_ushort(l3) << 16) | __half_as_ushort(l2);
}
__device__ __forceinline__ void hilo2pack(float a, float b, uint32_t& h, uint32_t& l) {
    hf ha, hb2, la, lb;
    hilo1(a, ha, la); hilo1(b, hb2, lb);
    h = ((uint32_t)__half_as_ushort(hb2) << 16) | __half_as_ushort(ha);
    l = ((uint32_t)__half_as_ushort(lb) << 16) | __half_as_ushort(la);
}

__device__ __forceinline__ void mma_f16(float* c, const uint32_t* a, const uint32_t* b) {
    asm volatile(
        "mma.sync.aligned.m16n8k16.row.col.f32.f16.f16.f32 "
        "{%0,%1,%2,%3}, {%4,%5,%6,%7}, {%8,%9}, {%0,%1,%2,%3};"
        : "+f"(c[0]), "+f"(c[1]), "+f"(c[2]), "+f"(c[3])
        : "r"(a[0]), "r"(a[1]), "r"(a[2]), "r"(a[3]), "r"(b[0]), "r"(b[1]));
}

#define LDMX4(r0, r1, r2, r3, addr) \
    asm volatile("ldmatrix.sync.aligned.m8n8.x4.shared.b16 {%0,%1,%2,%3}, [%4];" \
        : "=r"(r0), "=r"(r1), "=r"(r2), "=r"(r3) : "r"(addr))

#define CPA16(dst, src, sz) \
    asm volatile("cp.async.cg.shared.global [%0], [%1], 16, %2;" \
        :: "r"(dst), "l"(src), "r"(sz))
#define CPA_COMMIT()  asm volatile("cp.async.commit_group;" ::: "memory")

// BK=64 chunks; rows of 72 hf (144B) -> ldmatrix banks {4i..4i+3}, conflict-free
#define BK   64
#define LDT  72
#define ARR_B   (128 * LDT * 2)      // 18432
#define GSMEM_U (6 * ARR_B)          // 110592 (2-term: 2st x 3arr; 1-term: 3st x 2arr)

// ============================================================================
// NT GEMM: C = A * B^T. K-major fp16 operands. BK=64 chunks, single barrier.
// TERMS==2: Ah*Bh + Al*Bh  (2 stages)   TERMS==1: Ah*Bh  (3 stages)
// TRI: compacted lower-triangle grid.x.  CKEND: K limited to (bm+1)*128.
// Requires K % 64 == 0; 1-term call sites have nch >= 2.
// ============================================================================
template<int TRI, int CKEND, int OUT_HILO, int TERMS>
__global__ void __launch_bounds__(256, 2)
hgemm(const hf* __restrict__ Ah, const hf* __restrict__ Al,
      const hf* __restrict__ Bh,
      float* __restrict__ C, hf* __restrict__ Ch, hf* __restrict__ Cl,
      int M, int N, int K, int lda, int ldb, int ldc,
      long long sA, long long sB, long long sC)
{
    constexpr int NARR = TERMS + 1;
    constexpr int CHUNK_B = NARR * ARR_B;
    constexpr int BARR = (TERMS == 2) ? 2 : 1;
    constexpr int S = (TERMS == 2) ? 2 : 3;      // pipeline stages

    int bm, bn;
    if (TRI) {
        int bi = blockIdx.x;
        bm = (int)((sqrtf(8.f * (float)bi + 1.f) - 1.f) * 0.5f);
        while ((bm + 1) * (bm + 2) / 2 <= bi) bm++;
        while (bm * (bm + 1) / 2 > bi) bm--;
        bn = bi - bm * (bm + 1) / 2;
        if (bn > bm) return;
    } else {
        bm = blockIdx.y; bn = blockIdx.x;
    }
    extern __shared__ char smem[];
    const uint32_t sbase = smem_u32(smem);

    const int tid = threadIdx.x, lane = tid & 31, wid = tid >> 5;
    const int wm = wid & 1, wn = wid >> 1;

    Ah += (long long)blockIdx.z * sA;
    if (TERMS == 2) Al += (long long)blockIdx.z * sA;
    Bh += (long long)blockIdx.z * sB;

    const int Kend = CKEND ? min(K, (bm + 1) * 128) : K;
    const int nch = Kend / BK;

    // ---- cp.async: 4 passes of 32 rows; 16B per thread per pass per array ----
    const int ch = tid & 7;            // 16B chunk within 128B row payload
    const int rr = tid >> 3;           // 0..31
    const int ar0 = bm * 128 + rr;
    const int br0 = bn * 128 + rr;
    const hf* pAh = Ah + (long long)ar0 * lda + ch * 8;
    const hf* pAl = (TERMS == 2) ? Al + (long long)ar0 * lda + ch * 8 : nullptr;
    const uint32_t d0 = (uint32_t)(rr * (LDT * 2) + ch * 16);

    auto issue = [&](int slot, int k0) {
        uint32_t st = sbase + slot * CHUNK_B;
        #pragma unroll
        for (int p = 0; p < 4; p++) {
            uint32_t dd = d0 + p * (32 * LDT * 2);
            long long ro = (long long)(p * 32) * lda + k0;
            CPA16(st + 0 * ARR_B + dd, pAh + ro, 16u);
            if (TERMS == 2)
                CPA16(st + 1 * ARR_B + dd, pAl + ro, 16u);
            int brow = br0 + p * 32;
            uint32_t sz = (brow < N) ? 16u : 0u;
            const hf* pb = Bh + (long long)min(brow, N - 1) * ldb + ch * 8 + k0;
            CPA16(st + BARR * ARR_B + dd, pb, sz);
        }
    };

    // ---- ldmatrix lane offsets ----
    const int arow_l = wm * 64 + ((lane >> 3) & 1) * 8 + (lane & 7);
    const int acol_l = (lane >> 4) * 8;
    const uint32_t aoff = (uint32_t)(arow_l * LDT + acol_l) * 2;
    const int brow_l = wn * 32 + ((lane >> 4) & 1) * 8 + (lane & 7);
    const int bcol_l = ((lane >> 3) & 1) * 8;
    const uint32_t boff = (uint32_t)(brow_l * LDT + bcol_l) * 2;
    const uint32_t MISTR = 16 * LDT * 2;   // 2304

    float acc[4][4][4];
    #pragma unroll
    for (int a = 0; a < 4; a++)
        #pragma unroll
        for (int b = 0; b < 4; b++)
            #pragma unroll
            for (int q = 0; q < 4; q++) acc[a][b][q] = 0.f;

    issue(0, 0); CPA_COMMIT();
    if (S == 3) {
        if (nch > 1) issue(1, BK);
        CPA_COMMIT();
    }

    for (int c = 0; c < nch; c++) {
        if (S == 2) asm volatile("cp.async.wait_group 0;" ::: "memory");
        else        asm volatile("cp.async.wait_group 1;" ::: "memory");
        __syncthreads();
        const int cn = c + S - 1;
        if (cn < nch) issue(cn % S, cn * BK);
        CPA_COMMIT();
        const uint32_t st = sbase + (c % S) * CHUNK_B;
        #pragma unroll
        for (int ks = 0; ks < 4; ks++) {
            const uint32_t kof = ks * 32;
            uint32_t ah[4][4], al[4][4], bh[4][2];
            #pragma unroll
            for (int mi = 0; mi < 4; mi++) {
                LDMX4(ah[mi][0], ah[mi][1], ah[mi][2], ah[mi][3],
                      st + 0 * ARR_B + aoff + mi * MISTR + kof);
                if (TERMS == 2)
                    LDMX4(al[mi][0], al[mi][1], al[mi][2], al[mi][3],
                          st + 1 * ARR_B + aoff + mi * MISTR + kof);
            }
            #pragma unroll
            for (int p = 0; p < 2; p++)
                LDMX4(bh[2*p][0], bh[2*p][1], bh[2*p+1][0], bh[2*p+1][1],
                      st + BARR * ARR_B + boff + p * MISTR + kof);
            #pragma unroll
            for (int mi = 0; mi < 4; mi++)
                #pragma unroll
                for (int ni = 0; ni < 4; ni++) {
                    mma_f16(acc[mi][ni], ah[mi], bh[ni]);
                    if (TERMS == 2) mma_f16(acc[mi][ni], al[mi], bh[ni]);
                }
        }
    }

    const int qr = lane >> 2, qc = lane & 3;
    if (OUT_HILO) {
        hf* chp = Ch + (long long)blockIdx.z * sC;
        hf* clp = Cl + (long long)blockIdx.z * sC;
        #pragma unroll
        for (int mi = 0; mi < 4; mi++)
            #pragma unroll
            for (int ni = 0; ni < 4; ni++) {
                int r = bm * 128 + wm * 64 + mi * 16 + qr;
                int cc = bn * 128 + wn * 32 + ni * 8 + qc * 2;
                if (cc < N) {
                    uint32_t h0, l0, h1, l1;
                    hilo2pack(acc[mi][ni][0], acc[mi][ni][1], h0, l0);
                    hilo2pack(acc[mi][ni][2], acc[mi][ni][3], h1, l1);
                    *(uint32_t*)(chp + (long long)r * ldc + cc) = h0;
                    *(uint32_t*)(clp + (long long)r * ldc + cc) = l0;
                    *(uint32_t*)(chp + (long long)(r + 8) * ldc + cc) = h1;
                    *(uint32_t*)(clp + (long long)(r + 8) * ldc + cc) = l1;
                }
            }
    } else {
        float* cp = C + (long long)blockIdx.z * sC;
        #pragma unroll
        for (int mi = 0; mi < 4; mi++)
            #pragma unroll
            for (int ni = 0; ni < 4; ni++) {
                int r = bm * 128 + wm * 64 + mi * 16 + qr;
                int cc = bn * 128 + wn * 32 + ni * 8 + qc * 2;
                if (cc < N) {
                    *(float2*)(cp + (long long)r * ldc + cc) =
                        make_float2(acc[mi][ni][0], acc[mi][ni][1]);
                    *(float2*)(cp + (long long)(r + 8) * ldc + cc) =
                        make_float2(acc[mi][ni][2], acc[mi][ni][3]);
                }
            }
    }
}

// ============================================================================
// conversion / elementwise kernels (unchanged from round 10)
// ============================================================================
__global__ void cvt_hilo_k(const float* __restrict__ in, hf* __restrict__ oh,
                           hf* __restrict__ ol, long long n)
{
    long long i = ((long long)blockIdx.x * 256 + threadIdx.x) * 4;
    if (i >= n) return;
    float4 v = *(const float4*)(in + i);
    uint2 h, l; cvt_hilo4(v, h, l);
    *(uint2*)(oh + i) = h;
    *(uint2*)(ol + i) = l;
}

__global__ void cvt_hi_multi(const float* __restrict__ s0, hf* __restrict__ d0, long long n0,
                             const float* __restrict__ s1, hf* __restrict__ d1, long long n1,
                             const float* __restrict__ s2, hf* __restrict__ d2, long long n2,
                             const float* __restrict__ s3, hf* __restrict__ d3, long long n3,
                             int b1, int b2, int b3)
{
    int b = blockIdx.x;
    const float* s; hf* d; long long n; int lb;
    if (b < b1)      { s = s0; d = d0; n = n0; lb = b; }
    else if (b < b2) { s = s1; d = d1; n = n1; lb = b - b1; }
    else if (b < b3) { s = s2; d = d2; n = n2; lb = b - b2; }
    else             { s = s3; d = d3; n = n3; lb = b - b3; }
    long long i = ((long long)lb * 256 + threadIdx.x) * 4;
    if (i >= n) return;
    float4 v = *(const float4*)(s + i);
    uint2 h;
    hf h0 = __float2half_rn(v.x), h1 = __float2half_rn(v.y);
    hf h2 = __float2half_rn(v.z), h3 = __float2half_rn(v.w);
    h.x = ((uint32_t)__half_as_ushort(h1) << 16) | __half_as_ushort(h0);
    h.y = ((uint32_t)__half_as_ushort(h3) << 16) | __half_as_ushort(h2);
    *(uint2*)(d + i) = h;
}

__global__ void transcvt_hi_k(const float* __restrict__ in, hf* __restrict__ oh,
                              int ld_in, int ld_out, long long sIn, long long sOut)
{
    __shared__ float tile[32][33];
    const float* ip = in + (long long)blockIdx.z * sIn;
    int r0 = blockIdx.y * 32, c0 = blockIdx.x * 32;
    int tx = threadIdx.x & 31, ty = threadIdx.x >> 5;
    #pragma unroll
    for (int it = 0; it < 4; it++) {
        int r = ty + it * 8;
        tile[r][tx] = ip[(long long)(r0 + r) * ld_in + c0 + tx];
    }
    __syncthreads();
    #pragma unroll
    for (int it = 0; it < 4; it++) {
        int cr = ty + it * 8;
        long long o = (long long)blockIdx.z * sOut + (long long)(c0 + cr) * ld_out + r0 + tx;
        oh[o] = __float2half_rn(tile[tx][cr]);
    }
}

__global__ void rmsnorm_hilo(const float* __restrict__ X, const float* __restrict__ g,
                             hf* __restrict__ oh, hf* __restrict__ ol, int n, int ldx)
{
    const float* x = X + (long long)blockIdx.x * ldx;
    hf* ph = oh + (long long)blockIdx.x * n;
    hf* pl = ol + (long long)blockIdx.x * n;
    __shared__ float red[256];
    const int tid = threadIdx.x;
    float s = 0.f;
    for (int i = tid; i < n; i += 256) { float v = x[i]; s += v * v; }
    red[tid] = s; __syncthreads();
    for (int o = 128; o > 0; o >>= 1) {
        if (tid < o) red[tid] += red[tid + o];
        __syncthreads();
    }
    float inv = rsqrtf(red[0] / (float)n + EPSV);
    for (int i = tid; i < n; i += 256) {
        hf hb, lb; hilo1(x[i] * inv * g[i], hb, lb);
        ph[i] = hb; pl[i] = lb;
    }
}

__global__ void kv_post(float* __restrict__ KV, int ld, int off,
                        const float* __restrict__ g,
                        const float* __restrict__ cosb, const float* __restrict__ sinb,
                        hf* __restrict__ oh)
{
    const int srow = blockIdx.x;
    float* x = KV + (long long)srow * ld + off;
    hf* ph = oh + (long long)srow * KEFF;
    __shared__ float red[256];
    const int tid = threadIdx.x;
    float s = 0.f;
    for (int i = tid; i < KVLORA; i += 256) { float v = x[i]; s += v * v; }
    red[tid] = s; __syncthreads();
    for (int o = 128; o > 0; o >>= 1) {
        if (tid < o) red[tid] += red[tid + o];
        __syncthreads();
    }
    float inv = rsqrtf(red[0] / (float)KVLORA + EPSV);
    for (int i = tid; i < KVLORA; i += 256) x[i] = x[i] * inv * g[i];
    if (tid < 32) {
        float x1 = x[KVLORA + tid];
        float x2 = x[KVLORA + 32 + tid];
        float c1 = cosb[srow * ROPEW + tid];
        float c2 = cosb[srow * ROPEW + 32 + tid];
        float s1 = sinb[srow * ROPEW + tid];
        float s2 = sinb[srow * ROPEW + 32 + tid];
        x[KVLORA + tid]      = x1 * c1 - x2 * s1;
        x[KVLORA + 32 + tid] = x2 * c2 + x1 * s2;
    }
    __syncthreads();
    for (int i = tid; i < KEFF; i += 256)
        ph[i] = __float2half_rn(x[i]);
}

__global__ void q_rope(const hf* __restrict__ Qh, const hf* __restrict__ Ql,
                       hf* __restrict__ Eh, hf* __restrict__ El,
                       const float* __restrict__ cosb, const float* __restrict__ sinb)
{
    long long idx = (long long)blockIdx.x * blockDim.x + threadIdx.x;
    const long long total = (long long)SS * HH * 32;
    if (idx >= total) return;
    int j  = (int)(idx & 31);
    long long sh = idx >> 5;
    int h = (int)(sh & (HH - 1));
    int s = (int)(sh >> 5);
    long long qb = ((long long)s * HH + h) * QKH + NOPEW;
    float x1 = __half2float(Qh[qb + j]) + __half2float(Ql[qb + j]);
    float x2 = __half2float(Qh[qb + j + 32]) + __half2float(Ql[qb + j + 32]);
    float c1 = cosb[s * ROPEW + j];
    float c2 = cosb[s * ROPEW + 32 + j];
    float s1 = sinb[s * ROPEW + j];
    float s2 = sinb[s * ROPEW + 32 + j];
    long long ob = ((long long)h * SS + s) * KEFF + KVLORA;
    hf hb, lb;
    hilo1(x1 * c1 - x2 * s1, hb, lb);   Eh[ob + j] = hb;      El[ob + j] = lb;
    hilo1(x2 * c2 + x1 * s2, hb, lb);   Eh[ob + j + 32] = hb; El[ob + j + 32] = lb;
}

__global__ void softmax_causal(const float* __restrict__ Sc, hf* __restrict__ Ph)
{
    __shared__ float4 buf4[SS / 4];
    __shared__ float red[256];
    float* buf = (float*)buf4;
    const int m = blockIdx.x;
    const int h = blockIdx.y;
    const float* row = Sc + ((long long)h * SS + m) * SS;
    hf* ph = Ph + ((long long)h * SS + m) * SS;
    const int len = m + 1;
    const int n4 = len >> 2;
    const int pad = ((m >> 7) + 1) << 7;
    const int tid = threadIdx.x;

    float mx = -3.4e38f;
    for (int i = tid; i < n4; i += 256) {
        float4 v = *(const float4*)(row + i * 4);
        buf4[i] = v;
        mx = fmaxf(fmaxf(mx, fmaxf(v.x, v.y)), fmaxf(v.z, v.w));
    }
    for (int i = n4 * 4 + tid; i < len; i += 256) {
        float v = row[i]; buf[i] = v; mx = fmaxf(mx, v);
    }
    red[tid] = mx; __syncthreads();
    for (int o = 128; o > 0; o >>= 1) {
        if (tid < o) red[tid] = fmaxf(red[tid], red[tid + o]);
        __syncthreads();
    }
    const float rowmax = red[0];
    __syncthreads();

    float sum = 0.f;
    for (int i = tid; i < n4; i += 256) {
        float4 v = buf4[i];
        v.x = __expf(SCALE * (v.x - rowmax));
        v.y = __expf(SCALE * (v.y - rowmax));
        v.z = __expf(SCALE * (v.z - rowmax));
        v.w = __expf(SCALE * (v.w - rowmax));
        buf4[i] = v;
        sum += (v.x + v.y) + (v.z + v.w);
    }
    for (int i = n4 * 4 + tid; i < len; i += 256) {
        float e = __expf(SCALE * (buf[i] - rowmax));
        buf[i] = e; sum += e;
    }
    red[tid] = sum; __syncthreads();
    for (int o = 128; o > 0; o >>= 1) {
        if (tid < o) red[tid] += red[tid + o];
        __syncthreads();
    }
    const float rinv = 1.f / red[0];
    for (int i = tid; i < n4; i += 256) {
        float4 v = buf4[i];
        hf a = __float2half_rn(v.x * rinv), b = __float2half_rn(v.y * rinv);
        hf c = __float2half_rn(v.z * rinv), d = __float2half_rn(v.w * rinv);
        uint2 o2;
        o2.x = ((uint32_t)__half_as_ushort(b) << 16) | __half_as_ushort(a);
        o2.y = ((uint32_t)__half_as_ushort(d) << 16) | __half_as_ushort(c);
        *(uint2*)(ph + i * 4) = o2;
    }
    for (int i = n4 * 4 + tid; i < len; i += 256)
        ph[i] = __float2half_rn(buf[i] * rinv);
    const hf z = __float2half(0.f);
    for (int i = len + tid; i < pad; i += 256) ph[i] = z;
}

// ============================================================================
extern "C" void kernel_launch(void* const* d_in, const int* in_sizes, int n_in,
                              void* d_out, int out_size)
{
    (void)in_sizes; (void)n_in; (void)out_size;
    const float* h      = (const float*)d_in[0];
    const float* cosb   = (const float*)d_in[1];
    const float* sinb   = (const float*)d_in[2];
    const float* w_q_a  = (const float*)d_in[3];
    const float* gq     = (const float*)d_in[4];
    const float* w_q_b  = (const float*)d_in[5];
    const float* w_kv_a = (const float*)d_in[6];
    const float* gkv    = (const float*)d_in[7];
    const float* w_uk   = (const float*)d_in[8];
    const float* w_uv   = (const float*)d_in[9];
    const float* w_o    = (const float*)d_in[10];
    float* out = (float*)d_out;

    float *qakv_f, *sc;
    hf *hh, *hl, *wcomb_h, *wqb_h, *wo_h, *wukt_h, *wuvt_h;
    hf *qa_h, *qa_l, *q_h, *q_l, *keff_h, *kvct_h, *qeff_h, *qeff_l;
    hf *p_h, *ctxl_h, *ctxl_l, *ctx_h, *ctx_l;
    cudaGetSymbolAddress((void**)&qakv_f, g_qakv_f);
    cudaGetSymbolAddress((void**)&sc,     g_scores);
    cudaGetSymbolAddress((void**)&hh,     g_hh);     cudaGetSymbolAddress((void**)&hl,     g_hl);
    cudaGetSymbolAddress((void**)&wcomb_h, g_wcomb_h);
    cudaGetSymbolAddress((void**)&wqb_h,  g_wqb_h);
    cudaGetSymbolAddress((void**)&wo_h,   g_wo_h);
    cudaGetSymbolAddress((void**)&wukt_h, g_wukt_h);
    cudaGetSymbolAddress((void**)&wuvt_h, g_wuvt_h);
    cudaGetSymbolAddress((void**)&qa_h,   g_qa_h);   cudaGetSymbolAddress((void**)&qa_l,   g_qa_l);
    cudaGetSymbolAddress((void**)&q_h,    g_q_h);    cudaGetSymbolAddress((void**)&q_l,    g_q_l);
    cudaGetSymbolAddress((void**)&keff_h, g_keff_h);
    cudaGetSymbolAddress((void**)&kvct_h, g_kvct_h);
    cudaGetSymbolAddress((void**)&qeff_h, g_qeff_h); cudaGetSymbolAddress((void**)&qeff_l, g_qeff_l);
    cudaGetSymbolAddress((void**)&p_h,    g_p_h);
    cudaGetSymbolAddress((void**)&ctxl_h, g_ctxl_h); cudaGetSymbolAddress((void**)&ctxl_l, g_ctxl_l);
    cudaGetSymbolAddress((void**)&ctx_h,  g_ctx_h);  cudaGetSymbolAddress((void**)&ctx_l,  g_ctx_l);

    cudaFuncSetAttribute(hgemm<0,0,0,2>, cudaFuncAttributeMaxDynamicSharedMemorySize, GSMEM_U);
    cudaFuncSetAttribute(hgemm<0,0,1,2>, cudaFuncAttributeMaxDynamicSharedMemorySize, GSMEM_U);
    cudaFuncSetAttribute(hgemm<1,0,0,2>, cudaFuncAttributeMaxDynamicSharedMemorySize, GSMEM_U);
    cudaFuncSetAttribute(hgemm<0,1,1,1>, cudaFuncAttributeMaxDynamicSharedMemorySize, GSMEM_U);
    cudaFuncSetAttribute(hgemm<0,0,0,1>, cudaFuncAttributeMaxDynamicSharedMemorySize, GSMEM_U);

    // --- operand conversions ---
    {
        long long n = (long long)SS * DD;
        cvt_hilo_k<<<(unsigned)((n/4 + 255)/256), 256>>>(h, hh, hl, n);
    }
    {
        long long n0 = (long long)QLORA * DD;
        long long n1 = (long long)KEFF * DD;
        long long n2 = (long long)HH * QKH * QLORA;
        long long n3 = (long long)DD * HH * VH;
        int c0 = (int)((n0/4 + 255)/256), c1 = (int)((n1/4 + 255)/256);
        int c2 = (int)((n2/4 + 255)/256), c3 = (int)((n3/4 + 255)/256);
        cvt_hi_multi<<<(unsigned)(c0 + c1 + c2 + c3), 256>>>(
            w_q_a,  wcomb_h,      n0,
            w_kv_a, wcomb_h + n0, n1,
            w_q_b,  wqb_h,        n2,
            w_o,    wo_h,         n3,
            c0, c0 + c1, c0 + c1 + c2);
    }
    transcvt_hi_k<<<dim3(KVLORA/32, NOPEW/32, HH), 256>>>(
        w_uk, wukt_h, KVLORA, NOPEW,
        (long long)NOPEW*KVLORA, (long long)KVLORA*NOPEW);
    transcvt_hi_k<<<dim3(VH/32, KVLORA/32, HH), 256>>>(
        w_uv, wuvt_h, VH, KVLORA,
        (long long)KVLORA*VH, (long long)VH*KVLORA);

    // 1) [q_a | kv] = h @ [w_q_a | w_kv_a]^T -> fp32 combined  (2-term)
    hgemm<0,0,0,2><<<dim3((NCOMB + 127)/128, SS/128, 1), 256, GSMEM_U>>>(
        hh, hl, wcomb_h, qakv_f, nullptr, nullptr,
        SS, NCOMB, DD, DD, DD, NCOMB, 0, 0, 0);
    // 2) rmsnorm(q_a cols) -> hilo
    rmsnorm_hilo<<<SS, 256>>>(qakv_f, gq, qa_h, qa_l, QLORA, NCOMB);
    // 3) q = q_a @ w_q_b^T -> hilo  (2-term)
    hgemm<0,0,1,2><<<dim3((HH*QKH)/128, SS/128, 1), 256, GSMEM_U>>>(
        qa_h, qa_l, wqb_h, nullptr, q_h, q_l,
        SS, HH*QKH, QLORA, QLORA, QLORA, HH*QKH, 0, 0, 0);
    // 5) kv post: rmsnorm + rope -> keff hi
    kv_post<<<SS, 256>>>(qakv_f, NCOMB, QLORA, gkv, cosb, sinb, keff_h);
    // 5b) kv_c transpose -> kvct hi
    transcvt_hi_k<<<dim3(KVLORA/32, SS/32, 1), 256>>>(
        qakv_f + QLORA, kvct_h, NCOMB, SS, 0, 0);
    // 6) q_latent -> qeff[:, 0:512] hilo  (2-term, K=128 -> 2 chunks)
    hgemm<0,0,1,2><<<dim3(KVLORA/128, SS/128, HH), 256, GSMEM_U>>>(
        q_h, q_l, wukt_h, nullptr, qeff_h, qeff_l,
        SS, KVLORA, NOPEW, HH*QKH, NOPEW, KEFF,
        (long long)QKH, (long long)KVLORA*NOPEW, (long long)SS*KEFF);
    // 7) q rope -> qeff[:, 512:576] hilo
    {
        long long total = (long long)SS * HH * 32;
        q_rope<<<(unsigned)((total + 255) / 256), 256>>>(q_h, q_l, qeff_h, qeff_l, cosb, sinb);
    }
    // 8) scores = qeff @ keff^T -> fp32  (2-term, triangle grid, K=576 -> 9 chunks)
    {
        const int NT = SS / 128;
        const int NTRI = NT * (NT + 1) / 2;   // 136
        hgemm<1,0,0,2><<<dim3(NTRI, 1, HH), 256, GSMEM_U>>>(
            qeff_h, qeff_l, keff_h, sc, nullptr, nullptr,
            SS, SS, KEFF, KEFF, KEFF, SS,
            (long long)SS*KEFF, 0, (long long)SS*SS);
    }
    // 9) causal softmax (vectorized) -> P hi only (+zero pad)
    softmax_causal<<<dim3(SS, HH), 256>>>(sc, p_h);
    // 10) ctx_latent = P @ kvct^T (K limited) -> hilo  (1-term)
    hgemm<0,1,1,1><<<dim3(KVLORA/128, SS/128, HH), 256, GSMEM_U>>>(
        p_h, nullptr, kvct_h, nullptr, ctxl_h, ctxl_l,
        SS, KVLORA, SS, SS, SS, KVLORA,
        (long long)SS*SS, 0, (long long)SS*KVLORA);
    // 11) ctx = ctxl @ wuvt^T -> hilo  (2-term)
    hgemm<0,0,1,2><<<dim3(1, SS/128, HH), 256, GSMEM_U>>>(
        ctxl_h, ctxl_l, wuvt_h, nullptr, ctx_h, ctx_l,
        SS, VH, KVLORA, KVLORA, KVLORA, HH*VH,
        (long long)SS*KVLORA, (long long)VH*KVLORA, (long long)VH);
    // 12) out = ctx @ w_o^T -> fp32  (1-term)
    hgemm<0,0,0,1><<<dim3(DD/128, SS/128, 1), 256, GSMEM_U>>>(
        ctx_h, nullptr, wo_h, out, nullptr, nullptr,
        SS, DD, HH*VH, HH*VH, HH*VH, DD, 0, 0, 0);
}

// round 13
// speedup vs baseline: 5.8754x; 1.0975x over previous
#include <cuda_runtime.h>
#include <cuda_fp16.h>
#include <stdint.h>
#include <math.h>

// ---------------- problem constants ----------------
#define SS 2048
#define DD 4096
#define HH 32
#define QLORA 1536
#define KVLORA 512
#define ROPEW 64
#define NOPEW 128
#define QKH 192
#define VH 128
#define KEFF 576
#define NCOMB (QLORA + KEFF)   // 2112
#define EPSV 1e-6f
#define SCALE 0.07216878364870322f   // 1/sqrt(192)

typedef __half hf;

// ---------------- scratch ----------------
__device__ float g_qakv_f[(size_t)SS * NCOMB];
__device__ float g_scores[(size_t)HH * SS * SS];
__device__ hf g_hh[(size_t)SS * DD],            g_hl[(size_t)SS * DD];
__device__ hf g_wcomb_h[(size_t)NCOMB * DD];
__device__ hf g_wqb_h[(size_t)HH*QKH * QLORA];
__device__ hf g_wo_h[(size_t)DD * HH*VH];
__device__ hf g_wukt_h[(size_t)HH*KVLORA*NOPEW];
__device__ hf g_wuvt_h[(size_t)HH*VH*KVLORA];
__device__ hf g_qa_h[(size_t)SS * QLORA],       g_qa_l[(size_t)SS * QLORA];
__device__ hf g_q_h[(size_t)SS * HH*QKH],       g_q_l[(size_t)SS * HH*QKH];
__device__ hf g_keff_h[(size_t)SS * KEFF];
__device__ hf g_kvct_h[(size_t)KVLORA * SS];
__device__ hf g_qeff_h[(size_t)HH*SS*KEFF];        // hi only
__device__ hf g_p_h[(size_t)HH*SS*SS];
__device__ hf g_ctxl_h[(size_t)HH*SS*KVLORA],   g_ctxl_l[(size_t)HH*SS*KVLORA];
__device__ hf g_ctx_h[(size_t)SS * HH*VH],      g_ctx_l[(size_t)SS * HH*VH];

// ---------------- helpers ----------------
__device__ __forceinline__ uint32_t smem_u32(const void* p) {
    uint32_t a;
    asm("{ .reg .u64 t; cvta.to.shared.u64 t, %1; cvt.u32.u64 %0, t; }" : "=r"(a) : "l"(p));
    return a;
}

__device__ __forceinline__ void hilo1(float v, hf& h, hf& l) {
    h = __float2half_rn(v);
    l = __float2half_rn(v - __half2float(h));
}
__device__ __forceinline__ void cvt_hilo4(float4 v, uint2& hi, uint2& lo) {
    hf h0, h1, h2, h3, l0, l1, l2, l3;
    hilo1(v.x, h0, l0); hilo1(v.y, h1, l1); hilo1(v.z, h2, l2); hilo1(v.w, h3, l3);
    hi.x = ((uint32_t)__half_as_ushort(h1) << 16) | __half_as_ushort(h0);
    hi.y = ((uint32_t)__half_as_ushort(h3) << 16) | __half_as_ushort(h2);
    lo.x = ((uint32_t)__half_as_ushort(l1) << 16) | __half_as_ushort(l0);
    lo.y = ((uint32_t)__half_as_ushort(l3) << 16) | __half_as_ushort(l2);
}
__device__ __forceinline__ void hilo2pack(float a, float b, uint32_t& h, uint32_t& l) {
    hf ha, hb2, la, lb;
    hilo1(a, ha, la); hilo1(b, hb2, lb);
    h = ((uint32_t)__half_as_ushort(hb2) << 16) | __half_as_ushort(ha);
    l = ((uint32_t)__half_as_ushort(lb) << 16) | __half_as_ushort(la);
}
__device__ __forceinline__ uint32_t hi2pack(float a, float b) {
    hf ha = __float2half_rn(a), hb = __float2half_rn(b);
    return ((uint32_t)__half_as_ushort(hb) << 16) | __half_as_ushort(ha);
}

__device__ __forceinline__ void mma_f16(float* c, const uint32_t* a, const uint32_t* b) {
    asm volatile(
        "mma.sync.aligned.m16n8k16.row.col.f32.f16.f16.f32 "
        "{%0,%1,%2,%3}, {%4,%5,%6,%7}, {%8,%9}, {%0,%1,%2,%3};"
        : "+f"(c[0]), "+f"(c[1]), "+f"(c[2]), "+f"(c[3])
        : "r"(a[0]), "r"(a[1]), "r"(a[2]), "r"(a[3]), "r"(b[0]), "r"(b[1]));
}

#define LDMX4(r0, r1, r2, r3, addr) \
    asm volatile("ldmatrix.sync.aligned.m8n8.x4.shared.b16 {%0,%1,%2,%3}, [%4];" \
        : "=r"(r0), "=r"(r1), "=r"(r2), "=r"(r3) : "r"(addr))

#define CPA16(dst, src, sz) \
    asm volatile("cp.async.cg.shared.global [%0], [%1], 16, %2;" \
        :: "r"(dst), "l"(src), "r"(sz))
#define CPA_COMMIT()  asm volatile("cp.async.commit_group;" ::: "memory")

// BK=64 chunks; rows of 72 hf (144B) -> conflict-free ldmatrix
#define BK   64
#define LDT  72
#define ARR_B   (128 * LDT * 2)      // 18432
#define GSMEM_U (6 * ARR_B)          // 110592

// ============================================================================
// NT GEMM: C = A * B^T. K-major fp16 operands. BK=64 chunks, single barrier.
// TERMS==2: Ah*Bh + Al*Bh  (2 stages)   TERMS==1: Ah*Bh  (3 stages)
// OUT: 0 = fp32 C, 1 = fp16 hi/lo (Ch,Cl), 2 = fp16 hi only (Ch)
// TRI: compacted lower-triangle grid.x.  CKEND: K limited to (bm+1)*128.
// Requires K % 64 == 0.
// ============================================================================
template<int TRI, int CKEND, int OUT, int TERMS>
__global__ void __launch_bounds__(256, 2)
hgemm(const hf* __restrict__ Ah, const hf* __restrict__ Al,
      const hf* __restrict__ Bh,
      float* __restrict__ C, hf* __restrict__ Ch, hf* __restrict__ Cl,
      int M, int N, int K, int lda, int ldb, int ldc,
      long long sA, long long sB, long long sC)
{
    constexpr int NARR = TERMS + 1;
    constexpr int CHUNK_B = NARR * ARR_B;
    constexpr int BARR = (TERMS == 2) ? 2 : 1;
    constexpr int S = (TERMS == 2) ? 2 : 3;      // pipeline stages

    int bm, bn;
    if (TRI) {
        int bi = blockIdx.x;
        bm = (int)((sqrtf(8.f * (float)bi + 1.f) - 1.f) * 0.5f);
        while ((bm + 1) * (bm + 2) / 2 <= bi) bm++;
        while (bm * (bm + 1) / 2 > bi) bm--;
        bn = bi - bm * (bm + 1) / 2;
        if (bn > bm) return;
    } else {
        bm = blockIdx.y; bn = blockIdx.x;
    }
    extern __shared__ char smem[];
    const uint32_t sbase = smem_u32(smem);

    const int tid = threadIdx.x, lane = tid & 31, wid = tid >> 5;
    const int wm = wid & 1, wn = wid >> 1;

    Ah += (long long)blockIdx.z * sA;
    if (TERMS == 2) Al += (long long)blockIdx.z * sA;
    Bh += (long long)blockIdx.z * sB;

    const int Kend = CKEND ? min(K, (bm + 1) * 128) : K;
    const int nch = Kend / BK;

    const int ch = tid & 7;
    const int rr = tid >> 3;
    const int ar0 = bm * 128 + rr;
    const int br0 = bn * 128 + rr;
    const hf* pAh = Ah + (long long)ar0 * lda + ch * 8;
    const hf* pAl = (TERMS == 2) ? Al + (long long)ar0 * lda + ch * 8 : nullptr;
    const uint32_t d0 = (uint32_t)(rr * (LDT * 2) + ch * 16);

    auto issue = [&](int slot, int k0) {
        uint32_t st = sbase + slot * CHUNK_B;
        #pragma unroll
        for (int p = 0; p < 4; p++) {
            uint32_t dd = d0 + p * (32 * LDT * 2);
            long long ro = (long long)(p * 32) * lda + k0;
            CPA16(st + 0 * ARR_B + dd, pAh + ro, 16u);
            if (TERMS == 2)
                CPA16(st + 1 * ARR_B + dd, pAl + ro, 16u);
            int brow = br0 + p * 32;
            uint32_t sz = (brow < N) ? 16u : 0u;
            const hf* pb = Bh + (long long)min(brow, N - 1) * ldb + ch * 8 + k0;
            CPA16(st + BARR * ARR_B + dd, pb, sz);
        }
    };

    const int arow_l = wm * 64 + ((lane >> 3) & 1) * 8 + (lane & 7);
    const int acol_l = (lane >> 4) * 8;
    const uint32_t aoff = (uint32_t)(arow_l * LDT + acol_l) * 2;
    const int brow_l = wn * 32 + ((lane >> 4) & 1) * 8 + (lane & 7);
    const int bcol_l = ((lane >> 3) & 1) * 8;
    const uint32_t boff = (uint32_t)(brow_l * LDT + bcol_l) * 2;
    const uint32_t MISTR = 16 * LDT * 2;   // 2304

    float acc[4][4][4];
    #pragma unroll
    for (int a = 0; a < 4; a++)
        #pragma unroll
        for (int b = 0; b < 4; b++)
            #pragma unroll
            for (int q = 0; q < 4; q++) acc[a][b][q] = 0.f;

    issue(0, 0); CPA_COMMIT();
    if (S == 3) {
        if (nch > 1) issue(1, BK);
        CPA_COMMIT();
    }

    for (int c = 0; c < nch; c++) {
        if (S == 2) asm volatile("cp.async.wait_group 0;" ::: "memory");
        else        asm volatile("cp.async.wait_group 1;" ::: "memory");
        __syncthreads();
        const int cn = c + S - 1;
        if (cn < nch) issue(cn % S, cn * BK);
        CPA_COMMIT();
        const uint32_t st = sbase + (c % S) * CHUNK_B;
        #pragma unroll
        for (int ks = 0; ks < 4; ks++) {
            const uint32_t kof = ks * 32;
            uint32_t ah[4][4], al[4][4], bh[4][2];
            #pragma unroll
            for (int mi = 0; mi < 4; mi++) {
                LDMX4(ah[mi][0], ah[mi][1], ah[mi][2], ah[mi][3],
                      st + 0 * ARR_B + aoff + mi * MISTR + kof);
                if (TERMS == 2)
                    LDMX4(al[mi][0], al[mi][1], al[mi][2], al[mi][3],
                          st + 1 * ARR_B + aoff + mi * MISTR + kof);
            }
            #pragma unroll
            for (int p = 0; p < 2; p++)
                LDMX4(bh[2*p][0], bh[2*p][1], bh[2*p+1][0], bh[2*p+1][1],
                      st + BARR * ARR_B + boff + p * MISTR + kof);
            #pragma unroll
            for (int mi = 0; mi < 4; mi++)
                #pragma unroll
                for (int ni = 0; ni < 4; ni++) {
                    mma_f16(acc[mi][ni], ah[mi], bh[ni]);
                    if (TERMS == 2) mma_f16(acc[mi][ni], al[mi], bh[ni]);
                }
        }
    }

    const int qr = lane >> 2, qc = lane & 3;
    if (OUT == 1) {
        hf* chp = Ch + (long long)blockIdx.z * sC;
        hf* clp = Cl + (long long)blockIdx.z * sC;
        #pragma unroll
        for (int mi = 0; mi < 4; mi++)
            #pragma unroll
            for (int ni = 0; ni < 4; ni++) {
                int r = bm * 128 + wm * 64 + mi * 16 + qr;
                int cc = bn * 128 + wn * 32 + ni * 8 + qc * 2;
                if (cc < N) {
                    uint32_t h0, l0, h1, l1;
                    hilo2pack(acc[mi][ni][0], acc[mi][ni][1], h0, l0);
                    hilo2pack(acc[mi][ni][2], acc[mi][ni][3], h1, l1);
                    *(uint32_t*)(chp + (long long)r * ldc + cc) = h0;
                    *(uint32_t*)(clp + (long long)r * ldc + cc) = l0;
                    *(uint32_t*)(chp + (long long)(r + 8) * ldc + cc) = h1;
                    *(uint32_t*)(clp + (long long)(r + 8) * ldc + cc) = l1;
                }
            }
    } else if (OUT == 2) {
        hf* chp = Ch + (long long)blockIdx.z * sC;
        #pragma unroll
        for (int mi = 0; mi < 4; mi++)
            #pragma unroll
            for (int ni = 0; ni < 4; ni++) {
                int r = bm * 128 + wm * 64 + mi * 16 + qr;
                int cc = bn * 128 + wn * 32 + ni * 8 + qc * 2;
                if (cc < N) {
                    *(uint32_t*)(chp + (long long)r * ldc + cc) =
                        hi2pack(acc[mi][ni][0], acc[mi][ni][1]);
                    *(uint32_t*)(chp + (long long)(r + 8) * ldc + cc) =
                        hi2pack(acc[mi][ni][2], acc[mi][ni][3]);
                }
            }
    } else {
        float* cp = C + (long long)blockIdx.z * sC;
        #pragma unroll
        for (int mi = 0; mi < 4; mi++)
            #pragma unroll
            for (int ni = 0; ni < 4; ni++) {
                int r = bm * 128 + wm * 64 + mi * 16 + qr;
                int cc = bn * 128 + wn * 32 + ni * 8 + qc * 2;
                if (cc < N) {
                    *(float2*)(cp + (long long)r * ldc + cc) =
                        make_float2(acc[mi][ni][0], acc[mi][ni][1]);
                    *(float2*)(cp + (long long)(r + 8) * ldc + cc) =
                        make_float2(acc[mi][ni][2], acc[mi][ni][3]);
                }
            }
    }
}

// ============================================================================
// conversion / elementwise kernels
// ============================================================================
__global__ void cvt_hilo_k(const float* __restrict__ in, hf* __restrict__ oh,
                           hf* __restrict__ ol, long long n)
{
    long long i = ((long long)blockIdx.x * 256 + threadIdx.x) * 4;
    if (i >= n) return;
    float4 v = *(const float4*)(in + i);
    uint2 h, l; cvt_hilo4(v, h, l);
    *(uint2*)(oh + i) = h;
    *(uint2*)(ol + i) = l;
}

__global__ void cvt_hi_multi(const float* __restrict__ s0, hf* __restrict__ d0, long long n0,
                             const float* __restrict__ s1, hf* __restrict__ d1, long long n1,
                             const float* __restrict__ s2, hf* __restrict__ d2, long long n2,
                             const float* __restrict__ s3, hf* __restrict__ d3, long long n3,
                             int b1, int b2, int b3)
{
    int b = blockIdx.x;
    const float* s; hf* d; long long n; int lb;
    if (b < b1)      { s = s0; d = d0; n = n0; lb = b; }
    else if (b < b2) { s = s1; d = d1; n = n1; lb = b - b1; }
    else if (b < b3) { s = s2; d = d2; n = n2; lb = b - b2; }
    else             { s = s3; d = d3; n = n3; lb = b - b3; }
    long long i = ((long long)lb * 256 + threadIdx.x) * 4;
    if (i >= n) return;
    float4 v = *(const float4*)(s + i);
    uint2 h;
    hf h0 = __float2half_rn(v.x), h1 = __float2half_rn(v.y);
    hf h2 = __float2half_rn(v.z), h3 = __float2half_rn(v.w);
    h.x = ((uint32_t)__half_as_ushort(h1) << 16) | __half_as_ushort(h0);
    h.y = ((uint32_t)__half_as_ushort(h3) << 16) | __half_as_ushort(h2);
    *(uint2*)(d + i) = h;
}

__global__ void transcvt_hi_k(const float* __restrict__ in, hf* __restrict__ oh,
                              int ld_in, int ld_out, long long sIn, long long sOut)
{
    __shared__ float tile[32][33];
    const float* ip = in + (long long)blockIdx.z * sIn;
    int r0 = blockIdx.y * 32, c0 = blockIdx.x * 32;
    int tx = threadIdx.x & 31, ty = threadIdx.x >> 5;
    #pragma unroll
    for (int it = 0; it < 4; it++) {
        int r = ty + it * 8;
        tile[r][tx] = ip[(long long)(r0 + r) * ld_in + c0 + tx];
    }
    __syncthreads();
    #pragma unroll
    for (int it = 0; it < 4; it++) {
        int cr = ty + it * 8;
        long long o = (long long)blockIdx.z * sOut + (long long)(c0 + cr) * ld_out + r0 + tx;
        oh[o] = __float2half_rn(tile[tx][cr]);
    }
}

__global__ void rmsnorm_hilo(const float* __restrict__ X, const float* __restrict__ g,
                             hf* __restrict__ oh, hf* __restrict__ ol, int n, int ldx)
{
    const float* x = X + (long long)blockIdx.x * ldx;
    hf* ph = oh + (long long)blockIdx.x * n;
    hf* pl = ol + (long long)blockIdx.x * n;
    __shared__ float red[256];
    const int tid = threadIdx.x;
    float s = 0.f;
    for (int i = tid; i < n; i += 256) { float v = x[i]; s += v * v; }
    red[tid] = s; __syncthreads();
    for (int o = 128; o > 0; o >>= 1) {
        if (tid < o) red[tid] += red[tid + o];
        __syncthreads();
    }
    float inv = rsqrtf(red[0] / (float)n + EPSV);
    for (int i = tid; i < n; i += 256) {
        hf hb, lb; hilo1(x[i] * inv * g[i], hb, lb);
        ph[i] = hb; pl[i] = lb;
    }
}

__global__ void kv_post(float* __restrict__ KV, int ld, int off,
                        const float* __restrict__ g,
                        const float* __restrict__ cosb, const float* __restrict__ sinb,
                        hf* __restrict__ oh)
{
    const int srow = blockIdx.x;
    float* x = KV + (long long)srow * ld + off;
    hf* ph = oh + (long long)srow * KEFF;
    __shared__ float red[256];
    const int tid = threadIdx.x;
    float s = 0.f;
    for (int i = tid; i < KVLORA; i += 256) { float v = x[i]; s += v * v; }
    red[tid] = s; __syncthreads();
    for (int o = 128; o > 0; o >>= 1) {
        if (tid < o) red[tid] += red[tid + o];
        __syncthreads();
    }
    float inv = rsqrtf(red[0] / (float)KVLORA + EPSV);
    for (int i = tid; i < KVLORA; i += 256) x[i] = x[i] * inv * g[i];
    if (tid < 32) {
        float x1 = x[KVLORA + tid];
        float x2 = x[KVLORA + 32 + tid];
        float c1 = cosb[srow * ROPEW + tid];
        float c2 = cosb[srow * ROPEW + 32 + tid];
        float s1 = sinb[srow * ROPEW + tid];
        float s2 = sinb[srow * ROPEW + 32 + tid];
        x[KVLORA + tid]      = x1 * c1 - x2 * s1;
        x[KVLORA + 32 + tid] = x2 * c2 + x1 * s2;
    }
    __syncthreads();
    for (int i = tid; i < KEFF; i += 256)
        ph[i] = __float2half_rn(x[i]);
}

// q rope -> qeff hi only
__global__ void q_rope(const hf* __restrict__ Qh, const hf* __restrict__ Ql,
                       hf* __restrict__ Eh,
                       const float* __restrict__ cosb, const float* __restrict__ sinb)
{
    long long idx = (long long)blockIdx.x * blockDim.x + threadIdx.x;
    const long long total = (long long)SS * HH * 32;
    if (idx >= total) return;
    int j  = (int)(idx & 31);
    long long sh = idx >> 5;
    int h = (int)(sh & (HH - 1));
    int s = (int)(sh >> 5);
    long long qb = ((long long)s * HH + h) * QKH + NOPEW;
    float x1 = __half2float(Qh[qb + j]) + __half2float(Ql[qb + j]);
    float x2 = __half2float(Qh[qb + j + 32]) + __half2float(Ql[qb + j + 32]);
    float c1 = cosb[s * ROPEW + j];
    float c2 = cosb[s * ROPEW + 32 + j];
    float s1 = sinb[s * ROPEW + j];
    float s2 = sinb[s * ROPEW + 32 + j];
    long long ob = ((long long)h * SS + s) * KEFF + KVLORA;
    Eh[ob + j]      = __float2half_rn(x1 * c1 - x2 * s1);
    Eh[ob + j + 32] = __float2half_rn(x2 * c2 + x1 * s2);
}

__global__ void softmax_causal(const float* __restrict__ Sc, hf* __restrict__ Ph)
{
    __shared__ float4 buf4[SS / 4];
    __shared__ float red[256];
    float* buf = (float*)buf4;
    const int m = blockIdx.x;
    const int h = blockIdx.y;
    const float* row = Sc + ((long long)h * SS + m) * SS;
    hf* ph = Ph + ((long long)h * SS + m) * SS;
    const int len = m + 1;
    const int n4 = len >> 2;
    const int pad = ((m >> 7) + 1) << 7;
    const int tid = threadIdx.x;

    float mx = -3.4e38f;
    for (int i = tid; i < n4; i += 256) {
        float4 v = *(const float4*)(row + i * 4);
        buf4[i] = v;
        mx = fmaxf(fmaxf(mx, fmaxf(v.x, v.y)), fmaxf(v.z, v.w));
    }
    for (int i = n4 * 4 + tid; i < len; i += 256) {
        float v = row[i]; buf[i] = v; mx = fmaxf(mx, v);
    }
    red[tid] = mx; __syncthreads();
    for (int o = 128; o > 0; o >>= 1) {
        if (tid < o) red[tid] = fmaxf(red[tid], red[tid + o]);
        __syncthreads();
    }
    const float rowmax = red[0];
    __syncthreads();

    float sum = 0.f;
    for (int i = tid; i < n4; i += 256) {
        float4 v = buf4[i];
        v.x = __expf(SCALE * (v.x - rowmax));
        v.y = __expf(SCALE * (v.y - rowmax));
        v.z = __expf(SCALE * (v.z - rowmax));
        v.w = __expf(SCALE * (v.w - rowmax));
        buf4[i] = v;
        sum += (v.x + v.y) + (v.z + v.w);
    }
    for (int i = n4 * 4 + tid; i < len; i += 256) {
        float e = __expf(SCALE * (buf[i] - rowmax));
        buf[i] = e; sum += e;
    }
    red[tid] = sum; __syncthreads();
    for (int o = 128; o > 0; o >>= 1) {
        if (tid < o) red[tid] += red[tid + o];
        __syncthreads();
    }
    const float rinv = 1.f / red[0];
    for (int i = tid; i < n4; i += 256) {
        float4 v = buf4[i];
        hf a = __float2half_rn(v.x * rinv), b = __float2half_rn(v.y * rinv);
        hf c = __float2half_rn(v.z * rinv), d = __float2half_rn(v.w * rinv);
        uint2 o2;
        o2.x = ((uint32_t)__half_as_ushort(b) << 16) | __half_as_ushort(a);
        o2.y = ((uint32_t)__half_as_ushort(d) << 16) | __half_as_ushort(c);
        *(uint2*)(ph + i * 4) = o2;
    }
    for (int i = n4 * 4 + tid; i < len; i += 256)
        ph[i] = __float2half_rn(buf[i] * rinv);
    const hf z = __float2half(0.f);
    for (int i = len + tid; i < pad; i += 256) ph[i] = z;
}

// ============================================================================
extern "C" void kernel_launch(void* const* d_in, const int* in_sizes, int n_in,
                              void* d_out, int out_size)
{
    (void)in_sizes; (void)n_in; (void)out_size;
    const float* h      = (const float*)d_in[0];
    const float* cosb   = (const float*)d_in[1];
    const float* sinb   = (const float*)d_in[2];
    const float* w_q_a  = (const float*)d_in[3];
    const float* gq     = (const float*)d_in[4];
    const float* w_q_b  = (const float*)d_in[5];
    const float* w_kv_a = (const float*)d_in[6];
    const float* gkv    = (const float*)d_in[7];
    const float* w_uk   = (const float*)d_in[8];
    const float* w_uv   = (const float*)d_in[9];
    const float* w_o    = (const float*)d_in[10];
    float* out = (float*)d_out;

    float *qakv_f, *sc;
    hf *hh, *hl, *wcomb_h, *wqb_h, *wo_h, *wukt_h, *wuvt_h;
    hf *qa_h, *qa_l, *q_h, *q_l, *keff_h, *kvct_h, *qeff_h;
    hf *p_h, *ctxl_h, *ctxl_l, *ctx_h, *ctx_l;
    cudaGetSymbolAddress((void**)&qakv_f, g_qakv_f);
    cudaGetSymbolAddress((void**)&sc,     g_scores);
    cudaGetSymbolAddress((void**)&hh,     g_hh);     cudaGetSymbolAddress((void**)&hl,     g_hl);
    cudaGetSymbolAddress((void**)&wcomb_h, g_wcomb_h);
    cudaGetSymbolAddress((void**)&wqb_h,  g_wqb_h);
    cudaGetSymbolAddress((void**)&wo_h,   g_wo_h);
    cudaGetSymbolAddress((void**)&wukt_h, g_wukt_h);
    cudaGetSymbolAddress((void**)&wuvt_h, g_wuvt_h);
    cudaGetSymbolAddress((void**)&qa_h,   g_qa_h);   cudaGetSymbolAddress((void**)&qa_l,   g_qa_l);
    cudaGetSymbolAddress((void**)&q_h,    g_q_h);    cudaGetSymbolAddress((void**)&q_l,    g_q_l);
    cudaGetSymbolAddress((void**)&keff_h, g_keff_h);
    cudaGetSymbolAddress((void**)&kvct_h, g_kvct_h);
    cudaGetSymbolAddress((void**)&qeff_h, g_qeff_h);
    cudaGetSymbolAddress((void**)&p_h,    g_p_h);
    cudaGetSymbolAddress((void**)&ctxl_h, g_ctxl_h); cudaGetSymbolAddress((void**)&ctxl_l, g_ctxl_l);
    cudaGetSymbolAddress((void**)&ctx_h,  g_ctx_h);  cudaGetSymbolAddress((void**)&ctx_l,  g_ctx_l);

    cudaFuncSetAttribute(hgemm<0,0,0,2>, cudaFuncAttributeMaxDynamicSharedMemorySize, GSMEM_U);
    cudaFuncSetAttribute(hgemm<0,0,1,2>, cudaFuncAttributeMaxDynamicSharedMemorySize, GSMEM_U);
    cudaFuncSetAttribute(hgemm<0,0,2,2>, cudaFuncAttributeMaxDynamicSharedMemorySize, GSMEM_U);
    cudaFuncSetAttribute(hgemm<1,0,0,1>, cudaFuncAttributeMaxDynamicSharedMemorySize, GSMEM_U);
    cudaFuncSetAttribute(hgemm<0,1,1,1>, cudaFuncAttributeMaxDynamicSharedMemorySize, GSMEM_U);
    cudaFuncSetAttribute(hgemm<0,0,0,1>, cudaFuncAttributeMaxDynamicSharedMemorySize, GSMEM_U);

    // --- operand conversions ---
    {
        long long n = (long long)SS * DD;
        cvt_hilo_k<<<(unsigned)((n/4 + 255)/256), 256>>>(h, hh, hl, n);
    }
    {
        long long n0 = (long long)QLORA * DD;
        long long n1 = (long long)KEFF * DD;
        long long n2 = (long long)HH * QKH * QLORA;
        long long n3 = (long long)DD * HH * VH;
        int c0 = (int)((n0/4 + 255)/256), c1 = (int)((n1/4 + 255)/256);
        int c2 = (int)((n2/4 + 255)/256), c3 = (int)((n3/4 + 255)/256);
        cvt_hi_multi<<<(unsigned)(c0 + c1 + c2 + c3), 256>>>(
            w_q_a,  wcomb_h,      n0,
            w_kv_a, wcomb_h + n0, n1,
            w_q_b,  wqb_h,        n2,
            w_o,    wo_h,         n3,
            c0, c0 + c1, c0 + c1 + c2);
    }
    transcvt_hi_k<<<dim3(KVLORA/32, NOPEW/32, HH), 256>>>(
        w_uk, wukt_h, KVLORA, NOPEW,
        (long long)NOPEW*KVLORA, (long long)KVLORA*NOPEW);
    transcvt_hi_k<<<dim3(VH/32, KVLORA/32, HH), 256>>>(
        w_uv, wuvt_h, VH, KVLORA,
        (long long)KVLORA*VH, (long long)VH*KVLORA);

    // 1) [q_a | kv] = h @ [w_q_a | w_kv_a]^T -> fp32 combined  (2-term)
    hgemm<0,0,0,2><<<dim3((NCOMB + 127)/128, SS/128, 1), 256, GSMEM_U>>>(
        hh, hl, wcomb_h, qakv_f, nullptr, nullptr,
        SS, NCOMB, DD, DD, DD, NCOMB, 0, 0, 0);
    // 2) rmsnorm(q_a cols) -> hilo
    rmsnorm_hilo<<<SS, 256>>>(qakv_f, gq, qa_h, qa_l, QLORA, NCOMB);
    // 3) q = q_a @ w_q_b^T -> hilo  (2-term)
    hgemm<0,0,1,2><<<dim3((HH*QKH)/128, SS/128, 1), 256, GSMEM_U>>>(
        qa_h, qa_l, wqb_h, nullptr, q_h, q_l,
        SS, HH*QKH, QLORA, QLORA, QLORA, HH*QKH, 0, 0, 0);
    // 5) kv post: rmsnorm + rope -> keff hi
    kv_post<<<SS, 256>>>(qakv_f, NCOMB, QLORA, gkv, cosb, sinb, keff_h);
    // 5b) kv_c transpose -> kvct hi
    transcvt_hi_k<<<dim3(KVLORA/32, SS/32, 1), 256>>>(
        qakv_f + QLORA, kvct_h, NCOMB, SS, 0, 0);
    // 6) q_latent -> qeff[:, 0:512] hi only  (2-term in, OUT=2)
    hgemm<0,0,2,2><<<dim3(KVLORA/128, SS/128, HH), 256, GSMEM_U>>>(
        q_h, q_l, wukt_h, nullptr, qeff_h, nullptr,
        SS, KVLORA, NOPEW, HH*QKH, NOPEW, KEFF,
        (long long)QKH, (long long)KVLORA*NOPEW, (long long)SS*KEFF);
    // 7) q rope -> qeff[:, 512:576] hi only
    {
        long long total = (long long)SS * HH * 32;
        q_rope<<<(unsigned)((total + 255) / 256), 256>>>(q_h, q_l, qeff_h, cosb, sinb);
    }
    // 8) scores = qeff @ keff^T -> fp32  (1-term, triangle grid)
    {
        const int NT = SS / 128;
        const int NTRI = NT * (NT + 1) / 2;   // 136
        hgemm<1,0,0,1><<<dim3(NTRI, 1, HH), 256, GSMEM_U>>>(
            qeff_h, nullptr, keff_h, sc, nullptr, nullptr,
            SS, SS, KEFF, KEFF, KEFF, SS,
            (long long)SS*KEFF, 0, (long long)SS*SS);
    }
    // 9) causal softmax (vectorized) -> P hi only (+zero pad)
    softmax_causal<<<dim3(SS, HH), 256>>>(sc, p_h);
    // 10) ctx_latent = P @ kvct^T (K limited) -> hilo  (1-term)
    hgemm<0,1,1,1><<<dim3(KVLORA/128, SS/128, HH), 256, GSMEM_U>>>(
        p_h, nullptr, kvct_h, nullptr, ctxl_h, ctxl_l,
        SS, KVLORA, SS, SS, SS, KVLORA,
        (long long)SS*SS, 0, (long long)SS*KVLORA);
    // 11) ctx = ctxl @ wuvt^T -> hilo  (2-term)
    hgemm<0,0,1,2><<<dim3(1, SS/128, HH), 256, GSMEM_U>>>(
        ctxl_h, ctxl_l, wuvt_h, nullptr, ctx_h, ctx_l,
        SS, VH, KVLORA, KVLORA, KVLORA, HH*VH,
        (long long)SS*KVLORA, (long long)VH*KVLORA, (long long)VH);
    // 12) out = ctx @ w_o^T -> fp32  (1-term)
    hgemm<0,0,0,1><<<dim3(DD/128, SS/128, 1), 256, GSMEM_U>>>(
        ctx_h, nullptr, wo_h, out, nullptr, nullptr,
        SS, DD, HH*VH, HH*VH, HH*VH, DD, 0, 0, 0);
}

// round 14
// speedup vs baseline: 6.9616x; 1.1849x over previous
#include <cuda_runtime.h>
#include <cuda_fp16.h>
#include <stdint.h>
#include <math.h>

// ---------------- problem constants ----------------
#define SS 2048
#define DD 4096
#define HH 32
#define QLORA 1536
#define KVLORA 512
#define ROPEW 64
#define NOPEW 128
#define QKH 192
#define VH 128
#define KEFF 576
#define NCOMB (QLORA + KEFF)   // 2112
#define EPSV 1e-6f
#define SCALE 0.07216878364870322f   // 1/sqrt(192)

typedef __half hf;

// ---------------- scratch ----------------
__device__ float g_qakv_f[(size_t)SS * NCOMB];
__device__ float g_scores[(size_t)HH * SS * SS];
__device__ hf g_hh[(size_t)SS * DD];               // hi only
__device__ hf g_wcomb_h[(size_t)NCOMB * DD];
__device__ hf g_wqb_h[(size_t)HH*QKH * QLORA];
__device__ hf g_wo_h[(size_t)DD * HH*VH];
__device__ hf g_wukt_h[(size_t)HH*KVLORA*NOPEW];
__device__ hf g_wuvt_h[(size_t)HH*VH*KVLORA];
__device__ hf g_qa_h[(size_t)SS * QLORA];          // hi only
__device__ hf g_q_h[(size_t)SS * HH*QKH];          // hi only
__device__ hf g_keff_h[(size_t)SS * KEFF];
__device__ hf g_kvct_h[(size_t)KVLORA * SS];
__device__ hf g_qeff_h[(size_t)HH*SS*KEFF];        // hi only
__device__ hf g_p_h[(size_t)HH*SS*SS];
__device__ hf g_ctxl_h[(size_t)HH*SS*KVLORA],   g_ctxl_l[(size_t)HH*SS*KVLORA];
__device__ hf g_ctx_h[(size_t)SS * HH*VH],      g_ctx_l[(size_t)SS * HH*VH];

// ---------------- helpers ----------------
__device__ __forceinline__ uint32_t smem_u32(const void* p) {
    uint32_t a;
    asm("{ .reg .u64 t; cvta.to.shared.u64 t, %1; cvt.u32.u64 %0, t; }" : "=r"(a) : "l"(p));
    return a;
}

__device__ __forceinline__ void hilo1(float v, hf& h, hf& l) {
    h = __float2half_rn(v);
    l = __float2half_rn(v - __half2float(h));
}
__device__ __forceinline__ void hilo2pack(float a, float b, uint32_t& h, uint32_t& l) {
    hf ha, hb2, la, lb;
    hilo1(a, ha, la); hilo1(b, hb2, lb);
    h = ((uint32_t)__half_as_ushort(hb2) << 16) | __half_as_ushort(ha);
    l = ((uint32_t)__half_as_ushort(lb) << 16) | __half_as_ushort(la);
}
__device__ __forceinline__ uint32_t hi2pack(float a, float b) {
    hf ha = __float2half_rn(a), hb = __float2half_rn(b);
    return ((uint32_t)__half_as_ushort(hb) << 16) | __half_as_ushort(ha);
}

__device__ __forceinline__ void mma_f16(float* c, const uint32_t* a, const uint32_t* b) {
    asm volatile(
        "mma.sync.aligned.m16n8k16.row.col.f32.f16.f16.f32 "
        "{%0,%1,%2,%3}, {%4,%5,%6,%7}, {%8,%9}, {%0,%1,%2,%3};"
        : "+f"(c[0]), "+f"(c[1]), "+f"(c[2]), "+f"(c[3])
        : "r"(a[0]), "r"(a[1]), "r"(a[2]), "r"(a[3]), "r"(b[0]), "r"(b[1]));
}

#define LDMX4(r0, r1, r2, r3, addr) \
    asm volatile("ldmatrix.sync.aligned.m8n8.x4.shared.b16 {%0,%1,%2,%3}, [%4];" \
        : "=r"(r0), "=r"(r1), "=r"(r2), "=r"(r3) : "r"(addr))

#define CPA16(dst, src, sz) \
    asm volatile("cp.async.cg.shared.global [%0], [%1], 16, %2;" \
        :: "r"(dst), "l"(src), "r"(sz))
#define CPA_COMMIT()  asm volatile("cp.async.commit_group;" ::: "memory")

// BK=64 chunks; rows of 72 hf (144B) -> conflict-free ldmatrix
#define BK   64
#define LDT  72
#define ARR_B   (128 * LDT * 2)      // 18432
#define GSMEM_U (6 * ARR_B)          // 110592

// ============================================================================
// NT GEMM: C = A * B^T. K-major fp16 operands. BK=64 chunks, single barrier.
// TERMS==2: Ah*Bh + Al*Bh  (2 stages)   TERMS==1: Ah*Bh  (3 stages)
// OUT: 0 = fp32 C, 1 = fp16 hi/lo (Ch,Cl), 2 = fp16 hi only (Ch)
// TRI: compacted lower-triangle grid.x.  CKEND: K limited to (bm+1)*128.
// Requires K % 64 == 0.
// ============================================================================
template<int TRI, int CKEND, int OUT, int TERMS>
__global__ void __launch_bounds__(256, 2)
hgemm(const hf* __restrict__ Ah, const hf* __restrict__ Al,
      const hf* __restrict__ Bh,
      float* __restrict__ C, hf* __restrict__ Ch, hf* __restrict__ Cl,
      int M, int N, int K, int lda, int ldb, int ldc,
      long long sA, long long sB, long long sC)
{
    constexpr int NARR = TERMS + 1;
    constexpr int CHUNK_B = NARR * ARR_B;
    constexpr int BARR = (TERMS == 2) ? 2 : 1;
    constexpr int S = (TERMS == 2) ? 2 : 3;      // pipeline stages

    int bm, bn;
    if (TRI) {
        int bi = blockIdx.x;
        bm = (int)((sqrtf(8.f * (float)bi + 1.f) - 1.f) * 0.5f);
        while ((bm + 1) * (bm + 2) / 2 <= bi) bm++;
        while (bm * (bm + 1) / 2 > bi) bm--;
        bn = bi - bm * (bm + 1) / 2;
        if (bn > bm) return;
    } else {
        bm = blockIdx.y; bn = blockIdx.x;
    }
    extern __shared__ char smem[];
    const uint32_t sbase = smem_u32(smem);

    const int tid = threadIdx.x, lane = tid & 31, wid = tid >> 5;
    const int wm = wid & 1, wn = wid >> 1;

    Ah += (long long)blockIdx.z * sA;
    if (TERMS == 2) Al += (long long)blockIdx.z * sA;
    Bh += (long long)blockIdx.z * sB;

    const int Kend = CKEND ? min(K, (bm + 1) * 128) : K;
    const int nch = Kend / BK;

    const int ch = tid & 7;
    const int rr = tid >> 3;
    const int ar0 = bm * 128 + rr;
    const int br0 = bn * 128 + rr;
    const hf* pAh = Ah + (long long)ar0 * lda + ch * 8;
    const hf* pAl = (TERMS == 2) ? Al + (long long)ar0 * lda + ch * 8 : nullptr;
    const uint32_t d0 = (uint32_t)(rr * (LDT * 2) + ch * 16);

    auto issue = [&](int slot, int k0) {
        uint32_t st = sbase + slot * CHUNK_B;
        #pragma unroll
        for (int p = 0; p < 4; p++) {
            uint32_t dd = d0 + p * (32 * LDT * 2);
            long long ro = (long long)(p * 32) * lda + k0;
            CPA16(st + 0 * ARR_B + dd, pAh + ro, 16u);
            if (TERMS == 2)
                CPA16(st + 1 * ARR_B + dd, pAl + ro, 16u);
            int brow = br0 + p * 32;
            uint32_t sz = (brow < N) ? 16u : 0u;
            const hf* pb = Bh + (long long)min(brow, N - 1) * ldb + ch * 8 + k0;
            CPA16(st + BARR * ARR_B + dd, pb, sz);
        }
    };

    const int arow_l = wm * 64 + ((lane >> 3) & 1) * 8 + (lane & 7);
    const int acol_l = (lane >> 4) * 8;
    const uint32_t aoff = (uint32_t)(arow_l * LDT + acol_l) * 2;
    const int brow_l = wn * 32 + ((lane >> 4) & 1) * 8 + (lane & 7);
    const int bcol_l = ((lane >> 3) & 1) * 8;
    const uint32_t boff = (uint32_t)(brow_l * LDT + bcol_l) * 2;
    const uint32_t MISTR = 16 * LDT * 2;   // 2304

    float acc[4][4][4];
    #pragma unroll
    for (int a = 0; a < 4; a++)
        #pragma unroll
        for (int b = 0; b < 4; b++)
            #pragma unroll
            for (int q = 0; q < 4; q++) acc[a][b][q] = 0.f;

    issue(0, 0); CPA_COMMIT();
    if (S == 3) {
        if (nch > 1) issue(1, BK);
        CPA_COMMIT();
    }

    for (int c = 0; c < nch; c++) {
        if (S == 2) asm volatile("cp.async.wait_group 0;" ::: "memory");
        else        asm volatile("cp.async.wait_group 1;" ::: "memory");
        __syncthreads();
        const int cn = c + S - 1;
        if (cn < nch) issue(cn % S, cn * BK);
        CPA_COMMIT();
        const uint32_t st = sbase + (c % S) * CHUNK_B;
        #pragma unroll
        for (int ks = 0; ks < 4; ks++) {
            const uint32_t kof = ks * 32;
            uint32_t ah[4][4], al[4][4], bh[4][2];
            #pragma unroll
            for (int mi = 0; mi < 4; mi++) {
                LDMX4(ah[mi][0], ah[mi][1], ah[mi][2], ah[mi][3],
                      st + 0 * ARR_B + aoff + mi * MISTR + kof);
                if (TERMS == 2)
                    LDMX4(al[mi][0], al[mi][1], al[mi][2], al[mi][3],
                          st + 1 * ARR_B + aoff + mi * MISTR + kof);
            }
            #pragma unroll
            for (int p = 0; p < 2; p++)
                LDMX4(bh[2*p][0], bh[2*p][1], bh[2*p+1][0], bh[2*p+1][1],
                      st + BARR * ARR_B + boff + p * MISTR + kof);
            #pragma unroll
            for (int mi = 0; mi < 4; mi++)
                #pragma unroll
                for (int ni = 0; ni < 4; ni++) {
                    mma_f16(acc[mi][ni], ah[mi], bh[ni]);
                    if (TERMS == 2) mma_f16(acc[mi][ni], al[mi], bh[ni]);
                }
        }
    }

    const int qr = lane >> 2, qc = lane & 3;
    if (OUT == 1) {
        hf* chp = Ch + (long long)blockIdx.z * sC;
        hf* clp = Cl + (long long)blockIdx.z * sC;
        #pragma unroll
        for (int mi = 0; mi < 4; mi++)
            #pragma unroll
            for (int ni = 0; ni < 4; ni++) {
                int r = bm * 128 + wm * 64 + mi * 16 + qr;
                int cc = bn * 128 + wn * 32 + ni * 8 + qc * 2;
                if (cc < N) {
                    uint32_t h0, l0, h1, l1;
                    hilo2pack(acc[mi][ni][0], acc[mi][ni][1], h0, l0);
                    hilo2pack(acc[mi][ni][2], acc[mi][ni][3], h1, l1);
                    *(uint32_t*)(chp + (long long)r * ldc + cc) = h0;
                    *(uint32_t*)(clp + (long long)r * ldc + cc) = l0;
                    *(uint32_t*)(chp + (long long)(r + 8) * ldc + cc) = h1;
                    *(uint32_t*)(clp + (long long)(r + 8) * ldc + cc) = l1;
                }
            }
    } else if (OUT == 2) {
        hf* chp = Ch + (long long)blockIdx.z * sC;
        #pragma unroll
        for (int mi = 0; mi < 4; mi++)
            #pragma unroll
            for (int ni = 0; ni < 4; ni++) {
                int r = bm * 128 + wm * 64 + mi * 16 + qr;
                int cc = bn * 128 + wn * 32 + ni * 8 + qc * 2;
                if (cc < N) {
                    *(uint32_t*)(chp + (long long)r * ldc + cc) =
                        hi2pack(acc[mi][ni][0], acc[mi][ni][1]);
                    *(uint32_t*)(chp + (long long)(r + 8) * ldc + cc) =
                        hi2pack(acc[mi][ni][2], acc[mi][ni][3]);
                }
            }
    } else {
        float* cp = C + (long long)blockIdx.z * sC;
        #pragma unroll
        for (int mi = 0; mi < 4; mi++)
            #pragma unroll
            for (int ni = 0; ni < 4; ni++) {
                int r = bm * 128 + wm * 64 + mi * 16 + qr;
                int cc = bn * 128 + wn * 32 + ni * 8 + qc * 2;
                if (cc < N) {
                    *(float2*)(cp + (long long)r * ldc + cc) =
                        make_float2(acc[mi][ni][0], acc[mi][ni][1]);
                    *(float2*)(cp + (long long)(r + 8) * ldc + cc) =
                        make_float2(acc[mi][ni][2], acc[mi][ni][3]);
                }
            }
    }
}

// ============================================================================
// conversion / elementwise kernels
// ============================================================================
__global__ void cvt_hi_k(const float* __restrict__ in, hf* __restrict__ oh, long long n)
{
    long long i = ((long long)blockIdx.x * 256 + threadIdx.x) * 4;
    if (i >= n) return;
    float4 v = *(const float4*)(in + i);
    uint2 h;
    hf h0 = __float2half_rn(v.x), h1 = __float2half_rn(v.y);
    hf h2 = __float2half_rn(v.z), h3 = __float2half_rn(v.w);
    h.x = ((uint32_t)__half_as_ushort(h1) << 16) | __half_as_ushort(h0);
    h.y = ((uint32_t)__half_as_ushort(h3) << 16) | __half_as_ushort(h2);
    *(uint2*)(oh + i) = h;
}

__global__ void cvt_hi_multi(const float* __restrict__ s0, hf* __restrict__ d0, long long n0,
                             const float* __restrict__ s1, hf* __restrict__ d1, long long n1,
                             const float* __restrict__ s2, hf* __restrict__ d2, long long n2,
                             const float* __restrict__ s3, hf* __restrict__ d3, long long n3,
                             int b1, int b2, int b3)
{
    int b = blockIdx.x;
    const float* s; hf* d; long long n; int lb;
    if (b < b1)      { s = s0; d = d0; n = n0; lb = b; }
    else if (b < b2) { s = s1; d = d1; n = n1; lb = b - b1; }
    else if (b < b3) { s = s2; d = d2; n = n2; lb = b - b2; }
    else             { s = s3; d = d3; n = n3; lb = b - b3; }
    long long i = ((long long)lb * 256 + threadIdx.x) * 4;
    if (i >= n) return;
    float4 v = *(const float4*)(s + i);
    uint2 h;
    hf h0 = __float2half_rn(v.x), h1 = __float2half_rn(v.y);
    hf h2 = __float2half_rn(v.z), h3 = __float2half_rn(v.w);
    h.x = ((uint32_t)__half_as_ushort(h1) << 16) | __half_as_ushort(h0);
    h.y = ((uint32_t)__half_as_ushort(h3) << 16) | __half_as_ushort(h2);
    *(uint2*)(d + i) = h;
}

__global__ void transcvt_hi_k(const float* __restrict__ in, hf* __restrict__ oh,
                              int ld_in, int ld_out, long long sIn, long long sOut)
{
    __shared__ float tile[32][33];
    const float* ip = in + (long long)blockIdx.z * sIn;
    int r0 = blockIdx.y * 32, c0 = blockIdx.x * 32;
    int tx = threadIdx.x & 31, ty = threadIdx.x >> 5;
    #pragma unroll
    for (int it = 0; it < 4; it++) {
        int r = ty + it * 8;
        tile[r][tx] = ip[(long long)(r0 + r) * ld_in + c0 + tx];
    }
    __syncthreads();
    #pragma unroll
    for (int it = 0; it < 4; it++) {
        int cr = ty + it * 8;
        long long o = (long long)blockIdx.z * sOut + (long long)(c0 + cr) * ld_out + r0 + tx;
        oh[o] = __float2half_rn(tile[tx][cr]);
    }
}

// rmsnorm over first n cols (row stride ldx) -> fp16 hi only
__global__ void rmsnorm_hi(const float* __restrict__ X, const float* __restrict__ g,
                           hf* __restrict__ oh, int n, int ldx)
{
    const float* x = X + (long long)blockIdx.x * ldx;
    hf* ph = oh + (long long)blockIdx.x * n;
    __shared__ float red[256];
    const int tid = threadIdx.x;
    float s = 0.f;
    for (int i = tid; i < n; i += 256) { float v = x[i]; s += v * v; }
    red[tid] = s; __syncthreads();
    for (int o = 128; o > 0; o >>= 1) {
        if (tid < o) red[tid] += red[tid + o];
        __syncthreads();
    }
    float inv = rsqrtf(red[0] / (float)n + EPSV);
    for (int i = tid; i < n; i += 256)
        ph[i] = __float2half_rn(x[i] * inv * g[i]);
}

__global__ void kv_post(float* __restrict__ KV, int ld, int off,
                        const float* __restrict__ g,
                        const float* __restrict__ cosb, const float* __restrict__ sinb,
                        hf* __restrict__ oh)
{
    const int srow = blockIdx.x;
    float* x = KV + (long long)srow * ld + off;
    hf* ph = oh + (long long)srow * KEFF;
    __shared__ float red[256];
    const int tid = threadIdx.x;
    float s = 0.f;
    for (int i = tid; i < KVLORA; i += 256) { float v = x[i]; s += v * v; }
    red[tid] = s; __syncthreads();
    for (int o = 128; o > 0; o >>= 1) {
        if (tid < o) red[tid] += red[tid + o];
        __syncthreads();
    }
    float inv = rsqrtf(red[0] / (float)KVLORA + EPSV);
    for (int i = tid; i < KVLORA; i += 256) x[i] = x[i] * inv * g[i];
    if (tid < 32) {
        float x1 = x[KVLORA + tid];
        float x2 = x[KVLORA + 32 + tid];
        float c1 = cosb[srow * ROPEW + tid];
        float c2 = cosb[srow * ROPEW + 32 + tid];
        float s1 = sinb[srow * ROPEW + tid];
        float s2 = sinb[srow * ROPEW + 32 + tid];
        x[KVLORA + tid]      = x1 * c1 - x2 * s1;
        x[KVLORA + 32 + tid] = x2 * c2 + x1 * s2;
    }
    __syncthreads();
    for (int i = tid; i < KEFF; i += 256)
        ph[i] = __float2half_rn(x[i]);
}

// q rope (q hi only) -> qeff hi only
__global__ void q_rope(const hf* __restrict__ Qh, hf* __restrict__ Eh,
                       const float* __restrict__ cosb, const float* __restrict__ sinb)
{
    long long idx = (long long)blockIdx.x * blockDim.x + threadIdx.x;
    const long long total = (long long)SS * HH * 32;
    if (idx >= total) return;
    int j  = (int)(idx & 31);
    long long sh = idx >> 5;
    int h = (int)(sh & (HH - 1));
    int s = (int)(sh >> 5);
    long long qb = ((long long)s * HH + h) * QKH + NOPEW;
    float x1 = __half2float(Qh[qb + j]);
    float x2 = __half2float(Qh[qb + j + 32]);
    float c1 = cosb[s * ROPEW + j];
    float c2 = cosb[s * ROPEW + 32 + j];
    float s1 = sinb[s * ROPEW + j];
    float s2 = sinb[s * ROPEW + 32 + j];
    long long ob = ((long long)h * SS + s) * KEFF + KVLORA;
    Eh[ob + j]      = __float2half_rn(x1 * c1 - x2 * s1);
    Eh[ob + j + 32] = __float2half_rn(x2 * c2 + x1 * s2);
}

__global__ void softmax_causal(const float* __restrict__ Sc, hf* __restrict__ Ph)
{
    __shared__ float4 buf4[SS / 4];
    __shared__ float red[256];
    float* buf = (float*)buf4;
    const int m = blockIdx.x;
    const int h = blockIdx.y;
    const float* row = Sc + ((long long)h * SS + m) * SS;
    hf* ph = Ph + ((long long)h * SS + m) * SS;
    const int len = m + 1;
    const int n4 = len >> 2;
    const int pad = ((m >> 7) + 1) << 7;
    const int tid = threadIdx.x;

    float mx = -3.4e38f;
    for (int i = tid; i < n4; i += 256) {
        float4 v = *(const float4*)(row + i * 4);
        buf4[i] = v;
        mx = fmaxf(fmaxf(mx, fmaxf(v.x, v.y)), fmaxf(v.z, v.w));
    }
    for (int i = n4 * 4 + tid; i < len; i += 256) {
        float v = row[i]; buf[i] = v; mx = fmaxf(mx, v);
    }
    red[tid] = mx; __syncthreads();
    for (int o = 128; o > 0; o >>= 1) {
        if (tid < o) red[tid] = fmaxf(red[tid], red[tid + o]);
        __syncthreads();
    }
    const float rowmax = red[0];
    __syncthreads();

    float sum = 0.f;
    for (int i = tid; i < n4; i += 256) {
        float4 v = buf4[i];
        v.x = __expf(SCALE * (v.x - rowmax));
        v.y = __expf(SCALE * (v.y - rowmax));
        v.z = __expf(SCALE * (v.z - rowmax));
        v.w = __expf(SCALE * (v.w - rowmax));
        buf4[i] = v;
        sum += (v.x + v.y) + (v.z + v.w);
    }
    for (int i = n4 * 4 + tid; i < len; i += 256) {
        float e = __expf(SCALE * (buf[i] - rowmax));
        buf[i] = e; sum += e;
    }
    red[tid] = sum; __syncthreads();
    for (int o = 128; o > 0; o >>= 1) {
        if (tid < o) red[tid] += red[tid + o];
        __syncthreads();
    }
    const float rinv = 1.f / red[0];
    for (int i = tid; i < n4; i += 256) {
        float4 v = buf4[i];
        hf a = __float2half_rn(v.x * rinv), b = __float2half_rn(v.y * rinv);
        hf c = __float2half_rn(v.z * rinv), d = __float2half_rn(v.w * rinv);
        uint2 o2;
        o2.x = ((uint32_t)__half_as_ushort(b) << 16) | __half_as_ushort(a);
        o2.y = ((uint32_t)__half_as_ushort(d) << 16) | __half_as_ushort(c);
        *(uint2*)(ph + i * 4) = o2;
    }
    for (int i = n4 * 4 + tid; i < len; i += 256)
        ph[i] = __float2half_rn(buf[i] * rinv);
    const hf z = __float2half(0.f);
    for (int i = len + tid; i < pad; i += 256) ph[i] = z;
}

// ============================================================================
extern "C" void kernel_launch(void* const* d_in, const int* in_sizes, int n_in,
                              void* d_out, int out_size)
{
    (void)in_sizes; (void)n_in; (void)out_size;
    const float* h      = (const float*)d_in[0];
    const float* cosb   = (const float*)d_in[1];
    const float* sinb   = (const float*)d_in[2];
    const float* w_q_a  = (const float*)d_in[3];
    const float* gq     = (const float*)d_in[4];
    const float* w_q_b  = (const float*)d_in[5];
    const float* w_kv_a = (const float*)d_in[6];
    const float* gkv    = (const float*)d_in[7];
    const float* w_uk   = (const float*)d_in[8];
    const float* w_uv   = (const float*)d_in[9];
    const float* w_o    = (const float*)d_in[10];
    float* out = (float*)d_out;

    float *qakv_f, *sc;
    hf *hh, *wcomb_h, *wqb_h, *wo_h, *wukt_h, *wuvt_h;
    hf *qa_h, *q_h, *keff_h, *kvct_h, *qeff_h;
    hf *p_h, *ctxl_h, *ctxl_l, *ctx_h, *ctx_l;
    cudaGetSymbolAddress((void**)&qakv_f, g_qakv_f);
    cudaGetSymbolAddress((void**)&sc,     g_scores);
    cudaGetSymbolAddress((void**)&hh,     g_hh);
    cudaGetSymbolAddress((void**)&wcomb_h, g_wcomb_h);
    cudaGetSymbolAddress((void**)&wqb_h,  g_wqb_h);
    cudaGetSymbolAddress((void**)&wo_h,   g_wo_h);
    cudaGetSymbolAddress((void**)&wukt_h, g_wukt_h);
    cudaGetSymbolAddress((void**)&wuvt_h, g_wuvt_h);
    cudaGetSymbolAddress((void**)&qa_h,   g_qa_h);
    cudaGetSymbolAddress((void**)&q_h,    g_q_h);
    cudaGetSymbolAddress((void**)&keff_h, g_keff_h);
    cudaGetSymbolAddress((void**)&kvct_h, g_kvct_h);
    cudaGetSymbolAddress((void**)&qeff_h, g_qeff_h);
    cudaGetSymbolAddress((void**)&p_h,    g_p_h);
    cudaGetSymbolAddress((void**)&ctxl_h, g_ctxl_h); cudaGetSymbolAddress((void**)&ctxl_l, g_ctxl_l);
    cudaGetSymbolAddress((void**)&ctx_h,  g_ctx_h);  cudaGetSymbolAddress((void**)&ctx_l,  g_ctx_l);

    cudaFuncSetAttribute(hgemm<0,0,0,1>, cudaFuncAttributeMaxDynamicSharedMemorySize, GSMEM_U);
    cudaFuncSetAttribute(hgemm<0,0,2,1>, cudaFuncAttributeMaxDynamicSharedMemorySize, GSMEM_U);
    cudaFuncSetAttribute(hgemm<1,0,0,1>, cudaFuncAttributeMaxDynamicSharedMemorySize, GSMEM_U);
    cudaFuncSetAttribute(hgemm<0,1,1,1>, cudaFuncAttributeMaxDynamicSharedMemorySize, GSMEM_U);
    cudaFuncSetAttribute(hgemm<0,0,1,2>, cudaFuncAttributeMaxDynamicSharedMemorySize, GSMEM_U);

    // --- operand conversions (all hi-only now) ---
    {
        long long n = (long long)SS * DD;
        cvt_hi_k<<<(unsigned)((n/4 + 255)/256), 256>>>(h, hh, n);
    }
    {
        long long n0 = (long long)QLORA * DD;
        long long n1 = (long long)KEFF * DD;
        long long n2 = (long long)HH * QKH * QLORA;
        long long n3 = (long long)DD * HH * VH;
        int c0 = (int)((n0/4 + 255)/256), c1 = (int)((n1/4 + 255)/256);
        int c2 = (int)((n2/4 + 255)/256), c3 = (int)((n3/4 + 255)/256);
        cvt_hi_multi<<<(unsigned)(c0 + c1 + c2 + c3), 256>>>(
            w_q_a,  wcomb_h,      n0,
            w_kv_a, wcomb_h + n0, n1,
            w_q_b,  wqb_h,        n2,
            w_o,    wo_h,         n3,
            c0, c0 + c1, c0 + c1 + c2);
    }
    transcvt_hi_k<<<dim3(KVLORA/32, NOPEW/32, HH), 256>>>(
        w_uk, wukt_h, KVLORA, NOPEW,
        (long long)NOPEW*KVLORA, (long long)KVLORA*NOPEW);
    transcvt_hi_k<<<dim3(VH/32, KVLORA/32, HH), 256>>>(
        w_uv, wuvt_h, VH, KVLORA,
        (long long)KVLORA*VH, (long long)VH*KVLORA);

    // 1) [q_a | kv] = h @ [w_q_a | w_kv_a]^T -> fp32 combined  (1-term)
    hgemm<0,0,0,1><<<dim3((NCOMB + 127)/128, SS/128, 1), 256, GSMEM_U>>>(
        hh, nullptr, wcomb_h, qakv_f, nullptr, nullptr,
        SS, NCOMB, DD, DD, DD, NCOMB, 0, 0, 0);
    // 2) rmsnorm(q_a cols) -> hi only
    rmsnorm_hi<<<SS, 256>>>(qakv_f, gq, qa_h, QLORA, NCOMB);
    // 3) q = q_a @ w_q_b^T -> hi only  (1-term)
    hgemm<0,0,2,1><<<dim3((HH*QKH)/128, SS/128, 1), 256, GSMEM_U>>>(
        qa_h, nullptr, wqb_h, nullptr, q_h, nullptr,
        SS, HH*QKH, QLORA, QLORA, QLORA, HH*QKH, 0, 0, 0);
    // 5) kv post: rmsnorm + rope -> keff hi
    kv_post<<<SS, 256>>>(qakv_f, NCOMB, QLORA, gkv, cosb, sinb, keff_h);
    // 5b) kv_c transpose -> kvct hi
    transcvt_hi_k<<<dim3(KVLORA/32, SS/32, 1), 256>>>(
        qakv_f + QLORA, kvct_h, NCOMB, SS, 0, 0);
    // 6) q_latent -> qeff[:, 0:512] hi only  (1-term)
    hgemm<0,0,2,1><<<dim3(KVLORA/128, SS/128, HH), 256, GSMEM_U>>>(
        q_h, nullptr, wukt_h, nullptr, qeff_h, nullptr,
        SS, KVLORA, NOPEW, HH*QKH, NOPEW, KEFF,
        (long long)QKH, (long long)KVLORA*NOPEW, (long long)SS*KEFF);
    // 7) q rope -> qeff[:, 512:576] hi only
    {
        long long total = (long long)SS * HH * 32;
        q_rope<<<(unsigned)((total + 255) / 256), 256>>>(q_h, qeff_h, cosb, sinb);
    }
    // 8) scores = qeff @ keff^T -> fp32  (1-term, triangle grid)
    {
        const int NT = SS / 128;
        const int NTRI = NT * (NT + 1) / 2;   // 136
        hgemm<1,0,0,1><<<dim3(NTRI, 1, HH), 256, GSMEM_U>>>(
            qeff_h, nullptr, keff_h, sc, nullptr, nullptr,
            SS, SS, KEFF, KEFF, KEFF, SS,
            (long long)SS*KEFF, 0, (long long)SS*SS);
    }
    // 9) causal softmax (vectorized) -> P hi only (+zero pad)
    softmax_causal<<<dim3(SS, HH), 256>>>(sc, p_h);
    // 10) ctx_latent = P @ kvct^T (K limited) -> hilo  (1-term)
    hgemm<0,1,1,1><<<dim3(KVLORA/128, SS/128, HH), 256, GSMEM_U>>>(
        p_h, nullptr, kvct_h, nullptr, ctxl_h, ctxl_l,
        SS, KVLORA, SS, SS, SS, KVLORA,
        (long long)SS*SS, 0, (long long)SS*KVLORA);
    // 11) ctx = ctxl @ wuvt^T -> hilo  (2-term)
    hgemm<0,0,1,2><<<dim3(1, SS/128, HH), 256, GSMEM_U>>>(
        ctxl_h, ctxl_l, wuvt_h, nullptr, ctx_h, ctx_l,
        SS, VH, KVLORA, KVLORA, KVLORA, HH*VH,
        (long long)SS*KVLORA, (long long)VH*KVLORA, (long long)VH);
    // 12) out = ctx @ w_o^T -> fp32  (1-term)
    hgemm<0,0,0,1><<<dim3(DD/128, SS/128, 1), 256, GSMEM_U>>>(
        ctx_h, nullptr, wo_h, out, nullptr, nullptr,
        SS, DD, HH*VH, HH*VH, HH*VH, DD, 0, 0, 0);
}